// round 2
// baseline (speedup 1.0000x reference)
#include <cuda_runtime.h>
#include <math.h>

// ---------------- Problem constants ----------------
#define D_    768
#define H_    12
#define HD_   64
#define S_    197
#define L_    196
#define NB    16          // batch per image set
#define B2    32          // both image sets
#define FF_   3072
#define OUT_  512
#define QKV3  2304
#define IMG_  224
#define GRID_ 14
#define PCH_  16

// ---------------- Scratch (device globals; no allocation allowed) ----------------
__device__ float g_x12[B2 * S_ * D_];      // residual stream (x | x2)
__device__ float g_xln[B2 * S_ * D_];      // LN output
__device__ float g_qkv[B2 * S_ * QKV3];    // qkv
__device__ float g_att[B2 * S_ * D_];      // attention out (also conv_out temp)
__device__ float g_ffh[B2 * S_ * FF_];     // MLP hidden
__device__ float g_im2col[B2 * L_ * D_];   // patch im2col
__device__ float g_clsb[NB * L_];          // cls-row attention bias

// ======================================================================
// GEMM: C[M,N] = act( A[M,K] @ B[N,K]^T + bias[N] ) + resid[M,N]
// 128x128 tile, BK=8, 256 threads, 8x8 microtile (z-ordered), float4 smem.
// ======================================================================
__global__ __launch_bounds__(256) void gemm_kernel(
    const float* __restrict__ A, const float* __restrict__ B,
    const float* __restrict__ bias, const float* __restrict__ resid,
    float* __restrict__ C, int M, int N, int K, int act)
{
    __shared__ float As[8][132];
    __shared__ float Bs[8][132];

    const int bm = blockIdx.y * 128;
    const int bn = blockIdx.x * 128;
    const int tid = threadIdx.x;
    const int tx = tid & 15;       // 0..15
    const int ty = tid >> 4;       // 0..15

    const int lrow = tid >> 1;            // 0..127
    const int lcol = (tid & 1) * 4;       // 0 or 4

    float acc[8][8];
    #pragma unroll
    for (int i = 0; i < 8; i++)
        #pragma unroll
        for (int j = 0; j < 8; j++) acc[i][j] = 0.f;

    const bool avalid = (bm + lrow) < M;
    const float* Aptr = A + (size_t)(bm + lrow) * K + lcol;
    const float* Bptr = B + (size_t)(bn + lrow) * K + lcol;

    for (int k0 = 0; k0 < K; k0 += 8) {
        float4 av = avalid ? *(const float4*)(Aptr + k0) : make_float4(0.f, 0.f, 0.f, 0.f);
        float4 bv = *(const float4*)(Bptr + k0);
        As[lcol + 0][lrow] = av.x; As[lcol + 1][lrow] = av.y;
        As[lcol + 2][lrow] = av.z; As[lcol + 3][lrow] = av.w;
        Bs[lcol + 0][lrow] = bv.x; Bs[lcol + 1][lrow] = bv.y;
        Bs[lcol + 2][lrow] = bv.z; Bs[lcol + 3][lrow] = bv.w;
        __syncthreads();

        #pragma unroll
        for (int kk = 0; kk < 8; kk++) {
            float a[8], b[8];
            *(float4*)&a[0] = *(const float4*)&As[kk][ty * 4];
            *(float4*)&a[4] = *(const float4*)&As[kk][64 + ty * 4];
            *(float4*)&b[0] = *(const float4*)&Bs[kk][tx * 4];
            *(float4*)&b[4] = *(const float4*)&Bs[kk][64 + tx * 4];
            #pragma unroll
            for (int i = 0; i < 8; i++)
                #pragma unroll
                for (int j = 0; j < 8; j++)
                    acc[i][j] += a[i] * b[j];
        }
        __syncthreads();
    }

    #pragma unroll
    for (int i = 0; i < 8; i++) {
        int gm = bm + ((i < 4) ? (ty * 4 + i) : (64 + ty * 4 + i - 4));
        if (gm >= M) continue;
        #pragma unroll
        for (int j = 0; j < 8; j++) {
            int gn = bn + ((j < 4) ? (tx * 4 + j) : (64 + tx * 4 + j - 4));
            float v = acc[i][j];
            if (bias)  v += bias[gn];
            if (act)   v = v / (1.f + expf(-1.702f * v));   // GELU(sigmoid approx)
            if (resid) v += resid[(size_t)gm * N + gn];
            C[(size_t)gm * N + gn] = v;
        }
    }
}

// ======================================================================
// LayerNorm: one block (256 thr) per row of 768.
// ======================================================================
__global__ __launch_bounds__(256) void ln_kernel(
    const float* __restrict__ x, long in_stride,
    float* __restrict__ y, long out_stride,
    const float* __restrict__ g, const float* __restrict__ b, int rows)
{
    int r = blockIdx.x;
    if (r >= rows) return;
    const float* xr = x + (size_t)r * in_stride;
    float* yr = y + (size_t)r * out_stride;
    int t = threadIdx.x;

    float v0 = xr[t], v1 = xr[t + 256], v2 = xr[t + 512];

    __shared__ float red[8];
    __shared__ float bc;

    // mean
    float s = v0 + v1 + v2;
    #pragma unroll
    for (int o = 16; o > 0; o >>= 1) s += __shfl_xor_sync(0xffffffffu, s, o);
    if ((t & 31) == 0) red[t >> 5] = s;
    __syncthreads();
    if (t == 0) { float tot = 0.f; for (int i = 0; i < 8; i++) tot += red[i]; bc = tot; }
    __syncthreads();
    float mu = bc * (1.f / 768.f);

    float d0 = v0 - mu, d1 = v1 - mu, d2 = v2 - mu;
    float ss = d0 * d0 + d1 * d1 + d2 * d2;
    #pragma unroll
    for (int o = 16; o > 0; o >>= 1) ss += __shfl_xor_sync(0xffffffffu, ss, o);
    __syncthreads();            // protect red[] reuse
    if ((t & 31) == 0) red[t >> 5] = ss;
    __syncthreads();
    if (t == 0) { float tot = 0.f; for (int i = 0; i < 8; i++) tot += red[i]; bc = tot; }
    __syncthreads();
    float rs = rsqrtf(bc * (1.f / 768.f) + 1e-5f);

    yr[t]       = d0 * rs * g[t]       + b[t];
    yr[t + 256] = d1 * rs * g[t + 256] + b[t + 256];
    yr[t + 512] = d2 * rs * g[t + 512] + b[t + 512];
}

// ======================================================================
// Fused attention: one block per (head, batch). K,V in smem (stride-68
// padded, conflict-free float4). 8 warps; each warp owns queries w, w+8, ...
// ======================================================================
#define KVS 68
__global__ __launch_bounds__(256) void attn_kernel(
    const float* __restrict__ qkv, const float* __restrict__ clsbias,
    float* __restrict__ out)
{
    extern __shared__ float sm[];
    float* Ks = sm;                       // 197*68
    float* Vs = sm + S_ * KVS;            // 197*68
    float* Ps = Vs + S_ * KVS;            // 8*200

    const int h = blockIdx.x, b = blockIdx.y;
    const int tid = threadIdx.x;
    const int w = tid >> 5, lane = tid & 31;
    const size_t base = (size_t)b * S_ * QKV3;

    for (int i = tid; i < S_ * HD_; i += 256) {
        int s_ = i >> 6, hd = i & 63;
        size_t off = base + (size_t)s_ * QKV3 + h * HD_ + hd;
        Ks[s_ * KVS + hd] = qkv[off + D_];
        Vs[s_ * KVS + hd] = qkv[off + 2 * D_];
    }
    __syncthreads();

    for (int q = w; q < S_; q += 8) {
        const float4* qp = (const float4*)(qkv + base + (size_t)q * QKV3 + h * HD_);
        float4 qr[16];
        #pragma unroll
        for (int i = 0; i < 16; i++) qr[i] = qp[i];

        float sc[7];
        #pragma unroll
        for (int t = 0; t < 7; t++) {
            int k = lane + 32 * t;
            float sv = -1e30f;
            if (k < S_) {
                const float4* kp = (const float4*)(Ks + k * KVS);
                float a = 0.f;
                #pragma unroll
                for (int i = 0; i < 16; i++) {
                    float4 kk = kp[i];
                    a += qr[i].x * kk.x + qr[i].y * kk.y + qr[i].z * kk.z + qr[i].w * kk.w;
                }
                sv = a * 0.125f;
                if (clsbias && q == 0 && k >= 1) sv += clsbias[b * L_ + (k - 1)];
            }
            sc[t] = sv;
        }
        // softmax over k (warp-wide)
        float m = sc[0];
        #pragma unroll
        for (int t = 1; t < 7; t++) m = fmaxf(m, sc[t]);
        #pragma unroll
        for (int o = 16; o > 0; o >>= 1) m = fmaxf(m, __shfl_xor_sync(0xffffffffu, m, o));
        float se = 0.f;
        #pragma unroll
        for (int t = 0; t < 7; t++) {
            float e = (sc[t] > -1e29f) ? expf(sc[t] - m) : 0.f;
            sc[t] = e; se += e;
        }
        #pragma unroll
        for (int o = 16; o > 0; o >>= 1) se += __shfl_xor_sync(0xffffffffu, se, o);
        float inv = 1.f / se;
        #pragma unroll
        for (int t = 0; t < 7; t++) {
            int k = lane + 32 * t;
            if (k < S_) Ps[w * 200 + k] = sc[t] * inv;
        }
        __syncwarp();

        float o0 = 0.f, o1 = 0.f;
        for (int k = 0; k < S_; k++) {
            float p = Ps[w * 200 + k];
            o0 += p * Vs[k * KVS + lane];
            o1 += p * Vs[k * KVS + 32 + lane];
        }
        size_t orow = ((size_t)b * S_ + q) * D_ + h * HD_;
        out[orow + lane] = o0;
        out[orow + 32 + lane] = o1;
        __syncwarp();
    }
}

// ======================================================================
// Patch embed helpers
// ======================================================================
__global__ void im2col_kernel(const float* __restrict__ masked,
                              const float* __restrict__ prompted,
                              float* __restrict__ col)
{
    int idx = blockIdx.x * 256 + threadIdx.x;
    const int total = B2 * L_ * D_;
    if (idx >= total) return;
    int k = idx % D_;
    int m = idx / D_;
    int b = m / L_, l = m % L_;
    int gy = l / GRID_, gx = l % GRID_;
    int c = k >> 8, rem = k & 255;
    int py = rem >> 4, px = rem & 15;
    const float* src = (b < NB) ? (masked + (size_t)b * 3 * IMG_ * IMG_)
                                : (prompted + (size_t)(b - NB) * 3 * IMG_ * IMG_);
    col[idx] = src[((size_t)c * IMG_ + gy * PCH_ + py) * IMG_ + gx * PCH_ + px];
}

__global__ void embed_kernel(const float* __restrict__ conv_out,
                             const float* __restrict__ cls_emb,
                             const float* __restrict__ pos,
                             float* __restrict__ x)
{
    int idx = blockIdx.x * 256 + threadIdx.x;
    const int total = B2 * S_ * D_;
    if (idx >= total) return;
    int d = idx % D_;
    int bs = idx / D_;
    int s = bs % S_, b = bs / S_;
    float v = (s == 0) ? cls_emb[d] : conv_out[((size_t)b * L_ + (s - 1)) * D_ + d];
    x[idx] = v + pos[s * D_ + d];
}

__global__ void clsbias_kernel(const float* __restrict__ pm, float* __restrict__ cb)
{
    int i = blockIdx.x * 256 + threadIdx.x;
    if (i < NB * L_) cb[i] = (pm[i] != 0.f) ? 0.f : -1e30f;
}

// xa: x[:16] = 2 * (x2 with tokens masked) + x    (in place on x region)
__global__ void mask_combine_kernel(float* __restrict__ x, const float* __restrict__ x2,
                                    const float* __restrict__ pm)
{
    int idx = blockIdx.x * 256 + threadIdx.x;
    const int total = NB * S_ * D_;
    if (idx >= total) return;
    int bs = idx / D_;
    int s = bs % S_, b = bs / S_;
    float mf = (s == 0) ? 1.f : pm[b * L_ + (s - 1)];
    x[idx] = 2.f * x2[idx] * mf + x[idx];
}

// final: out[16,512] = cls_ln[16,768] @ proj[768,512]
__global__ void proj_out_kernel(const float* __restrict__ cls,
                                const float* __restrict__ proj,
                                float* __restrict__ out)
{
    int n = blockIdx.x * 256 + threadIdx.x;
    int m = blockIdx.y;
    if (n >= OUT_) return;
    float s = 0.f;
    #pragma unroll 4
    for (int k = 0; k < D_; k++) s += cls[m * D_ + k] * proj[(size_t)k * OUT_ + n];
    out[m * OUT_ + n] = s;
}

// ======================================================================
// Host orchestration
// ======================================================================
static float* symaddr(const void* s) {
    void* p = nullptr;
    cudaGetSymbolAddress(&p, s);
    return (float*)p;
}

static void run_gemm(const float* A, const float* B, const float* bias,
                     const float* resid, float* C, int M, int N, int K, int act)
{
    dim3 grid(N / 128, (M + 127) / 128);
    gemm_kernel<<<grid, 256>>>(A, B, bias, resid, C, M, N, K, act);
}

struct Ctx {
    float *x12, *xln, *qkv, *att, *ffh, *col, *clsb;
    const float *Wqkv, *bqkv, *Wo, *bo, *ln1g, *ln1b, *ln2g, *ln2b, *Wfc, *bfc, *Wp, *bp;
    int attn_smem;
};

static void run_block(const Ctx& c, float* x, int Bn, int layer, const float* bias)
{
    const int M = Bn * S_;
    ln_kernel<<<M, 256>>>(x, D_, c.xln, D_, c.ln1g + layer * D_, c.ln1b + layer * D_, M);
    run_gemm(c.xln, c.Wqkv + (size_t)layer * QKV3 * D_, c.bqkv + layer * QKV3,
             nullptr, c.qkv, M, QKV3, D_, 0);
    attn_kernel<<<dim3(H_, Bn), 256, c.attn_smem>>>(c.qkv, bias, c.att);
    run_gemm(c.att, c.Wo + (size_t)layer * D_ * D_, c.bo + layer * D_,
             x, x, M, D_, D_, 0);
    ln_kernel<<<M, 256>>>(x, D_, c.xln, D_, c.ln2g + layer * D_, c.ln2b + layer * D_, M);
    run_gemm(c.xln, c.Wfc + (size_t)layer * FF_ * D_, c.bfc + layer * FF_,
             nullptr, c.ffh, M, FF_, D_, 1);
    run_gemm(c.ffh, c.Wp + (size_t)layer * D_ * FF_, c.bp + layer * D_,
             x, x, M, D_, FF_, 0);
}

extern "C" void kernel_launch(void* const* d_in, const int* in_sizes, int n_in,
                              void* d_out, int out_size)
{
    const float* masked   = (const float*)d_in[0];
    const float* prompted = (const float*)d_in[1];
    const float* pred     = (const float*)d_in[2];
    const float* conv_w   = (const float*)d_in[3];
    const float* cls_emb  = (const float*)d_in[4];
    const float* pos_emb  = (const float*)d_in[5];
    const float* lnpre_g  = (const float*)d_in[6];
    const float* lnpre_b  = (const float*)d_in[7];

    Ctx c;
    c.Wqkv = (const float*)d_in[8];   c.bqkv = (const float*)d_in[9];
    c.Wo   = (const float*)d_in[10];  c.bo   = (const float*)d_in[11];
    c.ln1g = (const float*)d_in[12];  c.ln1b = (const float*)d_in[13];
    c.ln2g = (const float*)d_in[14];  c.ln2b = (const float*)d_in[15];
    c.Wfc  = (const float*)d_in[16];  c.bfc  = (const float*)d_in[17];
    c.Wp   = (const float*)d_in[18];  c.bp   = (const float*)d_in[19];
    const float* lnpost_g = (const float*)d_in[20];
    const float* lnpost_b = (const float*)d_in[21];
    const float* proj     = (const float*)d_in[22];
    float* out = (float*)d_out;

    c.x12  = symaddr(g_x12);
    c.xln  = symaddr(g_xln);
    c.qkv  = symaddr(g_qkv);
    c.att  = symaddr(g_att);
    c.ffh  = symaddr(g_ffh);
    c.col  = symaddr(g_im2col);
    c.clsb = symaddr(g_clsb);

    c.attn_smem = (2 * S_ * KVS + 8 * 200) * (int)sizeof(float);   // 113,568 B
    cudaFuncSetAttribute(attn_kernel, cudaFuncAttributeMaxDynamicSharedMemorySize,
                         c.attn_smem);

    // ---- patch embed (im2col GEMM) ----
    {
        const int total = B2 * L_ * D_;
        im2col_kernel<<<(total + 255) / 256, 256>>>(masked, prompted, c.col);
        // conv_w is (768, 3*16*16) contiguous → exactly (N,K) for our GEMM
        run_gemm(c.col, conv_w, nullptr, nullptr, c.att, B2 * L_, D_, D_, 0);
        const int tot2 = B2 * S_ * D_;
        embed_kernel<<<(tot2 + 255) / 256, 256>>>(c.att, cls_emb, pos_emb, c.x12);
        ln_kernel<<<B2 * S_, 256>>>(c.x12, D_, c.x12, D_, lnpre_g, lnpre_b, B2 * S_);
    }

    clsbias_kernel<<<(NB * L_ + 255) / 256, 256>>>(pred, c.clsb);

    // ---- 10 standard blocks on the concatenated batch ----
    for (int i = 0; i < 10; i++)
        run_block(c, c.x12, B2, i, nullptr);

    // ---- masking phase: layers 10 and 11 ----
    float* x  = c.x12;
    float* x2 = c.x12 + (size_t)NB * S_ * D_;
    const int layers2[2] = {10, 11};
    for (int t = 0; t < 2; t++) {
        int i = layers2[t];
        const int tot = NB * S_ * D_;
        mask_combine_kernel<<<(tot + 255) / 256, 256>>>(x, x2, pred);
        run_block(c, x, NB, i, nullptr);
        run_block(c, x2, NB, i, c.clsb);
    }

    // ---- head: LN_post on cls token, then @ proj ----
    ln_kernel<<<NB, 256>>>(x, (long)S_ * D_, c.xln, D_, lnpost_g, lnpost_b, NB);
    proj_out_kernel<<<dim3((OUT_ + 255) / 256, NB), 256>>>(c.xln, proj, out);

    (void)in_sizes; (void)n_in; (void)out_size;
}

// round 3
// speedup vs baseline: 1.0000x; 1.0000x over previous
#include <cuda_runtime.h>
#include <math.h>

// ---------------- Problem constants ----------------
#define D_    768
#define H_    12
#define HD_   64
#define S_    197
#define L_    196
#define NB    16          // batch per image set
#define B2    32          // both image sets
#define FF_   3072
#define OUT_  512
#define QKV3  2304
#define IMG_  224
#define GRID_ 14
#define PCH_  16

// ---------------- Scratch (device globals; no allocation allowed) ----------------
__device__ float g_x12[B2 * S_ * D_];      // residual stream (x | x2)
__device__ float g_xln[B2 * S_ * D_];      // LN output
__device__ float g_qkv[B2 * S_ * QKV3];    // qkv
__device__ float g_att[B2 * S_ * D_];      // attention out (also conv_out temp)
__device__ float g_ffh[B2 * S_ * FF_];     // MLP hidden
__device__ float g_im2col[B2 * L_ * D_];   // patch im2col
__device__ float g_clsb[NB * L_];          // cls-row attention bias

// ======================================================================
// GEMM: C[M,N] = act( A[M,K] @ B[N,K]^T + bias[N] ) + resid[M,N]
// 128x128 tile, BK=8, 256 threads, 8x8 microtile (z-ordered), float4 smem.
// ======================================================================
__global__ __launch_bounds__(256) void gemm_kernel(
    const float* __restrict__ A, const float* __restrict__ B,
    const float* __restrict__ bias, const float* __restrict__ resid,
    float* __restrict__ C, int M, int N, int K, int act)
{
    __shared__ float As[8][132];
    __shared__ float Bs[8][132];

    const int bm = blockIdx.y * 128;
    const int bn = blockIdx.x * 128;
    const int tid = threadIdx.x;
    const int tx = tid & 15;       // 0..15
    const int ty = tid >> 4;       // 0..15

    const int lrow = tid >> 1;            // 0..127
    const int lcol = (tid & 1) * 4;       // 0 or 4

    float acc[8][8];
    #pragma unroll
    for (int i = 0; i < 8; i++)
        #pragma unroll
        for (int j = 0; j < 8; j++) acc[i][j] = 0.f;

    const bool avalid = (bm + lrow) < M;
    const float* Aptr = A + (size_t)(bm + lrow) * K + lcol;
    const float* Bptr = B + (size_t)(bn + lrow) * K + lcol;

    for (int k0 = 0; k0 < K; k0 += 8) {
        float4 av = avalid ? *(const float4*)(Aptr + k0) : make_float4(0.f, 0.f, 0.f, 0.f);
        float4 bv = *(const float4*)(Bptr + k0);
        As[lcol + 0][lrow] = av.x; As[lcol + 1][lrow] = av.y;
        As[lcol + 2][lrow] = av.z; As[lcol + 3][lrow] = av.w;
        Bs[lcol + 0][lrow] = bv.x; Bs[lcol + 1][lrow] = bv.y;
        Bs[lcol + 2][lrow] = bv.z; Bs[lcol + 3][lrow] = bv.w;
        __syncthreads();

        #pragma unroll
        for (int kk = 0; kk < 8; kk++) {
            float a[8], b[8];
            *(float4*)&a[0] = *(const float4*)&As[kk][ty * 4];
            *(float4*)&a[4] = *(const float4*)&As[kk][64 + ty * 4];
            *(float4*)&b[0] = *(const float4*)&Bs[kk][tx * 4];
            *(float4*)&b[4] = *(const float4*)&Bs[kk][64 + tx * 4];
            #pragma unroll
            for (int i = 0; i < 8; i++)
                #pragma unroll
                for (int j = 0; j < 8; j++)
                    acc[i][j] += a[i] * b[j];
        }
        __syncthreads();
    }

    #pragma unroll
    for (int i = 0; i < 8; i++) {
        int gm = bm + ((i < 4) ? (ty * 4 + i) : (64 + ty * 4 + i - 4));
        if (gm >= M) continue;
        #pragma unroll
        for (int j = 0; j < 8; j++) {
            int gn = bn + ((j < 4) ? (tx * 4 + j) : (64 + tx * 4 + j - 4));
            float v = acc[i][j];
            if (bias)  v += bias[gn];
            if (act)   v = v / (1.f + expf(-1.702f * v));   // GELU(sigmoid approx)
            if (resid) v += resid[(size_t)gm * N + gn];
            C[(size_t)gm * N + gn] = v;
        }
    }
}

// ======================================================================
// LayerNorm: one block (256 thr) per row of 768.
// ======================================================================
__global__ __launch_bounds__(256) void ln_kernel(
    const float* __restrict__ x, long in_stride,
    float* __restrict__ y, long out_stride,
    const float* __restrict__ g, const float* __restrict__ b, int rows)
{
    int r = blockIdx.x;
    if (r >= rows) return;
    const float* xr = x + (size_t)r * in_stride;
    float* yr = y + (size_t)r * out_stride;
    int t = threadIdx.x;

    float v0 = xr[t], v1 = xr[t + 256], v2 = xr[t + 512];

    __shared__ float red[8];
    __shared__ float bc;

    // mean
    float s = v0 + v1 + v2;
    #pragma unroll
    for (int o = 16; o > 0; o >>= 1) s += __shfl_xor_sync(0xffffffffu, s, o);
    if ((t & 31) == 0) red[t >> 5] = s;
    __syncthreads();
    if (t == 0) { float tot = 0.f; for (int i = 0; i < 8; i++) tot += red[i]; bc = tot; }
    __syncthreads();
    float mu = bc * (1.f / 768.f);

    float d0 = v0 - mu, d1 = v1 - mu, d2 = v2 - mu;
    float ss = d0 * d0 + d1 * d1 + d2 * d2;
    #pragma unroll
    for (int o = 16; o > 0; o >>= 1) ss += __shfl_xor_sync(0xffffffffu, ss, o);
    __syncthreads();            // protect red[] reuse
    if ((t & 31) == 0) red[t >> 5] = ss;
    __syncthreads();
    if (t == 0) { float tot = 0.f; for (int i = 0; i < 8; i++) tot += red[i]; bc = tot; }
    __syncthreads();
    float rs = rsqrtf(bc * (1.f / 768.f) + 1e-5f);

    yr[t]       = d0 * rs * g[t]       + b[t];
    yr[t + 256] = d1 * rs * g[t + 256] + b[t + 256];
    yr[t + 512] = d2 * rs * g[t + 512] + b[t + 512];
}

// ======================================================================
// Fused attention: one block per (head, batch). K,V in smem (stride-68
// padded, conflict-free float4). 8 warps; each warp owns queries w, w+8, ...
// ======================================================================
#define KVS 68
__global__ __launch_bounds__(256) void attn_kernel(
    const float* __restrict__ qkv, const float* __restrict__ clsbias,
    float* __restrict__ out)
{
    extern __shared__ float sm[];
    float* Ks = sm;                       // 197*68
    float* Vs = sm + S_ * KVS;            // 197*68
    float* Ps = Vs + S_ * KVS;            // 8*200

    const int h = blockIdx.x, b = blockIdx.y;
    const int tid = threadIdx.x;
    const int w = tid >> 5, lane = tid & 31;
    const size_t base = (size_t)b * S_ * QKV3;

    for (int i = tid; i < S_ * HD_; i += 256) {
        int s_ = i >> 6, hd = i & 63;
        size_t off = base + (size_t)s_ * QKV3 + h * HD_ + hd;
        Ks[s_ * KVS + hd] = qkv[off + D_];
        Vs[s_ * KVS + hd] = qkv[off + 2 * D_];
    }
    __syncthreads();

    for (int q = w; q < S_; q += 8) {
        const float4* qp = (const float4*)(qkv + base + (size_t)q * QKV3 + h * HD_);
        float4 qr[16];
        #pragma unroll
        for (int i = 0; i < 16; i++) qr[i] = qp[i];

        float sc[7];
        #pragma unroll
        for (int t = 0; t < 7; t++) {
            int k = lane + 32 * t;
            float sv = -1e30f;
            if (k < S_) {
                const float4* kp = (const float4*)(Ks + k * KVS);
                float a = 0.f;
                #pragma unroll
                for (int i = 0; i < 16; i++) {
                    float4 kk = kp[i];
                    a += qr[i].x * kk.x + qr[i].y * kk.y + qr[i].z * kk.z + qr[i].w * kk.w;
                }
                sv = a * 0.125f;
                if (clsbias && q == 0 && k >= 1) sv += clsbias[b * L_ + (k - 1)];
            }
            sc[t] = sv;
        }
        // softmax over k (warp-wide)
        float m = sc[0];
        #pragma unroll
        for (int t = 1; t < 7; t++) m = fmaxf(m, sc[t]);
        #pragma unroll
        for (int o = 16; o > 0; o >>= 1) m = fmaxf(m, __shfl_xor_sync(0xffffffffu, m, o));
        float se = 0.f;
        #pragma unroll
        for (int t = 0; t < 7; t++) {
            float e = (sc[t] > -1e29f) ? expf(sc[t] - m) : 0.f;
            sc[t] = e; se += e;
        }
        #pragma unroll
        for (int o = 16; o > 0; o >>= 1) se += __shfl_xor_sync(0xffffffffu, se, o);
        float inv = 1.f / se;
        #pragma unroll
        for (int t = 0; t < 7; t++) {
            int k = lane + 32 * t;
            if (k < S_) Ps[w * 200 + k] = sc[t] * inv;
        }
        __syncwarp();

        float o0 = 0.f, o1 = 0.f;
        for (int k = 0; k < S_; k++) {
            float p = Ps[w * 200 + k];
            o0 += p * Vs[k * KVS + lane];
            o1 += p * Vs[k * KVS + 32 + lane];
        }
        size_t orow = ((size_t)b * S_ + q) * D_ + h * HD_;
        out[orow + lane] = o0;
        out[orow + 32 + lane] = o1;
        __syncwarp();
    }
}

// ======================================================================
// Patch embed helpers
// ======================================================================
__global__ void im2col_kernel(const float* __restrict__ masked,
                              const float* __restrict__ prompted,
                              float* __restrict__ col)
{
    int idx = blockIdx.x * 256 + threadIdx.x;
    const int total = B2 * L_ * D_;
    if (idx >= total) return;
    int k = idx % D_;
    int m = idx / D_;
    int b = m / L_, l = m % L_;
    int gy = l / GRID_, gx = l % GRID_;
    int c = k >> 8, rem = k & 255;
    int py = rem >> 4, px = rem & 15;
    const float* src = (b < NB) ? (masked + (size_t)b * 3 * IMG_ * IMG_)
                                : (prompted + (size_t)(b - NB) * 3 * IMG_ * IMG_);
    col[idx] = src[((size_t)c * IMG_ + gy * PCH_ + py) * IMG_ + gx * PCH_ + px];
}

__global__ void embed_kernel(const float* __restrict__ conv_out,
                             const float* __restrict__ cls_emb,
                             const float* __restrict__ pos,
                             float* __restrict__ x)
{
    int idx = blockIdx.x * 256 + threadIdx.x;
    const int total = B2 * S_ * D_;
    if (idx >= total) return;
    int d = idx % D_;
    int bs = idx / D_;
    int s = bs % S_, b = bs / S_;
    float v = (s == 0) ? cls_emb[d] : conv_out[((size_t)b * L_ + (s - 1)) * D_ + d];
    x[idx] = v + pos[s * D_ + d];
}

__global__ void clsbias_kernel(const float* __restrict__ pm, float* __restrict__ cb)
{
    int i = blockIdx.x * 256 + threadIdx.x;
    if (i < NB * L_) cb[i] = (pm[i] != 0.f) ? 0.f : -1e30f;
}

// xa: x[:16] = 2 * (x2 with tokens masked) + x    (in place on x region)
__global__ void mask_combine_kernel(float* __restrict__ x, const float* __restrict__ x2,
                                    const float* __restrict__ pm)
{
    int idx = blockIdx.x * 256 + threadIdx.x;
    const int total = NB * S_ * D_;
    if (idx >= total) return;
    int bs = idx / D_;
    int s = bs % S_, b = bs / S_;
    float mf = (s == 0) ? 1.f : pm[b * L_ + (s - 1)];
    x[idx] = 2.f * x2[idx] * mf + x[idx];
}

// final: out[16,512] = cls_ln[16,768] @ proj[768,512]
__global__ void proj_out_kernel(const float* __restrict__ cls,
                                const float* __restrict__ proj,
                                float* __restrict__ out)
{
    int n = blockIdx.x * 256 + threadIdx.x;
    int m = blockIdx.y;
    if (n >= OUT_) return;
    float s = 0.f;
    #pragma unroll 4
    for (int k = 0; k < D_; k++) s += cls[m * D_ + k] * proj[(size_t)k * OUT_ + n];
    out[m * OUT_ + n] = s;
}

// ======================================================================
// Host orchestration
// ======================================================================
static float* symaddr(const void* s) {
    void* p = nullptr;
    cudaGetSymbolAddress(&p, s);
    return (float*)p;
}

static void run_gemm(const float* A, const float* B, const float* bias,
                     const float* resid, float* C, int M, int N, int K, int act)
{
    dim3 grid(N / 128, (M + 127) / 128);
    gemm_kernel<<<grid, 256>>>(A, B, bias, resid, C, M, N, K, act);
}

struct Ctx {
    float *x12, *xln, *qkv, *att, *ffh, *col, *clsb;
    const float *Wqkv, *bqkv, *Wo, *bo, *ln1g, *ln1b, *ln2g, *ln2b, *Wfc, *bfc, *Wp, *bp;
    int attn_smem;
};

static void run_block(const Ctx& c, float* x, int Bn, int layer, const float* bias)
{
    const int M = Bn * S_;
    ln_kernel<<<M, 256>>>(x, D_, c.xln, D_, c.ln1g + layer * D_, c.ln1b + layer * D_, M);
    run_gemm(c.xln, c.Wqkv + (size_t)layer * QKV3 * D_, c.bqkv + layer * QKV3,
             nullptr, c.qkv, M, QKV3, D_, 0);
    attn_kernel<<<dim3(H_, Bn), 256, c.attn_smem>>>(c.qkv, bias, c.att);
    run_gemm(c.att, c.Wo + (size_t)layer * D_ * D_, c.bo + layer * D_,
             x, x, M, D_, D_, 0);
    ln_kernel<<<M, 256>>>(x, D_, c.xln, D_, c.ln2g + layer * D_, c.ln2b + layer * D_, M);
    run_gemm(c.xln, c.Wfc + (size_t)layer * FF_ * D_, c.bfc + layer * FF_,
             nullptr, c.ffh, M, FF_, D_, 1);
    run_gemm(c.ffh, c.Wp + (size_t)layer * D_ * FF_, c.bp + layer * D_,
             x, x, M, D_, FF_, 0);
}

extern "C" void kernel_launch(void* const* d_in, const int* in_sizes, int n_in,
                              void* d_out, int out_size)
{
    const float* masked   = (const float*)d_in[0];
    const float* prompted = (const float*)d_in[1];
    const float* pred     = (const float*)d_in[2];
    const float* conv_w   = (const float*)d_in[3];
    const float* cls_emb  = (const float*)d_in[4];
    const float* pos_emb  = (const float*)d_in[5];
    const float* lnpre_g  = (const float*)d_in[6];
    const float* lnpre_b  = (const float*)d_in[7];

    Ctx c;
    c.Wqkv = (const float*)d_in[8];   c.bqkv = (const float*)d_in[9];
    c.Wo   = (const float*)d_in[10];  c.bo   = (const float*)d_in[11];
    c.ln1g = (const float*)d_in[12];  c.ln1b = (const float*)d_in[13];
    c.ln2g = (const float*)d_in[14];  c.ln2b = (const float*)d_in[15];
    c.Wfc  = (const float*)d_in[16];  c.bfc  = (const float*)d_in[17];
    c.Wp   = (const float*)d_in[18];  c.bp   = (const float*)d_in[19];
    const float* lnpost_g = (const float*)d_in[20];
    const float* lnpost_b = (const float*)d_in[21];
    const float* proj     = (const float*)d_in[22];
    float* out = (float*)d_out;

    c.x12  = symaddr(g_x12);
    c.xln  = symaddr(g_xln);
    c.qkv  = symaddr(g_qkv);
    c.att  = symaddr(g_att);
    c.ffh  = symaddr(g_ffh);
    c.col  = symaddr(g_im2col);
    c.clsb = symaddr(g_clsb);

    c.attn_smem = (2 * S_ * KVS + 8 * 200) * (int)sizeof(float);   // 113,568 B
    cudaFuncSetAttribute(attn_kernel, cudaFuncAttributeMaxDynamicSharedMemorySize,
                         c.attn_smem);

    // ---- patch embed (im2col GEMM) ----
    {
        const int total = B2 * L_ * D_;
        im2col_kernel<<<(total + 255) / 256, 256>>>(masked, prompted, c.col);
        // conv_w is (768, 3*16*16) contiguous → exactly (N,K) for our GEMM
        run_gemm(c.col, conv_w, nullptr, nullptr, c.att, B2 * L_, D_, D_, 0);
        const int tot2 = B2 * S_ * D_;
        embed_kernel<<<(tot2 + 255) / 256, 256>>>(c.att, cls_emb, pos_emb, c.x12);
        ln_kernel<<<B2 * S_, 256>>>(c.x12, D_, c.x12, D_, lnpre_g, lnpre_b, B2 * S_);
    }

    clsbias_kernel<<<(NB * L_ + 255) / 256, 256>>>(pred, c.clsb);

    // ---- 10 standard blocks on the concatenated batch ----
    for (int i = 0; i < 10; i++)
        run_block(c, c.x12, B2, i, nullptr);

    // ---- masking phase: layers 10 and 11 ----
    float* x  = c.x12;
    float* x2 = c.x12 + (size_t)NB * S_ * D_;
    const int layers2[2] = {10, 11};
    for (int t = 0; t < 2; t++) {
        int i = layers2[t];
        const int tot = NB * S_ * D_;
        mask_combine_kernel<<<(tot + 255) / 256, 256>>>(x, x2, pred);
        run_block(c, x, NB, i, nullptr);
        run_block(c, x2, NB, i, c.clsb);
    }

    // ---- head: LN_post on cls token, then @ proj ----
    ln_kernel<<<NB, 256>>>(x, (long)S_ * D_, c.xln, D_, lnpost_g, lnpost_b, NB);
    proj_out_kernel<<<dim3((OUT_ + 255) / 256, NB), 256>>>(c.xln, proj, out);

    (void)in_sizes; (void)n_in; (void)out_size;
}

// round 4
// speedup vs baseline: 1.0001x; 1.0001x over previous
#include <cuda_runtime.h>
#include <math.h>

// ---------------- Problem constants ----------------
#define D_    768
#define H_    12
#define HD_   64
#define S_    197
#define L_    196
#define NB    16          // batch per image set
#define B2    32          // both image sets
#define FF_   3072
#define OUT_  512
#define QKV3  2304
#define IMG_  224
#define GRID_ 14
#define PCH_  16

// ---------------- Scratch (device globals; no allocation allowed) ----------------
__device__ float g_x12[B2 * S_ * D_];      // residual stream (x | x2)
__device__ float g_xln[B2 * S_ * D_];      // LN output
__device__ float g_qkv[B2 * S_ * QKV3];    // qkv
__device__ float g_att[B2 * S_ * D_];      // attention out (also conv_out temp)
__device__ float g_ffh[B2 * S_ * FF_];     // MLP hidden
__device__ float g_im2col[B2 * L_ * D_];   // patch im2col
__device__ float g_clsb[NB * L_];          // cls-row attention bias

// ======================================================================
// GEMM: C[M,N] = act( A[M,K] @ B[N,K]^T + bias[N] ) + resid[M,N]
// 128x128 tile, BK=8, 256 threads, 8x8 microtile (z-ordered), float4 smem.
// ======================================================================
__global__ __launch_bounds__(256) void gemm_kernel(
    const float* __restrict__ A, const float* __restrict__ B,
    const float* __restrict__ bias, const float* __restrict__ resid,
    float* __restrict__ C, int M, int N, int K, int act)
{
    __shared__ float As[8][132];
    __shared__ float Bs[8][132];

    const int bm = blockIdx.y * 128;
    const int bn = blockIdx.x * 128;
    const int tid = threadIdx.x;
    const int tx = tid & 15;       // 0..15
    const int ty = tid >> 4;       // 0..15

    const int lrow = tid >> 1;            // 0..127
    const int lcol = (tid & 1) * 4;       // 0 or 4

    float acc[8][8];
    #pragma unroll
    for (int i = 0; i < 8; i++)
        #pragma unroll
        for (int j = 0; j < 8; j++) acc[i][j] = 0.f;

    const bool avalid = (bm + lrow) < M;
    const float* Aptr = A + (size_t)(bm + lrow) * K + lcol;
    const float* Bptr = B + (size_t)(bn + lrow) * K + lcol;

    for (int k0 = 0; k0 < K; k0 += 8) {
        float4 av = avalid ? *(const float4*)(Aptr + k0) : make_float4(0.f, 0.f, 0.f, 0.f);
        float4 bv = *(const float4*)(Bptr + k0);
        As[lcol + 0][lrow] = av.x; As[lcol + 1][lrow] = av.y;
        As[lcol + 2][lrow] = av.z; As[lcol + 3][lrow] = av.w;
        Bs[lcol + 0][lrow] = bv.x; Bs[lcol + 1][lrow] = bv.y;
        Bs[lcol + 2][lrow] = bv.z; Bs[lcol + 3][lrow] = bv.w;
        __syncthreads();

        #pragma unroll
        for (int kk = 0; kk < 8; kk++) {
            float a[8], b[8];
            *(float4*)&a[0] = *(const float4*)&As[kk][ty * 4];
            *(float4*)&a[4] = *(const float4*)&As[kk][64 + ty * 4];
            *(float4*)&b[0] = *(const float4*)&Bs[kk][tx * 4];
            *(float4*)&b[4] = *(const float4*)&Bs[kk][64 + tx * 4];
            #pragma unroll
            for (int i = 0; i < 8; i++)
                #pragma unroll
                for (int j = 0; j < 8; j++)
                    acc[i][j] += a[i] * b[j];
        }
        __syncthreads();
    }

    #pragma unroll
    for (int i = 0; i < 8; i++) {
        int gm = bm + ((i < 4) ? (ty * 4 + i) : (64 + ty * 4 + i - 4));
        if (gm >= M) continue;
        #pragma unroll
        for (int j = 0; j < 8; j++) {
            int gn = bn + ((j < 4) ? (tx * 4 + j) : (64 + tx * 4 + j - 4));
            float v = acc[i][j];
            if (bias)  v += bias[gn];
            if (act)   v = v / (1.f + expf(-1.702f * v));   // GELU(sigmoid approx)
            if (resid) v += resid[(size_t)gm * N + gn];
            C[(size_t)gm * N + gn] = v;
        }
    }
}

// ======================================================================
// LayerNorm: one block (256 thr) per row of 768.
// ======================================================================
__global__ __launch_bounds__(256) void ln_kernel(
    const float* __restrict__ x, long in_stride,
    float* __restrict__ y, long out_stride,
    const float* __restrict__ g, const float* __restrict__ b, int rows)
{
    int r = blockIdx.x;
    if (r >= rows) return;
    const float* xr = x + (size_t)r * in_stride;
    float* yr = y + (size_t)r * out_stride;
    int t = threadIdx.x;

    float v0 = xr[t], v1 = xr[t + 256], v2 = xr[t + 512];

    __shared__ float red[8];
    __shared__ float bc;

    // mean
    float s = v0 + v1 + v2;
    #pragma unroll
    for (int o = 16; o > 0; o >>= 1) s += __shfl_xor_sync(0xffffffffu, s, o);
    if ((t & 31) == 0) red[t >> 5] = s;
    __syncthreads();
    if (t == 0) { float tot = 0.f; for (int i = 0; i < 8; i++) tot += red[i]; bc = tot; }
    __syncthreads();
    float mu = bc * (1.f / 768.f);

    float d0 = v0 - mu, d1 = v1 - mu, d2 = v2 - mu;
    float ss = d0 * d0 + d1 * d1 + d2 * d2;
    #pragma unroll
    for (int o = 16; o > 0; o >>= 1) ss += __shfl_xor_sync(0xffffffffu, ss, o);
    __syncthreads();            // protect red[] reuse
    if ((t & 31) == 0) red[t >> 5] = ss;
    __syncthreads();
    if (t == 0) { float tot = 0.f; for (int i = 0; i < 8; i++) tot += red[i]; bc = tot; }
    __syncthreads();
    float rs = rsqrtf(bc * (1.f / 768.f) + 1e-5f);

    yr[t]       = d0 * rs * g[t]       + b[t];
    yr[t + 256] = d1 * rs * g[t + 256] + b[t + 256];
    yr[t + 512] = d2 * rs * g[t + 512] + b[t + 512];
}

// ======================================================================
// Fused attention: one block per (head, batch). K,V in smem (stride-68
// padded, conflict-free float4). 8 warps; each warp owns queries w, w+8, ...
// ======================================================================
#define KVS 68
__global__ __launch_bounds__(256) void attn_kernel(
    const float* __restrict__ qkv, const float* __restrict__ clsbias,
    float* __restrict__ out)
{
    extern __shared__ float sm[];
    float* Ks = sm;                       // 197*68
    float* Vs = sm + S_ * KVS;            // 197*68
    float* Ps = Vs + S_ * KVS;            // 8*200

    const int h = blockIdx.x, b = blockIdx.y;
    const int tid = threadIdx.x;
    const int w = tid >> 5, lane = tid & 31;
    const size_t base = (size_t)b * S_ * QKV3;

    for (int i = tid; i < S_ * HD_; i += 256) {
        int s_ = i >> 6, hd = i & 63;
        size_t off = base + (size_t)s_ * QKV3 + h * HD_ + hd;
        Ks[s_ * KVS + hd] = qkv[off + D_];
        Vs[s_ * KVS + hd] = qkv[off + 2 * D_];
    }
    __syncthreads();

    for (int q = w; q < S_; q += 8) {
        const float4* qp = (const float4*)(qkv + base + (size_t)q * QKV3 + h * HD_);
        float4 qr[16];
        #pragma unroll
        for (int i = 0; i < 16; i++) qr[i] = qp[i];

        float sc[7];
        #pragma unroll
        for (int t = 0; t < 7; t++) {
            int k = lane + 32 * t;
            float sv = -1e30f;
            if (k < S_) {
                const float4* kp = (const float4*)(Ks + k * KVS);
                float a = 0.f;
                #pragma unroll
                for (int i = 0; i < 16; i++) {
                    float4 kk = kp[i];
                    a += qr[i].x * kk.x + qr[i].y * kk.y + qr[i].z * kk.z + qr[i].w * kk.w;
                }
                sv = a * 0.125f;
                if (clsbias && q == 0 && k >= 1) sv += clsbias[b * L_ + (k - 1)];
            }
            sc[t] = sv;
        }
        // softmax over k (warp-wide)
        float m = sc[0];
        #pragma unroll
        for (int t = 1; t < 7; t++) m = fmaxf(m, sc[t]);
        #pragma unroll
        for (int o = 16; o > 0; o >>= 1) m = fmaxf(m, __shfl_xor_sync(0xffffffffu, m, o));
        float se = 0.f;
        #pragma unroll
        for (int t = 0; t < 7; t++) {
            float e = (sc[t] > -1e29f) ? expf(sc[t] - m) : 0.f;
            sc[t] = e; se += e;
        }
        #pragma unroll
        for (int o = 16; o > 0; o >>= 1) se += __shfl_xor_sync(0xffffffffu, se, o);
        float inv = 1.f / se;
        #pragma unroll
        for (int t = 0; t < 7; t++) {
            int k = lane + 32 * t;
            if (k < S_) Ps[w * 200 + k] = sc[t] * inv;
        }
        __syncwarp();

        float o0 = 0.f, o1 = 0.f;
        for (int k = 0; k < S_; k++) {
            float p = Ps[w * 200 + k];
            o0 += p * Vs[k * KVS + lane];
            o1 += p * Vs[k * KVS + 32 + lane];
        }
        size_t orow = ((size_t)b * S_ + q) * D_ + h * HD_;
        out[orow + lane] = o0;
        out[orow + 32 + lane] = o1;
        __syncwarp();
    }
}

// ======================================================================
// Patch embed helpers
// ======================================================================
__global__ void im2col_kernel(const float* __restrict__ masked,
                              const float* __restrict__ prompted,
                              float* __restrict__ col)
{
    int idx = blockIdx.x * 256 + threadIdx.x;
    const int total = B2 * L_ * D_;
    if (idx >= total) return;
    int k = idx % D_;
    int m = idx / D_;
    int b = m / L_, l = m % L_;
    int gy = l / GRID_, gx = l % GRID_;
    int c = k >> 8, rem = k & 255;
    int py = rem >> 4, px = rem & 15;
    const float* src = (b < NB) ? (masked + (size_t)b * 3 * IMG_ * IMG_)
                                : (prompted + (size_t)(b - NB) * 3 * IMG_ * IMG_);
    col[idx] = src[((size_t)c * IMG_ + gy * PCH_ + py) * IMG_ + gx * PCH_ + px];
}

__global__ void embed_kernel(const float* __restrict__ conv_out,
                             const float* __restrict__ cls_emb,
                             const float* __restrict__ pos,
                             float* __restrict__ x)
{
    int idx = blockIdx.x * 256 + threadIdx.x;
    const int total = B2 * S_ * D_;
    if (idx >= total) return;
    int d = idx % D_;
    int bs = idx / D_;
    int s = bs % S_, b = bs / S_;
    float v = (s == 0) ? cls_emb[d] : conv_out[((size_t)b * L_ + (s - 1)) * D_ + d];
    x[idx] = v + pos[s * D_ + d];
}

__global__ void clsbias_kernel(const float* __restrict__ pm, float* __restrict__ cb)
{
    int i = blockIdx.x * 256 + threadIdx.x;
    if (i < NB * L_) cb[i] = (pm[i] != 0.f) ? 0.f : -1e30f;
}

// xa: x[:16] = 2 * (x2 with tokens masked) + x    (in place on x region)
__global__ void mask_combine_kernel(float* __restrict__ x, const float* __restrict__ x2,
                                    const float* __restrict__ pm)
{
    int idx = blockIdx.x * 256 + threadIdx.x;
    const int total = NB * S_ * D_;
    if (idx >= total) return;
    int bs = idx / D_;
    int s = bs % S_, b = bs / S_;
    float mf = (s == 0) ? 1.f : pm[b * L_ + (s - 1)];
    x[idx] = 2.f * x2[idx] * mf + x[idx];
}

// final: out[16,512] = cls_ln[16,768] @ proj[768,512]
__global__ void proj_out_kernel(const float* __restrict__ cls,
                                const float* __restrict__ proj,
                                float* __restrict__ out)
{
    int n = blockIdx.x * 256 + threadIdx.x;
    int m = blockIdx.y;
    if (n >= OUT_) return;
    float s = 0.f;
    #pragma unroll 4
    for (int k = 0; k < D_; k++) s += cls[m * D_ + k] * proj[(size_t)k * OUT_ + n];
    out[m * OUT_ + n] = s;
}

// ======================================================================
// Host orchestration
// ======================================================================
static float* symaddr(const void* s) {
    void* p = nullptr;
    cudaGetSymbolAddress(&p, s);
    return (float*)p;
}

static void run_gemm(const float* A, const float* B, const float* bias,
                     const float* resid, float* C, int M, int N, int K, int act)
{
    dim3 grid(N / 128, (M + 127) / 128);
    gemm_kernel<<<grid, 256>>>(A, B, bias, resid, C, M, N, K, act);
}

struct Ctx {
    float *x12, *xln, *qkv, *att, *ffh, *col, *clsb;
    const float *Wqkv, *bqkv, *Wo, *bo, *ln1g, *ln1b, *ln2g, *ln2b, *Wfc, *bfc, *Wp, *bp;
    int attn_smem;
};

static void run_block(const Ctx& c, float* x, int Bn, int layer, const float* bias)
{
    const int M = Bn * S_;
    ln_kernel<<<M, 256>>>(x, D_, c.xln, D_, c.ln1g + layer * D_, c.ln1b + layer * D_, M);
    run_gemm(c.xln, c.Wqkv + (size_t)layer * QKV3 * D_, c.bqkv + layer * QKV3,
             nullptr, c.qkv, M, QKV3, D_, 0);
    attn_kernel<<<dim3(H_, Bn), 256, c.attn_smem>>>(c.qkv, bias, c.att);
    run_gemm(c.att, c.Wo + (size_t)layer * D_ * D_, c.bo + layer * D_,
             x, x, M, D_, D_, 0);
    ln_kernel<<<M, 256>>>(x, D_, c.xln, D_, c.ln2g + layer * D_, c.ln2b + layer * D_, M);
    run_gemm(c.xln, c.Wfc + (size_t)layer * FF_ * D_, c.bfc + layer * FF_,
             nullptr, c.ffh, M, FF_, D_, 1);
    run_gemm(c.ffh, c.Wp + (size_t)layer * D_ * FF_, c.bp + layer * D_,
             x, x, M, D_, FF_, 0);
}

extern "C" void kernel_launch(void* const* d_in, const int* in_sizes, int n_in,
                              void* d_out, int out_size)
{
    const float* masked   = (const float*)d_in[0];
    const float* prompted = (const float*)d_in[1];
    const float* pred     = (const float*)d_in[2];
    const float* conv_w   = (const float*)d_in[3];
    const float* cls_emb  = (const float*)d_in[4];
    const float* pos_emb  = (const float*)d_in[5];
    const float* lnpre_g  = (const float*)d_in[6];
    const float* lnpre_b  = (const float*)d_in[7];

    Ctx c;
    c.Wqkv = (const float*)d_in[8];   c.bqkv = (const float*)d_in[9];
    c.Wo   = (const float*)d_in[10];  c.bo   = (const float*)d_in[11];
    c.ln1g = (const float*)d_in[12];  c.ln1b = (const float*)d_in[13];
    c.ln2g = (const float*)d_in[14];  c.ln2b = (const float*)d_in[15];
    c.Wfc  = (const float*)d_in[16];  c.bfc  = (const float*)d_in[17];
    c.Wp   = (const float*)d_in[18];  c.bp   = (const float*)d_in[19];
    const float* lnpost_g = (const float*)d_in[20];
    const float* lnpost_b = (const float*)d_in[21];
    const float* proj     = (const float*)d_in[22];
    float* out = (float*)d_out;

    c.x12  = symaddr(g_x12);
    c.xln  = symaddr(g_xln);
    c.qkv  = symaddr(g_qkv);
    c.att  = symaddr(g_att);
    c.ffh  = symaddr(g_ffh);
    c.col  = symaddr(g_im2col);
    c.clsb = symaddr(g_clsb);

    c.attn_smem = (2 * S_ * KVS + 8 * 200) * (int)sizeof(float);   // 113,568 B
    cudaFuncSetAttribute(attn_kernel, cudaFuncAttributeMaxDynamicSharedMemorySize,
                         c.attn_smem);

    // ---- patch embed (im2col GEMM) ----
    {
        const int total = B2 * L_ * D_;
        im2col_kernel<<<(total + 255) / 256, 256>>>(masked, prompted, c.col);
        // conv_w is (768, 3*16*16) contiguous → exactly (N,K) for our GEMM
        run_gemm(c.col, conv_w, nullptr, nullptr, c.att, B2 * L_, D_, D_, 0);
        const int tot2 = B2 * S_ * D_;
        embed_kernel<<<(tot2 + 255) / 256, 256>>>(c.att, cls_emb, pos_emb, c.x12);
        ln_kernel<<<B2 * S_, 256>>>(c.x12, D_, c.x12, D_, lnpre_g, lnpre_b, B2 * S_);
    }

    clsbias_kernel<<<(NB * L_ + 255) / 256, 256>>>(pred, c.clsb);

    // ---- 10 standard blocks on the concatenated batch ----
    for (int i = 0; i < 10; i++)
        run_block(c, c.x12, B2, i, nullptr);

    // ---- masking phase: layers 10 and 11 ----
    float* x  = c.x12;
    float* x2 = c.x12 + (size_t)NB * S_ * D_;
    const int layers2[2] = {10, 11};
    for (int t = 0; t < 2; t++) {
        int i = layers2[t];
        const int tot = NB * S_ * D_;
        mask_combine_kernel<<<(tot + 255) / 256, 256>>>(x, x2, pred);
        run_block(c, x, NB, i, nullptr);
        run_block(c, x2, NB, i, c.clsb);
    }

    // ---- head: LN_post on cls token, then @ proj ----
    ln_kernel<<<NB, 256>>>(x, (long)S_ * D_, c.xln, D_, lnpost_g, lnpost_b, NB);
    proj_out_kernel<<<dim3((OUT_ + 255) / 256, NB), 256>>>(c.xln, proj, out);

    (void)in_sizes; (void)n_in; (void)out_size;
}

// round 5
// speedup vs baseline: 1.0007x; 1.0006x over previous
#include <cuda_runtime.h>
#include <math.h>

// ---------------- Problem constants ----------------
#define D_    768
#define H_    12
#define HD_   64
#define S_    197
#define L_    196
#define NB    16          // batch per image set
#define B2    32          // both image sets
#define FF_   3072
#define OUT_  512
#define QKV3  2304
#define IMG_  224
#define GRID_ 14
#define PCH_  16

// ---------------- Scratch (device globals; no allocation allowed) ----------------
__device__ float g_x12[B2 * S_ * D_];      // residual stream (x | x2)
__device__ float g_xln[B2 * S_ * D_];      // LN output
__device__ float g_qkv[B2 * S_ * QKV3];    // qkv
__device__ float g_att[B2 * S_ * D_];      // attention out (also conv_out temp)
__device__ float g_ffh[B2 * S_ * FF_];     // MLP hidden
__device__ float g_im2col[B2 * L_ * D_];   // patch im2col
__device__ float g_clsb[NB * L_];          // cls-row attention bias

// ======================================================================
// GEMM: C[M,N] = act( A[M,K] @ B[N,K]^T + bias[N] ) + resid[M,N]
// 128x128 tile, BK=8, 256 threads, 8x8 microtile (z-ordered), float4 smem.
// ======================================================================
__global__ __launch_bounds__(256) void gemm_kernel(
    const float* __restrict__ A, const float* __restrict__ B,
    const float* __restrict__ bias, const float* __restrict__ resid,
    float* __restrict__ C, int M, int N, int K, int act)
{
    __shared__ float As[8][132];
    __shared__ float Bs[8][132];

    const int bm = blockIdx.y * 128;
    const int bn = blockIdx.x * 128;
    const int tid = threadIdx.x;
    const int tx = tid & 15;       // 0..15
    const int ty = tid >> 4;       // 0..15

    const int lrow = tid >> 1;            // 0..127
    const int lcol = (tid & 1) * 4;       // 0 or 4

    float acc[8][8];
    #pragma unroll
    for (int i = 0; i < 8; i++)
        #pragma unroll
        for (int j = 0; j < 8; j++) acc[i][j] = 0.f;

    const bool avalid = (bm + lrow) < M;
    const float* Aptr = A + (size_t)(bm + lrow) * K + lcol;
    const float* Bptr = B + (size_t)(bn + lrow) * K + lcol;

    for (int k0 = 0; k0 < K; k0 += 8) {
        float4 av = avalid ? *(const float4*)(Aptr + k0) : make_float4(0.f, 0.f, 0.f, 0.f);
        float4 bv = *(const float4*)(Bptr + k0);
        As[lcol + 0][lrow] = av.x; As[lcol + 1][lrow] = av.y;
        As[lcol + 2][lrow] = av.z; As[lcol + 3][lrow] = av.w;
        Bs[lcol + 0][lrow] = bv.x; Bs[lcol + 1][lrow] = bv.y;
        Bs[lcol + 2][lrow] = bv.z; Bs[lcol + 3][lrow] = bv.w;
        __syncthreads();

        #pragma unroll
        for (int kk = 0; kk < 8; kk++) {
            float a[8], b[8];
            *(float4*)&a[0] = *(const float4*)&As[kk][ty * 4];
            *(float4*)&a[4] = *(const float4*)&As[kk][64 + ty * 4];
            *(float4*)&b[0] = *(const float4*)&Bs[kk][tx * 4];
            *(float4*)&b[4] = *(const float4*)&Bs[kk][64 + tx * 4];
            #pragma unroll
            for (int i = 0; i < 8; i++)
                #pragma unroll
                for (int j = 0; j < 8; j++)
                    acc[i][j] += a[i] * b[j];
        }
        __syncthreads();
    }

    #pragma unroll
    for (int i = 0; i < 8; i++) {
        int gm = bm + ((i < 4) ? (ty * 4 + i) : (64 + ty * 4 + i - 4));
        if (gm >= M) continue;
        #pragma unroll
        for (int j = 0; j < 8; j++) {
            int gn = bn + ((j < 4) ? (tx * 4 + j) : (64 + tx * 4 + j - 4));
            float v = acc[i][j];
            if (bias)  v += bias[gn];
            if (act)   v = v / (1.f + expf(-1.702f * v));   // GELU(sigmoid approx)
            if (resid) v += resid[(size_t)gm * N + gn];
            C[(size_t)gm * N + gn] = v;
        }
    }
}

// ======================================================================
// LayerNorm: one block (256 thr) per row of 768.
// ======================================================================
__global__ __launch_bounds__(256) void ln_kernel(
    const float* __restrict__ x, long in_stride,
    float* __restrict__ y, long out_stride,
    const float* __restrict__ g, const float* __restrict__ b, int rows)
{
    int r = blockIdx.x;
    if (r >= rows) return;
    const float* xr = x + (size_t)r * in_stride;
    float* yr = y + (size_t)r * out_stride;
    int t = threadIdx.x;

    float v0 = xr[t], v1 = xr[t + 256], v2 = xr[t + 512];

    __shared__ float red[8];
    __shared__ float bc;

    // mean
    float s = v0 + v1 + v2;
    #pragma unroll
    for (int o = 16; o > 0; o >>= 1) s += __shfl_xor_sync(0xffffffffu, s, o);
    if ((t & 31) == 0) red[t >> 5] = s;
    __syncthreads();
    if (t == 0) { float tot = 0.f; for (int i = 0; i < 8; i++) tot += red[i]; bc = tot; }
    __syncthreads();
    float mu = bc * (1.f / 768.f);

    float d0 = v0 - mu, d1 = v1 - mu, d2 = v2 - mu;
    float ss = d0 * d0 + d1 * d1 + d2 * d2;
    #pragma unroll
    for (int o = 16; o > 0; o >>= 1) ss += __shfl_xor_sync(0xffffffffu, ss, o);
    __syncthreads();            // protect red[] reuse
    if ((t & 31) == 0) red[t >> 5] = ss;
    __syncthreads();
    if (t == 0) { float tot = 0.f; for (int i = 0; i < 8; i++) tot += red[i]; bc = tot; }
    __syncthreads();
    float rs = rsqrtf(bc * (1.f / 768.f) + 1e-5f);

    yr[t]       = d0 * rs * g[t]       + b[t];
    yr[t + 256] = d1 * rs * g[t + 256] + b[t + 256];
    yr[t + 512] = d2 * rs * g[t + 512] + b[t + 512];
}

// ======================================================================
// Fused attention: one block per (head, batch). K,V in smem (stride-68
// padded, conflict-free float4). 8 warps; each warp owns queries w, w+8, ...
// ======================================================================
#define KVS 68
__global__ __launch_bounds__(256) void attn_kernel(
    const float* __restrict__ qkv, const float* __restrict__ clsbias,
    float* __restrict__ out)
{
    extern __shared__ float sm[];
    float* Ks = sm;                       // 197*68
    float* Vs = sm + S_ * KVS;            // 197*68
    float* Ps = Vs + S_ * KVS;            // 8*200

    const int h = blockIdx.x, b = blockIdx.y;
    const int tid = threadIdx.x;
    const int w = tid >> 5, lane = tid & 31;
    const size_t base = (size_t)b * S_ * QKV3;

    for (int i = tid; i < S_ * HD_; i += 256) {
        int s_ = i >> 6, hd = i & 63;
        size_t off = base + (size_t)s_ * QKV3 + h * HD_ + hd;
        Ks[s_ * KVS + hd] = qkv[off + D_];
        Vs[s_ * KVS + hd] = qkv[off + 2 * D_];
    }
    __syncthreads();

    for (int q = w; q < S_; q += 8) {
        const float4* qp = (const float4*)(qkv + base + (size_t)q * QKV3 + h * HD_);
        float4 qr[16];
        #pragma unroll
        for (int i = 0; i < 16; i++) qr[i] = qp[i];

        float sc[7];
        #pragma unroll
        for (int t = 0; t < 7; t++) {
            int k = lane + 32 * t;
            float sv = -1e30f;
            if (k < S_) {
                const float4* kp = (const float4*)(Ks + k * KVS);
                float a = 0.f;
                #pragma unroll
                for (int i = 0; i < 16; i++) {
                    float4 kk = kp[i];
                    a += qr[i].x * kk.x + qr[i].y * kk.y + qr[i].z * kk.z + qr[i].w * kk.w;
                }
                sv = a * 0.125f;
                if (clsbias && q == 0 && k >= 1) sv += clsbias[b * L_ + (k - 1)];
            }
            sc[t] = sv;
        }
        // softmax over k (warp-wide)
        float m = sc[0];
        #pragma unroll
        for (int t = 1; t < 7; t++) m = fmaxf(m, sc[t]);
        #pragma unroll
        for (int o = 16; o > 0; o >>= 1) m = fmaxf(m, __shfl_xor_sync(0xffffffffu, m, o));
        float se = 0.f;
        #pragma unroll
        for (int t = 0; t < 7; t++) {
            float e = (sc[t] > -1e29f) ? expf(sc[t] - m) : 0.f;
            sc[t] = e; se += e;
        }
        #pragma unroll
        for (int o = 16; o > 0; o >>= 1) se += __shfl_xor_sync(0xffffffffu, se, o);
        float inv = 1.f / se;
        #pragma unroll
        for (int t = 0; t < 7; t++) {
            int k = lane + 32 * t;
            if (k < S_) Ps[w * 200 + k] = sc[t] * inv;
        }
        __syncwarp();

        float o0 = 0.f, o1 = 0.f;
        for (int k = 0; k < S_; k++) {
            float p = Ps[w * 200 + k];
            o0 += p * Vs[k * KVS + lane];
            o1 += p * Vs[k * KVS + 32 + lane];
        }
        size_t orow = ((size_t)b * S_ + q) * D_ + h * HD_;
        out[orow + lane] = o0;
        out[orow + 32 + lane] = o1;
        __syncwarp();
    }
}

// ======================================================================
// Patch embed helpers
// ======================================================================
__global__ void im2col_kernel(const float* __restrict__ masked,
                              const float* __restrict__ prompted,
                              float* __restrict__ col)
{
    int idx = blockIdx.x * 256 + threadIdx.x;
    const int total = B2 * L_ * D_;
    if (idx >= total) return;
    int k = idx % D_;
    int m = idx / D_;
    int b = m / L_, l = m % L_;
    int gy = l / GRID_, gx = l % GRID_;
    int c = k >> 8, rem = k & 255;
    int py = rem >> 4, px = rem & 15;
    const float* src = (b < NB) ? (masked + (size_t)b * 3 * IMG_ * IMG_)
                                : (prompted + (size_t)(b - NB) * 3 * IMG_ * IMG_);
    col[idx] = src[((size_t)c * IMG_ + gy * PCH_ + py) * IMG_ + gx * PCH_ + px];
}

__global__ void embed_kernel(const float* __restrict__ conv_out,
                             const float* __restrict__ cls_emb,
                             const float* __restrict__ pos,
                             float* __restrict__ x)
{
    int idx = blockIdx.x * 256 + threadIdx.x;
    const int total = B2 * S_ * D_;
    if (idx >= total) return;
    int d = idx % D_;
    int bs = idx / D_;
    int s = bs % S_, b = bs / S_;
    float v = (s == 0) ? cls_emb[d] : conv_out[((size_t)b * L_ + (s - 1)) * D_ + d];
    x[idx] = v + pos[s * D_ + d];
}

__global__ void clsbias_kernel(const float* __restrict__ pm, float* __restrict__ cb)
{
    int i = blockIdx.x * 256 + threadIdx.x;
    if (i < NB * L_) cb[i] = (pm[i] != 0.f) ? 0.f : -1e30f;
}

// xa: x[:16] = 2 * (x2 with tokens masked) + x    (in place on x region)
__global__ void mask_combine_kernel(float* __restrict__ x, const float* __restrict__ x2,
                                    const float* __restrict__ pm)
{
    int idx = blockIdx.x * 256 + threadIdx.x;
    const int total = NB * S_ * D_;
    if (idx >= total) return;
    int bs = idx / D_;
    int s = bs % S_, b = bs / S_;
    float mf = (s == 0) ? 1.f : pm[b * L_ + (s - 1)];
    x[idx] = 2.f * x2[idx] * mf + x[idx];
}

// final: out[16,512] = cls_ln[16,768] @ proj[768,512]
__global__ void proj_out_kernel(const float* __restrict__ cls,
                                const float* __restrict__ proj,
                                float* __restrict__ out)
{
    int n = blockIdx.x * 256 + threadIdx.x;
    int m = blockIdx.y;
    if (n >= OUT_) return;
    float s = 0.f;
    #pragma unroll 4
    for (int k = 0; k < D_; k++) s += cls[m * D_ + k] * proj[(size_t)k * OUT_ + n];
    out[m * OUT_ + n] = s;
}

// ======================================================================
// Host orchestration
// ======================================================================
static float* symaddr(const void* s) {
    void* p = nullptr;
    cudaGetSymbolAddress(&p, s);
    return (float*)p;
}

static void run_gemm(const float* A, const float* B, const float* bias,
                     const float* resid, float* C, int M, int N, int K, int act)
{
    dim3 grid(N / 128, (M + 127) / 128);
    gemm_kernel<<<grid, 256>>>(A, B, bias, resid, C, M, N, K, act);
}

struct Ctx {
    float *x12, *xln, *qkv, *att, *ffh, *col, *clsb;
    const float *Wqkv, *bqkv, *Wo, *bo, *ln1g, *ln1b, *ln2g, *ln2b, *Wfc, *bfc, *Wp, *bp;
    int attn_smem;
};

static void run_block(const Ctx& c, float* x, int Bn, int layer, const float* bias)
{
    const int M = Bn * S_;
    ln_kernel<<<M, 256>>>(x, D_, c.xln, D_, c.ln1g + layer * D_, c.ln1b + layer * D_, M);
    run_gemm(c.xln, c.Wqkv + (size_t)layer * QKV3 * D_, c.bqkv + layer * QKV3,
             nullptr, c.qkv, M, QKV3, D_, 0);
    attn_kernel<<<dim3(H_, Bn), 256, c.attn_smem>>>(c.qkv, bias, c.att);
    run_gemm(c.att, c.Wo + (size_t)layer * D_ * D_, c.bo + layer * D_,
             x, x, M, D_, D_, 0);
    ln_kernel<<<M, 256>>>(x, D_, c.xln, D_, c.ln2g + layer * D_, c.ln2b + layer * D_, M);
    run_gemm(c.xln, c.Wfc + (size_t)layer * FF_ * D_, c.bfc + layer * FF_,
             nullptr, c.ffh, M, FF_, D_, 1);
    run_gemm(c.ffh, c.Wp + (size_t)layer * D_ * FF_, c.bp + layer * D_,
             x, x, M, D_, FF_, 0);
}

extern "C" void kernel_launch(void* const* d_in, const int* in_sizes, int n_in,
                              void* d_out, int out_size)
{
    const float* masked   = (const float*)d_in[0];
    const float* prompted = (const float*)d_in[1];
    const float* pred     = (const float*)d_in[2];
    const float* conv_w   = (const float*)d_in[3];
    const float* cls_emb  = (const float*)d_in[4];
    const float* pos_emb  = (const float*)d_in[5];
    const float* lnpre_g  = (const float*)d_in[6];
    const float* lnpre_b  = (const float*)d_in[7];

    Ctx c;
    c.Wqkv = (const float*)d_in[8];   c.bqkv = (const float*)d_in[9];
    c.Wo   = (const float*)d_in[10];  c.bo   = (const float*)d_in[11];
    c.ln1g = (const float*)d_in[12];  c.ln1b = (const float*)d_in[13];
    c.ln2g = (const float*)d_in[14];  c.ln2b = (const float*)d_in[15];
    c.Wfc  = (const float*)d_in[16];  c.bfc  = (const float*)d_in[17];
    c.Wp   = (const float*)d_in[18];  c.bp   = (const float*)d_in[19];
    const float* lnpost_g = (const float*)d_in[20];
    const float* lnpost_b = (const float*)d_in[21];
    const float* proj     = (const float*)d_in[22];
    float* out = (float*)d_out;

    c.x12  = symaddr(g_x12);
    c.xln  = symaddr(g_xln);
    c.qkv  = symaddr(g_qkv);
    c.att  = symaddr(g_att);
    c.ffh  = symaddr(g_ffh);
    c.col  = symaddr(g_im2col);
    c.clsb = symaddr(g_clsb);

    c.attn_smem = (2 * S_ * KVS + 8 * 200) * (int)sizeof(float);   // 113,568 B
    cudaFuncSetAttribute(attn_kernel, cudaFuncAttributeMaxDynamicSharedMemorySize,
                         c.attn_smem);

    // ---- patch embed (im2col GEMM) ----
    {
        const int total = B2 * L_ * D_;
        im2col_kernel<<<(total + 255) / 256, 256>>>(masked, prompted, c.col);
        // conv_w is (768, 3*16*16) contiguous → exactly (N,K) for our GEMM
        run_gemm(c.col, conv_w, nullptr, nullptr, c.att, B2 * L_, D_, D_, 0);
        const int tot2 = B2 * S_ * D_;
        embed_kernel<<<(tot2 + 255) / 256, 256>>>(c.att, cls_emb, pos_emb, c.x12);
        ln_kernel<<<B2 * S_, 256>>>(c.x12, D_, c.x12, D_, lnpre_g, lnpre_b, B2 * S_);
    }

    clsbias_kernel<<<(NB * L_ + 255) / 256, 256>>>(pred, c.clsb);

    // ---- 10 standard blocks on the concatenated batch ----
    for (int i = 0; i < 10; i++)
        run_block(c, c.x12, B2, i, nullptr);

    // ---- masking phase: layers 10 and 11 ----
    float* x  = c.x12;
    float* x2 = c.x12 + (size_t)NB * S_ * D_;
    const int layers2[2] = {10, 11};
    for (int t = 0; t < 2; t++) {
        int i = layers2[t];
        const int tot = NB * S_ * D_;
        mask_combine_kernel<<<(tot + 255) / 256, 256>>>(x, x2, pred);
        run_block(c, x, NB, i, nullptr);
        run_block(c, x2, NB, i, c.clsb);
    }

    // ---- head: LN_post on cls token, then @ proj ----
    ln_kernel<<<NB, 256>>>(x, (long)S_ * D_, c.xln, D_, lnpost_g, lnpost_b, NB);
    proj_out_kernel<<<dim3((OUT_ + 255) / 256, NB), 256>>>(c.xln, proj, out);

    (void)in_sizes; (void)n_in; (void)out_size;
}

// round 6
// speedup vs baseline: 2.2983x; 2.2968x over previous
#include <cuda_runtime.h>
#include <math.h>
#include <stdint.h>

// ---------------- Problem constants ----------------
#define D_    768
#define H_    12
#define HD_   64
#define S_    197
#define L_    196
#define NB    16          // batch per image set
#define B2    32          // both image sets
#define FF_   3072
#define OUT_  512
#define QKV3  2304
#define IMG_  224
#define GRID_ 14
#define PCH_  16

// ---------------- Scratch (device globals; no allocation allowed) ----------------
__device__ float g_x12[B2 * S_ * D_];      // residual stream (x | x2)
__device__ float g_xln[B2 * S_ * D_];      // LN output
__device__ float g_qkv[B2 * S_ * QKV3];    // qkv
__device__ float g_att[B2 * S_ * D_];      // attention out (also conv_out temp)
__device__ float g_ffh[B2 * S_ * FF_];     // MLP hidden
__device__ float g_im2col[B2 * L_ * D_];   // patch im2col
__device__ float g_clsb[NB * L_];          // cls-row attention bias

// ======================================================================
// TF32 tensor-core GEMM:
//   C[M,N] = act( A[M,K] @ B[N,K]^T + bias[N] ) + resid[M,N]
// 128x128x32 block tile, 256 threads (8 warps, 4x2), warp tile 32x64.
// mma.sync m16n8k8 tf32, cp.async double-buffered smem, stride-36 smem
// (conflict-free fragment loads: bank = 4*grp + qid).
// ======================================================================
#define TBK  32
#define TSTR 36          // smem row stride in words
#define TSTAGE (128 * TSTR)   // words per stage per operand

__device__ __forceinline__ uint32_t f2tf32(float x) {
    uint32_t u;
    asm("cvt.rna.tf32.f32 %0, %1;" : "=r"(u) : "f"(x));
    return u;
}

#define MMA_TF32(d, a, b)                                             \
    asm volatile(                                                     \
        "mma.sync.aligned.m16n8k8.row.col.f32.tf32.tf32.f32 "         \
        "{%0,%1,%2,%3}, {%4,%5,%6,%7}, {%8,%9}, {%0,%1,%2,%3};"       \
        : "+f"(d[0]), "+f"(d[1]), "+f"(d[2]), "+f"(d[3])              \
        : "r"(a[0]), "r"(a[1]), "r"(a[2]), "r"(a[3]),                 \
          "r"(b[0]), "r"(b[1]))

__global__ __launch_bounds__(256, 2) void gemm_tc(
    const float* __restrict__ A, const float* __restrict__ B,
    const float* __restrict__ bias, const float* __restrict__ resid,
    float* __restrict__ C, int M, int N, int K, int act)
{
    extern __shared__ float sm[];
    float* As = sm;                    // 2 stages * 128*36
    float* Bs = sm + 2 * TSTAGE;       // 2 stages * 128*36

    const int tid  = threadIdx.x;
    const int lane = tid & 31, wid = tid >> 5;
    const int wm = wid & 3, wn = wid >> 2;         // warp tile (32*wm, 64*wn)
    const int grp = lane >> 2, qid = lane & 3;
    const int bm = blockIdx.y * 128, bn = blockIdx.x * 128;

    // loader mapping: 1024 float4 per tile per operand; 4 per thread
    const int lr0 = tid >> 3;                      // base row (0..31)
    const int lc4 = (tid & 7) * 4;                 // k-offset within tile

    float acc[2][8][4];
    #pragma unroll
    for (int mf = 0; mf < 2; mf++)
        #pragma unroll
        for (int nf = 0; nf < 8; nf++)
            #pragma unroll
            for (int r = 0; r < 4; r++) acc[mf][nf][r] = 0.f;

    const int niter = K / TBK;

    // ---- cp.async tile issue ----
    auto issue = [&](int it, int st) {
        const int k0 = it * TBK;
        #pragma unroll
        for (int i = 0; i < 4; i++) {
            const int row = lr0 + i * 32;
            // A (guard rows >= M: clamp ptr, zero-fill via src_size=0)
            {
                int gr = bm + row;
                int ok = (gr < M);
                const float* src = A + (size_t)(ok ? gr : (M - 1)) * K + k0 + lc4;
                uint32_t dst = (uint32_t)__cvta_generic_to_shared(
                    As + st * TSTAGE + row * TSTR + lc4);
                int sz = ok ? 16 : 0;
                asm volatile("cp.async.cg.shared.global [%0], [%1], 16, %2;"
                             :: "r"(dst), "l"(src), "r"(sz));
            }
            // B (N is always a multiple of 128)
            {
                const float* src = B + (size_t)(bn + row) * K + k0 + lc4;
                uint32_t dst = (uint32_t)__cvta_generic_to_shared(
                    Bs + st * TSTAGE + row * TSTR + lc4);
                asm volatile("cp.async.cg.shared.global [%0], [%1], 16;"
                             :: "r"(dst), "l"(src));
            }
        }
        asm volatile("cp.async.commit_group;");
    };

    issue(0, 0);
    int stage = 0;

    for (int it = 0; it < niter; it++) {
        if (it + 1 < niter) {
            issue(it + 1, stage ^ 1);
            asm volatile("cp.async.wait_group 1;");
        } else {
            asm volatile("cp.async.wait_group 0;");
        }
        __syncthreads();

        const float* Ab = As + stage * TSTAGE;
        const float* Bb = Bs + stage * TSTAGE;
        const int mr = wm * 32 + grp;
        const int nr = wn * 64 + grp;

        #pragma unroll
        for (int ks = 0; ks < TBK; ks += 8) {
            uint32_t af[2][4], bf[8][2];
            #pragma unroll
            for (int mf = 0; mf < 2; mf++) {
                const float* p = Ab + (mr + mf * 16) * TSTR + ks + qid;
                af[mf][0] = f2tf32(p[0]);
                af[mf][1] = f2tf32(p[8 * TSTR]);
                af[mf][2] = f2tf32(p[4]);
                af[mf][3] = f2tf32(p[8 * TSTR + 4]);
            }
            #pragma unroll
            for (int nf = 0; nf < 8; nf++) {
                const float* p = Bb + (nr + nf * 8) * TSTR + ks + qid;
                bf[nf][0] = f2tf32(p[0]);
                bf[nf][1] = f2tf32(p[4]);
            }
            #pragma unroll
            for (int mf = 0; mf < 2; mf++)
                #pragma unroll
                for (int nf = 0; nf < 8; nf++)
                    MMA_TF32(acc[mf][nf], af[mf], bf[nf]);
        }
        __syncthreads();
        stage ^= 1;
    }

    // ---- epilogue ----
    #pragma unroll
    for (int mf = 0; mf < 2; mf++) {
        #pragma unroll
        for (int half = 0; half < 2; half++) {
            const int gm = bm + wm * 32 + mf * 16 + grp + half * 8;
            if (gm >= M) continue;
            #pragma unroll
            for (int nf = 0; nf < 8; nf++) {
                const int gn = bn + wn * 64 + nf * 8 + 2 * qid;
                float v0 = acc[mf][nf][half * 2 + 0];
                float v1 = acc[mf][nf][half * 2 + 1];
                if (bias) { v0 += bias[gn]; v1 += bias[gn + 1]; }
                if (act) {
                    v0 = v0 / (1.f + expf(-1.702f * v0));
                    v1 = v1 / (1.f + expf(-1.702f * v1));
                }
                if (resid) {
                    const float* rp = resid + (size_t)gm * N + gn;
                    v0 += rp[0]; v1 += rp[1];
                }
                float2 o; o.x = v0; o.y = v1;
                *(float2*)(C + (size_t)gm * N + gn) = o;
            }
        }
    }
}

// ======================================================================
// LayerNorm: one block (256 thr) per row of 768.
// ======================================================================
__global__ __launch_bounds__(256) void ln_kernel(
    const float* __restrict__ x, long in_stride,
    float* __restrict__ y, long out_stride,
    const float* __restrict__ g, const float* __restrict__ b, int rows)
{
    int r = blockIdx.x;
    if (r >= rows) return;
    const float* xr = x + (size_t)r * in_stride;
    float* yr = y + (size_t)r * out_stride;
    int t = threadIdx.x;

    float v0 = xr[t], v1 = xr[t + 256], v2 = xr[t + 512];

    __shared__ float red[8];
    __shared__ float bc;

    float s = v0 + v1 + v2;
    #pragma unroll
    for (int o = 16; o > 0; o >>= 1) s += __shfl_xor_sync(0xffffffffu, s, o);
    if ((t & 31) == 0) red[t >> 5] = s;
    __syncthreads();
    if (t == 0) { float tot = 0.f; for (int i = 0; i < 8; i++) tot += red[i]; bc = tot; }
    __syncthreads();
    float mu = bc * (1.f / 768.f);

    float d0 = v0 - mu, d1 = v1 - mu, d2 = v2 - mu;
    float ss = d0 * d0 + d1 * d1 + d2 * d2;
    #pragma unroll
    for (int o = 16; o > 0; o >>= 1) ss += __shfl_xor_sync(0xffffffffu, ss, o);
    __syncthreads();
    if ((t & 31) == 0) red[t >> 5] = ss;
    __syncthreads();
    if (t == 0) { float tot = 0.f; for (int i = 0; i < 8; i++) tot += red[i]; bc = tot; }
    __syncthreads();
    float rs = rsqrtf(bc * (1.f / 768.f) + 1e-5f);

    yr[t]       = d0 * rs * g[t]       + b[t];
    yr[t + 256] = d1 * rs * g[t + 256] + b[t + 256];
    yr[t + 512] = d2 * rs * g[t + 512] + b[t + 512];
}

// ======================================================================
// Fused attention: one block per (head, batch). K,V in smem.
// ======================================================================
#define KVS 68
__global__ __launch_bounds__(256) void attn_kernel(
    const float* __restrict__ qkv, const float* __restrict__ clsbias,
    float* __restrict__ out)
{
    extern __shared__ float sm[];
    float* Ks = sm;
    float* Vs = sm + S_ * KVS;
    float* Ps = Vs + S_ * KVS;

    const int h = blockIdx.x, b = blockIdx.y;
    const int tid = threadIdx.x;
    const int w = tid >> 5, lane = tid & 31;
    const size_t base = (size_t)b * S_ * QKV3;

    for (int i = tid; i < S_ * HD_; i += 256) {
        int s_ = i >> 6, hd = i & 63;
        size_t off = base + (size_t)s_ * QKV3 + h * HD_ + hd;
        Ks[s_ * KVS + hd] = qkv[off + D_];
        Vs[s_ * KVS + hd] = qkv[off + 2 * D_];
    }
    __syncthreads();

    for (int q = w; q < S_; q += 8) {
        const float4* qp = (const float4*)(qkv + base + (size_t)q * QKV3 + h * HD_);
        float4 qr[16];
        #pragma unroll
        for (int i = 0; i < 16; i++) qr[i] = qp[i];

        float sc[7];
        #pragma unroll
        for (int t = 0; t < 7; t++) {
            int k = lane + 32 * t;
            float sv = -1e30f;
            if (k < S_) {
                const float4* kp = (const float4*)(Ks + k * KVS);
                float a = 0.f;
                #pragma unroll
                for (int i = 0; i < 16; i++) {
                    float4 kk = kp[i];
                    a += qr[i].x * kk.x + qr[i].y * kk.y + qr[i].z * kk.z + qr[i].w * kk.w;
                }
                sv = a * 0.125f;
                if (clsbias && q == 0 && k >= 1) sv += clsbias[b * L_ + (k - 1)];
            }
            sc[t] = sv;
        }
        float m = sc[0];
        #pragma unroll
        for (int t = 1; t < 7; t++) m = fmaxf(m, sc[t]);
        #pragma unroll
        for (int o = 16; o > 0; o >>= 1) m = fmaxf(m, __shfl_xor_sync(0xffffffffu, m, o));
        float se = 0.f;
        #pragma unroll
        for (int t = 0; t < 7; t++) {
            float e = (sc[t] > -1e29f) ? expf(sc[t] - m) : 0.f;
            sc[t] = e; se += e;
        }
        #pragma unroll
        for (int o = 16; o > 0; o >>= 1) se += __shfl_xor_sync(0xffffffffu, se, o);
        float inv = 1.f / se;
        #pragma unroll
        for (int t = 0; t < 7; t++) {
            int k = lane + 32 * t;
            if (k < S_) Ps[w * 200 + k] = sc[t] * inv;
        }
        __syncwarp();

        float o0 = 0.f, o1 = 0.f;
        for (int k = 0; k < S_; k++) {
            float p = Ps[w * 200 + k];
            o0 += p * Vs[k * KVS + lane];
            o1 += p * Vs[k * KVS + 32 + lane];
        }
        size_t orow = ((size_t)b * S_ + q) * D_ + h * HD_;
        out[orow + lane] = o0;
        out[orow + 32 + lane] = o1;
        __syncwarp();
    }
}

// ======================================================================
// Patch embed helpers
// ======================================================================
__global__ void im2col_kernel(const float* __restrict__ masked,
                              const float* __restrict__ prompted,
                              float* __restrict__ col)
{
    int idx = blockIdx.x * 256 + threadIdx.x;
    const int total = B2 * L_ * D_;
    if (idx >= total) return;
    int k = idx % D_;
    int m = idx / D_;
    int b = m / L_, l = m % L_;
    int gy = l / GRID_, gx = l % GRID_;
    int c = k >> 8, rem = k & 255;
    int py = rem >> 4, px = rem & 15;
    const float* src = (b < NB) ? (masked + (size_t)b * 3 * IMG_ * IMG_)
                                : (prompted + (size_t)(b - NB) * 3 * IMG_ * IMG_);
    col[idx] = src[((size_t)c * IMG_ + gy * PCH_ + py) * IMG_ + gx * PCH_ + px];
}

__global__ void embed_kernel(const float* __restrict__ conv_out,
                             const float* __restrict__ cls_emb,
                             const float* __restrict__ pos,
                             float* __restrict__ x)
{
    int idx = blockIdx.x * 256 + threadIdx.x;
    const int total = B2 * S_ * D_;
    if (idx >= total) return;
    int d = idx % D_;
    int bs = idx / D_;
    int s = bs % S_, b = bs / S_;
    float v = (s == 0) ? cls_emb[d] : conv_out[((size_t)b * L_ + (s - 1)) * D_ + d];
    x[idx] = v + pos[s * D_ + d];
}

__global__ void clsbias_kernel(const float* __restrict__ pm, float* __restrict__ cb)
{
    int i = blockIdx.x * 256 + threadIdx.x;
    if (i < NB * L_) cb[i] = (pm[i] != 0.f) ? 0.f : -1e30f;
}

__global__ void mask_combine_kernel(float* __restrict__ x, const float* __restrict__ x2,
                                    const float* __restrict__ pm)
{
    int idx = blockIdx.x * 256 + threadIdx.x;
    const int total = NB * S_ * D_;
    if (idx >= total) return;
    int bs = idx / D_;
    int s = bs % D_ ? bs % S_ : bs % S_;   // (kept simple below)
    s = bs % S_;
    int b = bs / S_;
    float mf = (s == 0) ? 1.f : pm[b * L_ + (s - 1)];
    x[idx] = 2.f * x2[idx] * mf + x[idx];
}

__global__ void proj_out_kernel(const float* __restrict__ cls,
                                const float* __restrict__ proj,
                                float* __restrict__ out)
{
    int n = blockIdx.x * 256 + threadIdx.x;
    int m = blockIdx.y;
    if (n >= OUT_) return;
    float s = 0.f;
    #pragma unroll 4
    for (int k = 0; k < D_; k++) s += cls[m * D_ + k] * proj[(size_t)k * OUT_ + n];
    out[m * OUT_ + n] = s;
}

// ======================================================================
// Host orchestration
// ======================================================================
static float* symaddr(const void* s) {
    void* p = nullptr;
    cudaGetSymbolAddress(&p, s);
    return (float*)p;
}

#define GEMM_SMEM (4 * TSTAGE * (int)sizeof(float))   // 73,728 B

static void run_gemm(const float* A, const float* B, const float* bias,
                     const float* resid, float* C, int M, int N, int K, int act)
{
    dim3 grid(N / 128, (M + 127) / 128);
    gemm_tc<<<grid, 256, GEMM_SMEM>>>(A, B, bias, resid, C, M, N, K, act);
}

struct Ctx {
    float *x12, *xln, *qkv, *att, *ffh, *col, *clsb;
    const float *Wqkv, *bqkv, *Wo, *bo, *ln1g, *ln1b, *ln2g, *ln2b, *Wfc, *bfc, *Wp, *bp;
    int attn_smem;
};

static void run_block(const Ctx& c, float* x, int Bn, int layer, const float* bias)
{
    const int M = Bn * S_;
    ln_kernel<<<M, 256>>>(x, D_, c.xln, D_, c.ln1g + layer * D_, c.ln1b + layer * D_, M);
    run_gemm(c.xln, c.Wqkv + (size_t)layer * QKV3 * D_, c.bqkv + layer * QKV3,
             nullptr, c.qkv, M, QKV3, D_, 0);
    attn_kernel<<<dim3(H_, Bn), 256, c.attn_smem>>>(c.qkv, bias, c.att);
    run_gemm(c.att, c.Wo + (size_t)layer * D_ * D_, c.bo + layer * D_,
             x, x, M, D_, D_, 0);
    ln_kernel<<<M, 256>>>(x, D_, c.xln, D_, c.ln2g + layer * D_, c.ln2b + layer * D_, M);
    run_gemm(c.xln, c.Wfc + (size_t)layer * FF_ * D_, c.bfc + layer * FF_,
             nullptr, c.ffh, M, FF_, D_, 1);
    run_gemm(c.ffh, c.Wp + (size_t)layer * D_ * FF_, c.bp + layer * D_,
             x, x, M, D_, FF_, 0);
}

extern "C" void kernel_launch(void* const* d_in, const int* in_sizes, int n_in,
                              void* d_out, int out_size)
{
    const float* masked   = (const float*)d_in[0];
    const float* prompted = (const float*)d_in[1];
    const float* pred     = (const float*)d_in[2];
    const float* conv_w   = (const float*)d_in[3];
    const float* cls_emb  = (const float*)d_in[4];
    const float* pos_emb  = (const float*)d_in[5];
    const float* lnpre_g  = (const float*)d_in[6];
    const float* lnpre_b  = (const float*)d_in[7];

    Ctx c;
    c.Wqkv = (const float*)d_in[8];   c.bqkv = (const float*)d_in[9];
    c.Wo   = (const float*)d_in[10];  c.bo   = (const float*)d_in[11];
    c.ln1g = (const float*)d_in[12];  c.ln1b = (const float*)d_in[13];
    c.ln2g = (const float*)d_in[14];  c.ln2b = (const float*)d_in[15];
    c.Wfc  = (const float*)d_in[16];  c.bfc  = (const float*)d_in[17];
    c.Wp   = (const float*)d_in[18];  c.bp   = (const float*)d_in[19];
    const float* lnpost_g = (const float*)d_in[20];
    const float* lnpost_b = (const float*)d_in[21];
    const float* proj     = (const float*)d_in[22];
    float* out = (float*)d_out;

    c.x12  = symaddr(g_x12);
    c.xln  = symaddr(g_xln);
    c.qkv  = symaddr(g_qkv);
    c.att  = symaddr(g_att);
    c.ffh  = symaddr(g_ffh);
    c.col  = symaddr(g_im2col);
    c.clsb = symaddr(g_clsb);

    c.attn_smem = (2 * S_ * KVS + 8 * 200) * (int)sizeof(float);
    cudaFuncSetAttribute(attn_kernel, cudaFuncAttributeMaxDynamicSharedMemorySize,
                         c.attn_smem);
    cudaFuncSetAttribute(gemm_tc, cudaFuncAttributeMaxDynamicSharedMemorySize,
                         GEMM_SMEM);

    // ---- patch embed (im2col GEMM) ----
    {
        const int total = B2 * L_ * D_;
        im2col_kernel<<<(total + 255) / 256, 256>>>(masked, prompted, c.col);
        run_gemm(c.col, conv_w, nullptr, nullptr, c.att, B2 * L_, D_, D_, 0);
        const int tot2 = B2 * S_ * D_;
        embed_kernel<<<(tot2 + 255) / 256, 256>>>(c.att, cls_emb, pos_emb, c.x12);
        ln_kernel<<<B2 * S_, 256>>>(c.x12, D_, c.x12, D_, lnpre_g, lnpre_b, B2 * S_);
    }

    clsbias_kernel<<<(NB * L_ + 255) / 256, 256>>>(pred, c.clsb);

    for (int i = 0; i < 10; i++)
        run_block(c, c.x12, B2, i, nullptr);

    float* x  = c.x12;
    float* x2 = c.x12 + (size_t)NB * S_ * D_;
    const int layers2[2] = {10, 11};
    for (int t = 0; t < 2; t++) {
        int i = layers2[t];
        const int tot = NB * S_ * D_;
        mask_combine_kernel<<<(tot + 255) / 256, 256>>>(x, x2, pred);
        run_block(c, x, NB, i, nullptr);
        run_block(c, x2, NB, i, c.clsb);
    }

    ln_kernel<<<NB, 256>>>(x, (long)S_ * D_, c.xln, D_, lnpost_g, lnpost_b, NB);
    proj_out_kernel<<<dim3((OUT_ + 255) / 256, NB), 256>>>(c.xln, proj, out);

    (void)in_sizes; (void)n_in; (void)out_size;
}

// round 7
// speedup vs baseline: 2.3258x; 1.0119x over previous
#include <cuda_runtime.h>
#include <math.h>
#include <stdint.h>

// ---------------- Problem constants ----------------
#define D_    768
#define H_    12
#define HD_   64
#define S_    197
#define L_    196
#define NB    16          // batch per image set
#define B2    32          // both image sets
#define FF_   3072
#define OUT_  512
#define QKV3  2304
#define IMG_  224
#define GRID_ 14
#define PCH_  16
#define LAYERS_ 12

// ---------------- Scratch (device globals; no allocation allowed) ----------------
__device__ float g_x12[B2 * S_ * D_];      // residual stream (x | x2)
__device__ float g_xln[B2 * S_ * D_];      // LN output (tf32-rounded)
__device__ float g_qkv[B2 * S_ * QKV3];    // qkv (raw fp32)
__device__ float g_att[B2 * S_ * D_];      // attention out (tf32-rounded)
__device__ float g_ffh[B2 * S_ * FF_];     // MLP hidden (tf32-rounded)
__device__ float g_im2col[B2 * L_ * D_];   // patch im2col (tf32-rounded)
__device__ float g_clsb[NB * L_];          // cls-row attention bias

// tf32-rounded weight copies
__device__ float g_wqkv[LAYERS_ * QKV3 * D_];   // 21.2M
__device__ float g_wo  [LAYERS_ * D_ * D_];     // 7.1M
__device__ float g_wfc [LAYERS_ * FF_ * D_];    // 28.3M
__device__ float g_wp  [LAYERS_ * D_ * FF_];    // 28.3M
__device__ float g_wcv [D_ * D_];               // conv_w as (768,768)

__device__ __forceinline__ uint32_t f2tf32(float x) {
    uint32_t u;
    asm("cvt.rna.tf32.f32 %0, %1;" : "=r"(u) : "f"(x));
    return u;
}
__device__ __forceinline__ float rna32(float x) {
    return __uint_as_float(f2tf32(x));
}

// ---- weight pre-rounding (once per launch; ~115us total) ----
__global__ void round4_kernel(const float4* __restrict__ in,
                              float4* __restrict__ out, int n4)
{
    for (int i = blockIdx.x * 256 + threadIdx.x; i < n4; i += gridDim.x * 256) {
        float4 v = in[i];
        v.x = rna32(v.x); v.y = rna32(v.y); v.z = rna32(v.z); v.w = rna32(v.w);
        out[i] = v;
    }
}

// ======================================================================
// TF32 tensor-core GEMM (operands PRE-ROUNDED to tf32):
//   C[M,N] = act( A[M,K] @ B[N,K]^T + bias[N] ) + resid[M,N]
// 128x128x32 block tile, 256 threads (8 warps 4x2), warp tile 32x64.
// Inner loop: 6 ldmatrix.x4 + 16 mma per k8 — no CVT, no scalar LDS.
// ======================================================================
#define TBK  32
#define TSTR 36                 // smem row stride in words
#define TSTAGE (128 * TSTR)     // words per stage per operand

#define LDSM4(r0, r1, r2, r3, addr)                                    \
    asm volatile("ldmatrix.sync.aligned.m8n8.x4.shared.b16 "           \
                 "{%0,%1,%2,%3}, [%4];"                                \
                 : "=r"(r0), "=r"(r1), "=r"(r2), "=r"(r3) : "r"(addr))

#define MMA_TF32(d, a, b)                                              \
    asm volatile(                                                      \
        "mma.sync.aligned.m16n8k8.row.col.f32.tf32.tf32.f32 "          \
        "{%0,%1,%2,%3}, {%4,%5,%6,%7}, {%8,%9}, {%0,%1,%2,%3};"        \
        : "+f"(d[0]), "+f"(d[1]), "+f"(d[2]), "+f"(d[3])               \
        : "r"((a)[0]), "r"((a)[1]), "r"((a)[2]), "r"((a)[3]),          \
          "r"((b)[0]), "r"((b)[1]))

__global__ __launch_bounds__(256, 2) void gemm_tc(
    const float* __restrict__ A, const float* __restrict__ B,
    const float* __restrict__ bias, const float* __restrict__ resid,
    float* __restrict__ C, int M, int N, int K, int act)
{
    extern __shared__ float sm[];
    float* As = sm;                    // 2 stages * 128*36
    float* Bs = sm + 2 * TSTAGE;       // 2 stages * 128*36

    const int tid  = threadIdx.x;
    const int lane = tid & 31, wid = tid >> 5;
    const int wm = wid & 3, wn = wid >> 2;         // warp tile (32*wm, 64*wn)
    const int grp = lane >> 2, qid = lane & 3;
    const int bm = blockIdx.y * 128, bn = blockIdx.x * 128;

    // loader mapping: 4 float4 rows per thread per operand
    const int lr0 = tid >> 3;                      // base row (0..31)
    const int lc4 = (tid & 7) * 4;                 // k-offset within tile

    float acc[2][8][4];
    #pragma unroll
    for (int mf = 0; mf < 2; mf++)
        #pragma unroll
        for (int nf = 0; nf < 8; nf++)
            #pragma unroll
            for (int r = 0; r < 4; r++) acc[mf][nf][r] = 0.f;

    const int niter = K / TBK;

    auto issue = [&](int it, int st) {
        const int k0 = it * TBK;
        #pragma unroll
        for (int i = 0; i < 4; i++) {
            const int row = lr0 + i * 32;
            {   // A (rows >= M zero-filled via src_size 0)
                int gr = bm + row;
                int ok = (gr < M);
                const float* src = A + (size_t)(ok ? gr : (M - 1)) * K + k0 + lc4;
                uint32_t dst = (uint32_t)__cvta_generic_to_shared(
                    As + st * TSTAGE + row * TSTR + lc4);
                int sz = ok ? 16 : 0;
                asm volatile("cp.async.cg.shared.global [%0], [%1], 16, %2;"
                             :: "r"(dst), "l"(src), "r"(sz));
            }
            {   // B (N multiple of 128)
                const float* src = B + (size_t)(bn + row) * K + k0 + lc4;
                uint32_t dst = (uint32_t)__cvta_generic_to_shared(
                    Bs + st * TSTAGE + row * TSTR + lc4);
                asm volatile("cp.async.cg.shared.global [%0], [%1], 16;"
                             :: "r"(dst), "l"(src));
            }
        }
        asm volatile("cp.async.commit_group;");
    };

    // per-lane ldmatrix base byte-offsets (lane == row within the 32/64 span)
    const uint32_t smemBase = (uint32_t)__cvta_generic_to_shared(sm);
    const uint32_t aOff  = smemBase + (uint32_t)((wm * 32 + lane) * TSTR) * 4u;
    const uint32_t bOff0 = smemBase + (uint32_t)((2 * TSTAGE + (wn * 64 + lane) * TSTR)) * 4u;
    const uint32_t bOff1 = bOff0 + (uint32_t)(32 * TSTR) * 4u;

    issue(0, 0);
    int stage = 0;

    for (int it = 0; it < niter; it++) {
        if (it + 1 < niter) {
            issue(it + 1, stage ^ 1);
            asm volatile("cp.async.wait_group 1;");
        } else {
            asm volatile("cp.async.wait_group 0;");
        }
        __syncthreads();

        const uint32_t stB = (uint32_t)(stage * TSTAGE) * 4u;
        const uint32_t aB  = aOff  + stB;
        const uint32_t bB0 = bOff0 + stB;
        const uint32_t bB1 = bOff1 + stB;

        #pragma unroll
        for (int ks = 0; ks < TBK; ks += 8) {
            uint32_t a[8], b[16];
            // A: tiles (mf0:a0,a1 | mf1:a0,a1) then (+4 cols: a2,a3)
            LDSM4(a[0], a[1], a[4], a[5], aB + (ks) * 4u);
            LDSM4(a[2], a[3], a[6], a[7], aB + (ks + 4) * 4u);
            // B: b0 of nf0..3 / nf4..7, then b1 (+4 cols)
            LDSM4(b[0],  b[2],  b[4],  b[6],  bB0 + (ks) * 4u);
            LDSM4(b[8],  b[10], b[12], b[14], bB1 + (ks) * 4u);
            LDSM4(b[1],  b[3],  b[5],  b[7],  bB0 + (ks + 4) * 4u);
            LDSM4(b[9],  b[11], b[13], b[15], bB1 + (ks + 4) * 4u);
            #pragma unroll
            for (int mf = 0; mf < 2; mf++)
                #pragma unroll
                for (int nf = 0; nf < 8; nf++)
                    MMA_TF32(acc[mf][nf], &a[mf * 4], &b[nf * 2]);
        }
        __syncthreads();
        stage ^= 1;
    }

    // ---- epilogue ----
    #pragma unroll
    for (int mf = 0; mf < 2; mf++) {
        #pragma unroll
        for (int half = 0; half < 2; half++) {
            const int gm = bm + wm * 32 + mf * 16 + grp + half * 8;
            if (gm >= M) continue;
            #pragma unroll
            for (int nf = 0; nf < 8; nf++) {
                const int gn = bn + wn * 64 + nf * 8 + 2 * qid;
                float v0 = acc[mf][nf][half * 2 + 0];
                float v1 = acc[mf][nf][half * 2 + 1];
                if (bias) { v0 += bias[gn]; v1 += bias[gn + 1]; }
                if (act) {
                    v0 = v0 / (1.f + expf(-1.702f * v0));
                    v1 = v1 / (1.f + expf(-1.702f * v1));
                    v0 = rna32(v0); v1 = rna32(v1);   // ffh feeds next GEMM
                }
                if (resid) {
                    const float* rp = resid + (size_t)gm * N + gn;
                    v0 += rp[0]; v1 += rp[1];
                }
                float2 o; o.x = v0; o.y = v1;
                *(float2*)(C + (size_t)gm * N + gn) = o;
            }
        }
    }
}

// ======================================================================
// LayerNorm: one block (256 thr) per row of 768. rnd=1 → tf32-round output.
// ======================================================================
__global__ __launch_bounds__(256) void ln_kernel(
    const float* __restrict__ x, long in_stride,
    float* __restrict__ y, long out_stride,
    const float* __restrict__ g, const float* __restrict__ b, int rows, int rnd)
{
    int r = blockIdx.x;
    if (r >= rows) return;
    const float* xr = x + (size_t)r * in_stride;
    float* yr = y + (size_t)r * out_stride;
    int t = threadIdx.x;

    float v0 = xr[t], v1 = xr[t + 256], v2 = xr[t + 512];

    __shared__ float red[8];
    __shared__ float bc;

    float s = v0 + v1 + v2;
    #pragma unroll
    for (int o = 16; o > 0; o >>= 1) s += __shfl_xor_sync(0xffffffffu, s, o);
    if ((t & 31) == 0) red[t >> 5] = s;
    __syncthreads();
    if (t == 0) { float tot = 0.f; for (int i = 0; i < 8; i++) tot += red[i]; bc = tot; }
    __syncthreads();
    float mu = bc * (1.f / 768.f);

    float d0 = v0 - mu, d1 = v1 - mu, d2 = v2 - mu;
    float ss = d0 * d0 + d1 * d1 + d2 * d2;
    #pragma unroll
    for (int o = 16; o > 0; o >>= 1) ss += __shfl_xor_sync(0xffffffffu, ss, o);
    __syncthreads();
    if ((t & 31) == 0) red[t >> 5] = ss;
    __syncthreads();
    if (t == 0) { float tot = 0.f; for (int i = 0; i < 8; i++) tot += red[i]; bc = tot; }
    __syncthreads();
    float rs = rsqrtf(bc * (1.f / 768.f) + 1e-5f);

    float o0 = d0 * rs * g[t]       + b[t];
    float o1 = d1 * rs * g[t + 256] + b[t + 256];
    float o2 = d2 * rs * g[t + 512] + b[t + 512];
    if (rnd) { o0 = rna32(o0); o1 = rna32(o1); o2 = rna32(o2); }
    yr[t] = o0; yr[t + 256] = o1; yr[t + 512] = o2;
}

// ======================================================================
// Fused attention (fp32 SIMT): one block per (head, batch).
// Output tf32-rounded (feeds Wo GEMM).
// ======================================================================
#define KVS 68
__global__ __launch_bounds__(256) void attn_kernel(
    const float* __restrict__ qkv, const float* __restrict__ clsbias,
    float* __restrict__ out)
{
    extern __shared__ float sm[];
    float* Ks = sm;
    float* Vs = sm + S_ * KVS;
    float* Ps = Vs + S_ * KVS;

    const int h = blockIdx.x, b = blockIdx.y;
    const int tid = threadIdx.x;
    const int w = tid >> 5, lane = tid & 31;
    const size_t base = (size_t)b * S_ * QKV3;

    for (int i = tid; i < S_ * HD_; i += 256) {
        int s_ = i >> 6, hd = i & 63;
        size_t off = base + (size_t)s_ * QKV3 + h * HD_ + hd;
        Ks[s_ * KVS + hd] = qkv[off + D_];
        Vs[s_ * KVS + hd] = qkv[off + 2 * D_];
    }
    __syncthreads();

    for (int q = w; q < S_; q += 8) {
        const float4* qp = (const float4*)(qkv + base + (size_t)q * QKV3 + h * HD_);
        float4 qr[16];
        #pragma unroll
        for (int i = 0; i < 16; i++) qr[i] = qp[i];

        float sc[7];
        #pragma unroll
        for (int t = 0; t < 7; t++) {
            int k = lane + 32 * t;
            float sv = -1e30f;
            if (k < S_) {
                const float4* kp = (const float4*)(Ks + k * KVS);
                float a = 0.f;
                #pragma unroll
                for (int i = 0; i < 16; i++) {
                    float4 kk = kp[i];
                    a += qr[i].x * kk.x + qr[i].y * kk.y + qr[i].z * kk.z + qr[i].w * kk.w;
                }
                sv = a * 0.125f;
                if (clsbias && q == 0 && k >= 1) sv += clsbias[b * L_ + (k - 1)];
            }
            sc[t] = sv;
        }
        float m = sc[0];
        #pragma unroll
        for (int t = 1; t < 7; t++) m = fmaxf(m, sc[t]);
        #pragma unroll
        for (int o = 16; o > 0; o >>= 1) m = fmaxf(m, __shfl_xor_sync(0xffffffffu, m, o));
        float se = 0.f;
        #pragma unroll
        for (int t = 0; t < 7; t++) {
            float e = (sc[t] > -1e29f) ? expf(sc[t] - m) : 0.f;
            sc[t] = e; se += e;
        }
        #pragma unroll
        for (int o = 16; o > 0; o >>= 1) se += __shfl_xor_sync(0xffffffffu, se, o);
        float inv = 1.f / se;
        #pragma unroll
        for (int t = 0; t < 7; t++) {
            int k = lane + 32 * t;
            if (k < S_) Ps[w * 200 + k] = sc[t] * inv;
        }
        __syncwarp();

        float o0 = 0.f, o1 = 0.f;
        for (int k = 0; k < S_; k++) {
            float p = Ps[w * 200 + k];
            o0 += p * Vs[k * KVS + lane];
            o1 += p * Vs[k * KVS + 32 + lane];
        }
        size_t orow = ((size_t)b * S_ + q) * D_ + h * HD_;
        out[orow + lane]      = rna32(o0);
        out[orow + 32 + lane] = rna32(o1);
        __syncwarp();
    }
}

// ======================================================================
// Patch embed helpers
// ======================================================================
__global__ void im2col_kernel(const float* __restrict__ masked,
                              const float* __restrict__ prompted,
                              float* __restrict__ col)
{
    int idx = blockIdx.x * 256 + threadIdx.x;
    const int total = B2 * L_ * D_;
    if (idx >= total) return;
    int k = idx % D_;
    int m = idx / D_;
    int b = m / L_, l = m % L_;
    int gy = l / GRID_, gx = l % GRID_;
    int c = k >> 8, rem = k & 255;
    int py = rem >> 4, px = rem & 15;
    const float* src = (b < NB) ? (masked + (size_t)b * 3 * IMG_ * IMG_)
                                : (prompted + (size_t)(b - NB) * 3 * IMG_ * IMG_);
    col[idx] = rna32(src[((size_t)c * IMG_ + gy * PCH_ + py) * IMG_ + gx * PCH_ + px]);
}

__global__ void embed_kernel(const float* __restrict__ conv_out,
                             const float* __restrict__ cls_emb,
                             const float* __restrict__ pos,
                             float* __restrict__ x)
{
    int idx = blockIdx.x * 256 + threadIdx.x;
    const int total = B2 * S_ * D_;
    if (idx >= total) return;
    int d = idx % D_;
    int bs = idx / D_;
    int s = bs % S_, b = bs / S_;
    float v = (s == 0) ? cls_emb[d] : conv_out[((size_t)b * L_ + (s - 1)) * D_ + d];
    x[idx] = v + pos[s * D_ + d];
}

__global__ void clsbias_kernel(const float* __restrict__ pm, float* __restrict__ cb)
{
    int i = blockIdx.x * 256 + threadIdx.x;
    if (i < NB * L_) cb[i] = (pm[i] != 0.f) ? 0.f : -1e30f;
}

__global__ void mask_combine_kernel(float* __restrict__ x, const float* __restrict__ x2,
                                    const float* __restrict__ pm)
{
    int idx = blockIdx.x * 256 + threadIdx.x;
    const int total = NB * S_ * D_;
    if (idx >= total) return;
    int bs = idx / D_;
    int s = bs % S_;
    int b = bs / S_;
    float mf = (s == 0) ? 1.f : pm[b * L_ + (s - 1)];
    x[idx] = 2.f * x2[idx] * mf + x[idx];
}

__global__ void proj_out_kernel(const float* __restrict__ cls,
                                const float* __restrict__ proj,
                                float* __restrict__ out)
{
    int n = blockIdx.x * 256 + threadIdx.x;
    int m = blockIdx.y;
    if (n >= OUT_) return;
    float s = 0.f;
    #pragma unroll 4
    for (int k = 0; k < D_; k++) s += cls[m * D_ + k] * proj[(size_t)k * OUT_ + n];
    out[m * OUT_ + n] = s;
}

// ======================================================================
// Host orchestration
// ======================================================================
static float* symaddr(const void* s) {
    void* p = nullptr;
    cudaGetSymbolAddress(&p, s);
    return (float*)p;
}

#define GEMM_SMEM (4 * TSTAGE * (int)sizeof(float))   // 73,728 B

static void run_gemm(const float* A, const float* B, const float* bias,
                     const float* resid, float* C, int M, int N, int K, int act)
{
    dim3 grid(N / 128, (M + 127) / 128);
    gemm_tc<<<grid, 256, GEMM_SMEM>>>(A, B, bias, resid, C, M, N, K, act);
}

static void run_round(const float* in, float* out, long n)
{
    int n4 = (int)(n / 4);
    int blocks = (n4 + 255) / 256;
    if (blocks > 16384) blocks = 16384;
    round4_kernel<<<blocks, 256>>>((const float4*)in, (float4*)out, n4);
}

struct Ctx {
    float *x12, *xln, *qkv, *att, *ffh, *col, *clsb;
    const float *Wqkv, *bqkv, *Wo, *bo, *ln1g, *ln1b, *ln2g, *ln2b, *Wfc, *bfc, *Wp, *bp;
    int attn_smem;
};

static void run_block(const Ctx& c, float* x, int Bn, int layer, const float* bias)
{
    const int M = Bn * S_;
    ln_kernel<<<M, 256>>>(x, D_, c.xln, D_, c.ln1g + layer * D_, c.ln1b + layer * D_, M, 1);
    run_gemm(c.xln, c.Wqkv + (size_t)layer * QKV3 * D_, c.bqkv + layer * QKV3,
             nullptr, c.qkv, M, QKV3, D_, 0);
    attn_kernel<<<dim3(H_, Bn), 256, c.attn_smem>>>(c.qkv, bias, c.att);
    run_gemm(c.att, c.Wo + (size_t)layer * D_ * D_, c.bo + layer * D_,
             x, x, M, D_, D_, 0);
    ln_kernel<<<M, 256>>>(x, D_, c.xln, D_, c.ln2g + layer * D_, c.ln2b + layer * D_, M, 1);
    run_gemm(c.xln, c.Wfc + (size_t)layer * FF_ * D_, c.bfc + layer * FF_,
             nullptr, c.ffh, M, FF_, D_, 1);
    run_gemm(c.ffh, c.Wp + (size_t)layer * D_ * FF_, c.bp + layer * D_,
             x, x, M, D_, FF_, 0);
}

extern "C" void kernel_launch(void* const* d_in, const int* in_sizes, int n_in,
                              void* d_out, int out_size)
{
    const float* masked   = (const float*)d_in[0];
    const float* prompted = (const float*)d_in[1];
    const float* pred     = (const float*)d_in[2];
    const float* conv_w   = (const float*)d_in[3];
    const float* cls_emb  = (const float*)d_in[4];
    const float* pos_emb  = (const float*)d_in[5];
    const float* lnpre_g  = (const float*)d_in[6];
    const float* lnpre_b  = (const float*)d_in[7];

    const float* Wqkv_raw = (const float*)d_in[8];
    const float* bqkv     = (const float*)d_in[9];
    const float* Wo_raw   = (const float*)d_in[10];
    const float* bo       = (const float*)d_in[11];
    const float* ln1g     = (const float*)d_in[12];
    const float* ln1b     = (const float*)d_in[13];
    const float* ln2g     = (const float*)d_in[14];
    const float* ln2b     = (const float*)d_in[15];
    const float* Wfc_raw  = (const float*)d_in[16];
    const float* bfc      = (const float*)d_in[17];
    const float* Wp_raw   = (const float*)d_in[18];
    const float* bp       = (const float*)d_in[19];
    const float* lnpost_g = (const float*)d_in[20];
    const float* lnpost_b = (const float*)d_in[21];
    const float* proj     = (const float*)d_in[22];
    float* out = (float*)d_out;

    Ctx c;
    c.x12  = symaddr(g_x12);
    c.xln  = symaddr(g_xln);
    c.qkv  = symaddr(g_qkv);
    c.att  = symaddr(g_att);
    c.ffh  = symaddr(g_ffh);
    c.col  = symaddr(g_im2col);
    c.clsb = symaddr(g_clsb);

    float* wqkv = symaddr(g_wqkv);
    float* wo   = symaddr(g_wo);
    float* wfc  = symaddr(g_wfc);
    float* wp   = symaddr(g_wp);
    float* wcv  = symaddr(g_wcv);

    // pre-round all GEMM B-operands to tf32 (RNA)
    run_round(Wqkv_raw, wqkv, (long)LAYERS_ * QKV3 * D_);
    run_round(Wo_raw,   wo,   (long)LAYERS_ * D_ * D_);
    run_round(Wfc_raw,  wfc,  (long)LAYERS_ * FF_ * D_);
    run_round(Wp_raw,   wp,   (long)LAYERS_ * D_ * FF_);
    run_round(conv_w,   wcv,  (long)D_ * D_);

    c.Wqkv = wqkv; c.bqkv = bqkv;
    c.Wo   = wo;   c.bo   = bo;
    c.ln1g = ln1g; c.ln1b = ln1b;
    c.ln2g = ln2g; c.ln2b = ln2b;
    c.Wfc  = wfc;  c.bfc  = bfc;
    c.Wp   = wp;   c.bp   = bp;

    c.attn_smem = (2 * S_ * KVS + 8 * 200) * (int)sizeof(float);
    cudaFuncSetAttribute(attn_kernel, cudaFuncAttributeMaxDynamicSharedMemorySize,
                         c.attn_smem);
    cudaFuncSetAttribute(gemm_tc, cudaFuncAttributeMaxDynamicSharedMemorySize,
                         GEMM_SMEM);

    // ---- patch embed (im2col GEMM) ----
    {
        const int total = B2 * L_ * D_;
        im2col_kernel<<<(total + 255) / 256, 256>>>(masked, prompted, c.col);
        run_gemm(c.col, wcv, nullptr, nullptr, c.att, B2 * L_, D_, D_, 0);
        const int tot2 = B2 * S_ * D_;
        embed_kernel<<<(tot2 + 255) / 256, 256>>>(c.att, cls_emb, pos_emb, c.x12);
        // ln_pre writes the residual stream: keep UNROUNDED (rnd=0)
        ln_kernel<<<B2 * S_, 256>>>(c.x12, D_, c.x12, D_, lnpre_g, lnpre_b, B2 * S_, 0);
    }

    clsbias_kernel<<<(NB * L_ + 255) / 256, 256>>>(pred, c.clsb);

    for (int i = 0; i < 10; i++)
        run_block(c, c.x12, B2, i, nullptr);

    float* x  = c.x12;
    float* x2 = c.x12 + (size_t)NB * S_ * D_;
    const int layers2[2] = {10, 11};
    for (int t = 0; t < 2; t++) {
        int i = layers2[t];
        const int tot = NB * S_ * D_;
        mask_combine_kernel<<<(tot + 255) / 256, 256>>>(x, x2, pred);
        run_block(c, x, NB, i, nullptr);
        run_block(c, x2, NB, i, c.clsb);
    }

    ln_kernel<<<NB, 256>>>(x, (long)S_ * D_, c.xln, D_, lnpost_g, lnpost_b, NB, 0);
    proj_out_kernel<<<dim3((OUT_ + 255) / 256, NB), 256>>>(c.xln, proj, out);

    (void)in_sizes; (void)n_in; (void)out_size;
}

// round 8
// speedup vs baseline: 3.5747x; 1.5370x over previous
#include <cuda_runtime.h>
#include <cuda_fp16.h>
#include <math.h>
#include <stdint.h>

// ---------------- Problem constants ----------------
#define D_    768
#define H_    12
#define HD_   64
#define S_    197
#define L_    196
#define NB    16          // batch per image set
#define B2    32          // both image sets
#define FF_   3072
#define OUT_  512
#define QKV3  2304
#define IMG_  224
#define GRID_ 14
#define PCH_  16
#define LAYERS_ 12

// ---------------- Scratch (device globals; no allocation allowed) ----------------
__device__ float  g_x12[B2 * S_ * D_];      // residual stream (fp32)
__device__ __half g_xln[B2 * S_ * D_];      // LN output (fp16)
__device__ float  g_qkv[B2 * S_ * QKV3];    // qkv (fp32, feeds attention)
__device__ __half g_att[B2 * S_ * D_];      // attention out / conv_out temp (fp16)
__device__ __half g_ffh[B2 * S_ * FF_];     // MLP hidden (fp16)
__device__ __half g_im2col[B2 * L_ * D_];   // patch im2col (fp16)
__device__ float  g_clsb[NB * L_];          // cls-row attention bias
__device__ float  g_cls[NB * D_];           // ln_post output (fp32)

// fp16 weight copies (B operands, [N,K] row-major)
__device__ __half g_wqkv[LAYERS_ * QKV3 * D_];
__device__ __half g_wo  [LAYERS_ * D_ * D_];
__device__ __half g_wfc [LAYERS_ * FF_ * D_];
__device__ __half g_wp  [LAYERS_ * D_ * FF_];
__device__ __half g_wcv [D_ * D_];

// ---- weight fp32 -> fp16 conversion (once per launch) ----
__global__ void cvt_half_kernel(const float4* __restrict__ in,
                                uint2* __restrict__ out, int n4)
{
    for (int i = blockIdx.x * 256 + threadIdx.x; i < n4; i += gridDim.x * 256) {
        float4 v = in[i];
        __half2 h0 = __floats2half2_rn(v.x, v.y);
        __half2 h1 = __floats2half2_rn(v.z, v.w);
        uint2 o;
        o.x = *(uint32_t*)&h0;
        o.y = *(uint32_t*)&h1;
        out[i] = o;
    }
}

// ======================================================================
// FP16 tensor-core GEMM:
//   C[M,N] = act( A[M,K]h @ B[N,K]h^T + bias[N] ) (+ resid[M,N])
// 128x128x64 block tile, 256 threads (8 warps 4x2), warp tile 32x64.
// smem: 128B rows (64 halfs), SW128 xor swizzle -> conflict-free
// cp.async stores and ldmatrix.x4 loads. mma.sync m16n8k16 f16->f32.
// flags: bit0 = half output, bit1 = GELU.
// ======================================================================
#define HBK   64                 // K per tile (halfs)
#define HST   16384              // bytes per stage per operand (128*128)

#define LDSM4(r0, r1, r2, r3, addr)                                    \
    asm volatile("ldmatrix.sync.aligned.m8n8.x4.shared.b16 "           \
                 "{%0,%1,%2,%3}, [%4];"                                \
                 : "=r"(r0), "=r"(r1), "=r"(r2), "=r"(r3) : "r"(addr))

#define MMA_F16(d, a, b)                                               \
    asm volatile(                                                      \
        "mma.sync.aligned.m16n8k16.row.col.f32.f16.f16.f32 "           \
        "{%0,%1,%2,%3}, {%4,%5,%6,%7}, {%8,%9}, {%0,%1,%2,%3};"        \
        : "+f"((d)[0]), "+f"((d)[1]), "+f"((d)[2]), "+f"((d)[3])       \
        : "r"((a)[0]), "r"((a)[1]), "r"((a)[2]), "r"((a)[3]),          \
          "r"((b)[0]), "r"((b)[1]))

__global__ __launch_bounds__(256, 2) void gemm_h(
    const __half* __restrict__ A, const __half* __restrict__ B,
    const float* __restrict__ bias, const float* __restrict__ resid,
    void* __restrict__ Cv, int M, int N, int K, int flags)
{
    extern __shared__ char smb[];
    // layout: A stage0 | A stage1 | B stage0 | B stage1  (16KB each)

    const int tid  = threadIdx.x;
    const int lane = tid & 31, wid = tid >> 5;
    const int wm = wid & 3, wn = wid >> 2;         // warp tile (32*wm, 64*wn)
    const int grp = lane >> 2, qid = lane & 3;
    const int bm = blockIdx.y * 128, bn = blockIdx.x * 128;

    const uint32_t smemBase = (uint32_t)__cvta_generic_to_shared(smb);

    // loader mapping: thread -> (row = tid>>3, chunk c = tid&7), 4 row-blocks
    const int lr0 = tid >> 3;
    const int lc  = tid & 7;

    float acc[2][8][4];
    #pragma unroll
    for (int mf = 0; mf < 2; mf++)
        #pragma unroll
        for (int nf = 0; nf < 8; nf++)
            #pragma unroll
            for (int r = 0; r < 4; r++) acc[mf][nf][r] = 0.f;

    const int niter = K / HBK;

    auto issue = [&](int it, int st) {
        const int k0 = it * HBK;
        #pragma unroll
        for (int i = 0; i < 4; i++) {
            const int row = lr0 + i * 32;
            const uint32_t xoff = (uint32_t)(row * 128 + ((lc ^ (row & 7)) * 16));
            {   // A (rows >= M zero-filled via src-size 0)
                int gr = bm + row;
                int ok = (gr < M);
                const __half* src = A + (size_t)(ok ? gr : (M - 1)) * K + k0 + lc * 8;
                uint32_t dst = smemBase + st * HST + xoff;
                int sz = ok ? 16 : 0;
                asm volatile("cp.async.cg.shared.global [%0], [%1], 16, %2;"
                             :: "r"(dst), "l"(src), "r"(sz));
            }
            {   // B (N multiple of 128)
                const __half* src = B + (size_t)(bn + row) * K + k0 + lc * 8;
                uint32_t dst = smemBase + 2 * HST + st * HST + xoff;
                asm volatile("cp.async.cg.shared.global [%0], [%1], 16;"
                             :: "r"(dst), "l"(src));
            }
        }
        asm volatile("cp.async.commit_group;");
    };

    issue(0, 0);
    int stage = 0;

    // precompute per-lane ldmatrix row/xor pieces
    const int aRowIn = lane & 15;            // row within 16
    const int aKHalf = lane >> 4;            // 0/1 -> +8 halfs
    const int bMat   = lane >> 3;            // 0..3
    const int bRowIn = (lane & 7) + ((bMat >> 1) << 3);   // row within 16
    const int bKHalf = bMat & 1;

    for (int it = 0; it < niter; it++) {
        if (it + 1 < niter) {
            issue(it + 1, stage ^ 1);
            asm volatile("cp.async.wait_group 1;");
        } else {
            asm volatile("cp.async.wait_group 0;");
        }
        __syncthreads();

        const uint32_t aStage = smemBase + stage * HST;
        const uint32_t bStage = smemBase + 2 * HST + stage * HST;

        #pragma unroll
        for (int ks = 0; ks < HBK; ks += 16) {
            const int kc = ks >> 3;                    // chunk base (0,2,4,6)
            uint32_t a[2][4], b[16];
            #pragma unroll
            for (int mf = 0; mf < 2; mf++) {
                const int row = wm * 32 + mf * 16 + aRowIn;
                const int ch  = (kc + aKHalf) ^ (row & 7);
                LDSM4(a[mf][0], a[mf][1], a[mf][2], a[mf][3],
                      aStage + (uint32_t)(row * 128 + ch * 16));
            }
            #pragma unroll
            for (int np = 0; np < 4; np++) {
                const int row = wn * 64 + np * 16 + bRowIn;
                const int ch  = (kc + bKHalf) ^ (row & 7);
                LDSM4(b[np * 4 + 0], b[np * 4 + 1], b[np * 4 + 2], b[np * 4 + 3],
                      bStage + (uint32_t)(row * 128 + ch * 16));
            }
            #pragma unroll
            for (int mf = 0; mf < 2; mf++)
                #pragma unroll
                for (int np = 0; np < 4; np++) {
                    MMA_F16(acc[mf][np * 2 + 0], a[mf], &b[np * 4 + 0]);
                    MMA_F16(acc[mf][np * 2 + 1], a[mf], &b[np * 4 + 2]);
                }
        }
        __syncthreads();
        stage ^= 1;
    }

    // ---- epilogue ----
    const int halfOut = flags & 1;
    const int act     = flags & 2;
    float* Cf = (float*)Cv;
    __half* Ch = (__half*)Cv;

    #pragma unroll
    for (int mf = 0; mf < 2; mf++) {
        #pragma unroll
        for (int hh = 0; hh < 2; hh++) {
            const int gm = bm + wm * 32 + mf * 16 + grp + hh * 8;
            if (gm >= M) continue;
            #pragma unroll
            for (int nf = 0; nf < 8; nf++) {
                const int gn = bn + wn * 64 + nf * 8 + 2 * qid;
                float v0 = acc[mf][nf][hh * 2 + 0];
                float v1 = acc[mf][nf][hh * 2 + 1];
                if (bias) { v0 += bias[gn]; v1 += bias[gn + 1]; }
                if (act) {
                    v0 = v0 / (1.f + expf(-1.702f * v0));
                    v1 = v1 / (1.f + expf(-1.702f * v1));
                }
                if (resid) {
                    const float* rp = resid + (size_t)gm * N + gn;
                    v0 += rp[0]; v1 += rp[1];
                }
                if (halfOut) {
                    __half2 h = __floats2half2_rn(v0, v1);
                    *(__half2*)(Ch + (size_t)gm * N + gn) = h;
                } else {
                    float2 o; o.x = v0; o.y = v1;
                    *(float2*)(Cf + (size_t)gm * N + gn) = o;
                }
            }
        }
    }
}

// ======================================================================
// LayerNorm: one block (256 thr) per row of 768. Output type templated.
// ======================================================================
template <typename TO>
__global__ __launch_bounds__(256) void ln_kernel(
    const float* __restrict__ x, long in_stride,
    TO* __restrict__ y, long out_stride,
    const float* __restrict__ g, const float* __restrict__ b, int rows)
{
    int r = blockIdx.x;
    if (r >= rows) return;
    const float* xr = x + (size_t)r * in_stride;
    TO* yr = y + (size_t)r * out_stride;
    int t = threadIdx.x;

    float v0 = xr[t], v1 = xr[t + 256], v2 = xr[t + 512];

    __shared__ float red[8];
    __shared__ float bc;

    float s = v0 + v1 + v2;
    #pragma unroll
    for (int o = 16; o > 0; o >>= 1) s += __shfl_xor_sync(0xffffffffu, s, o);
    if ((t & 31) == 0) red[t >> 5] = s;
    __syncthreads();
    if (t == 0) { float tot = 0.f; for (int i = 0; i < 8; i++) tot += red[i]; bc = tot; }
    __syncthreads();
    float mu = bc * (1.f / 768.f);

    float d0 = v0 - mu, d1 = v1 - mu, d2 = v2 - mu;
    float ss = d0 * d0 + d1 * d1 + d2 * d2;
    #pragma unroll
    for (int o = 16; o > 0; o >>= 1) ss += __shfl_xor_sync(0xffffffffu, ss, o);
    __syncthreads();
    if ((t & 31) == 0) red[t >> 5] = ss;
    __syncthreads();
    if (t == 0) { float tot = 0.f; for (int i = 0; i < 8; i++) tot += red[i]; bc = tot; }
    __syncthreads();
    float rs = rsqrtf(bc * (1.f / 768.f) + 1e-5f);

    yr[t]       = (TO)(d0 * rs * g[t]       + b[t]);
    yr[t + 256] = (TO)(d1 * rs * g[t + 256] + b[t + 256]);
    yr[t + 512] = (TO)(d2 * rs * g[t + 512] + b[t + 512]);
}

// ======================================================================
// Fused attention (fp32 SIMT): one block per (head, batch). fp16 output.
// ======================================================================
#define KVS 68
__global__ __launch_bounds__(256) void attn_kernel(
    const float* __restrict__ qkv, const float* __restrict__ clsbias,
    __half* __restrict__ out)
{
    extern __shared__ float sm[];
    float* Ks = sm;
    float* Vs = sm + S_ * KVS;
    float* Ps = Vs + S_ * KVS;

    const int h = blockIdx.x, b = blockIdx.y;
    const int tid = threadIdx.x;
    const int w = tid >> 5, lane = tid & 31;
    const size_t base = (size_t)b * S_ * QKV3;

    for (int i = tid; i < S_ * HD_; i += 256) {
        int s_ = i >> 6, hd = i & 63;
        size_t off = base + (size_t)s_ * QKV3 + h * HD_ + hd;
        Ks[s_ * KVS + hd] = qkv[off + D_];
        Vs[s_ * KVS + hd] = qkv[off + 2 * D_];
    }
    __syncthreads();

    for (int q = w; q < S_; q += 8) {
        const float4* qp = (const float4*)(qkv + base + (size_t)q * QKV3 + h * HD_);
        float4 qr[16];
        #pragma unroll
        for (int i = 0; i < 16; i++) qr[i] = qp[i];

        float sc[7];
        #pragma unroll
        for (int t = 0; t < 7; t++) {
            int k = lane + 32 * t;
            float sv = -1e30f;
            if (k < S_) {
                const float4* kp = (const float4*)(Ks + k * KVS);
                float a = 0.f;
                #pragma unroll
                for (int i = 0; i < 16; i++) {
                    float4 kk = kp[i];
                    a += qr[i].x * kk.x + qr[i].y * kk.y + qr[i].z * kk.z + qr[i].w * kk.w;
                }
                sv = a * 0.125f;
                if (clsbias && q == 0 && k >= 1) sv += clsbias[b * L_ + (k - 1)];
            }
            sc[t] = sv;
        }
        float m = sc[0];
        #pragma unroll
        for (int t = 1; t < 7; t++) m = fmaxf(m, sc[t]);
        #pragma unroll
        for (int o = 16; o > 0; o >>= 1) m = fmaxf(m, __shfl_xor_sync(0xffffffffu, m, o));
        float se = 0.f;
        #pragma unroll
        for (int t = 0; t < 7; t++) {
            float e = (sc[t] > -1e29f) ? expf(sc[t] - m) : 0.f;
            sc[t] = e; se += e;
        }
        #pragma unroll
        for (int o = 16; o > 0; o >>= 1) se += __shfl_xor_sync(0xffffffffu, se, o);
        float inv = 1.f / se;
        #pragma unroll
        for (int t = 0; t < 7; t++) {
            int k = lane + 32 * t;
            if (k < S_) Ps[w * 200 + k] = sc[t] * inv;
        }
        __syncwarp();

        float o0 = 0.f, o1 = 0.f;
        for (int k = 0; k < S_; k++) {
            float p = Ps[w * 200 + k];
            o0 += p * Vs[k * KVS + lane];
            o1 += p * Vs[k * KVS + 32 + lane];
        }
        size_t orow = ((size_t)b * S_ + q) * D_ + h * HD_;
        out[orow + lane]      = __float2half_rn(o0);
        out[orow + 32 + lane] = __float2half_rn(o1);
        __syncwarp();
    }
}

// ======================================================================
// Patch embed helpers
// ======================================================================
__global__ void im2col_kernel(const float* __restrict__ masked,
                              const float* __restrict__ prompted,
                              __half* __restrict__ col)
{
    int idx = blockIdx.x * 256 + threadIdx.x;
    const int total = B2 * L_ * D_;
    if (idx >= total) return;
    int k = idx % D_;
    int m = idx / D_;
    int b = m / L_, l = m % L_;
    int gy = l / GRID_, gx = l % GRID_;
    int c = k >> 8, rem = k & 255;
    int py = rem >> 4, px = rem & 15;
    const float* src = (b < NB) ? (masked + (size_t)b * 3 * IMG_ * IMG_)
                                : (prompted + (size_t)(b - NB) * 3 * IMG_ * IMG_);
    col[idx] = __float2half_rn(
        src[((size_t)c * IMG_ + gy * PCH_ + py) * IMG_ + gx * PCH_ + px]);
}

__global__ void embed_kernel(const __half* __restrict__ conv_out,
                             const float* __restrict__ cls_emb,
                             const float* __restrict__ pos,
                             float* __restrict__ x)
{
    int idx = blockIdx.x * 256 + threadIdx.x;
    const int total = B2 * S_ * D_;
    if (idx >= total) return;
    int d = idx % D_;
    int bs = idx / D_;
    int s = bs % S_, b = bs / S_;
    float v = (s == 0) ? cls_emb[d]
                       : __half2float(conv_out[((size_t)b * L_ + (s - 1)) * D_ + d]);
    x[idx] = v + pos[s * D_ + d];
}

__global__ void clsbias_kernel(const float* __restrict__ pm, float* __restrict__ cb)
{
    int i = blockIdx.x * 256 + threadIdx.x;
    if (i < NB * L_) cb[i] = (pm[i] != 0.f) ? 0.f : -1e30f;
}

__global__ void mask_combine_kernel(float* __restrict__ x, const float* __restrict__ x2,
                                    const float* __restrict__ pm)
{
    int idx = blockIdx.x * 256 + threadIdx.x;
    const int total = NB * S_ * D_;
    if (idx >= total) return;
    int bs = idx / D_;
    int s = bs % S_;
    int b = bs / S_;
    float mf = (s == 0) ? 1.f : pm[b * L_ + (s - 1)];
    x[idx] = 2.f * x2[idx] * mf + x[idx];
}

__global__ void proj_out_kernel(const float* __restrict__ cls,
                                const float* __restrict__ proj,
                                float* __restrict__ out)
{
    int n = blockIdx.x * 256 + threadIdx.x;
    int m = blockIdx.y;
    if (n >= OUT_) return;
    float s = 0.f;
    #pragma unroll 4
    for (int k = 0; k < D_; k++) s += cls[m * D_ + k] * proj[(size_t)k * OUT_ + n];
    out[m * OUT_ + n] = s;
}

// ======================================================================
// Host orchestration
// ======================================================================
template <typename T>
static T* symaddr_t(const void* s) {
    void* p = nullptr;
    cudaGetSymbolAddress(&p, s);
    return (T*)p;
}

#define GEMM_SMEM (4 * HST)   // 65,536 B

static void run_gemm(const __half* A, const __half* B, const float* bias,
                     const float* resid, void* C, int M, int N, int K, int flags)
{
    dim3 grid(N / 128, (M + 127) / 128);
    gemm_h<<<grid, 256, GEMM_SMEM>>>(A, B, bias, resid, C, M, N, K, flags);
}

static void run_cvt(const float* in, __half* out, long n)
{
    int n4 = (int)(n / 4);
    int blocks = (n4 + 255) / 256;
    if (blocks > 16384) blocks = 16384;
    cvt_half_kernel<<<blocks, 256>>>((const float4*)in, (uint2*)out, n4);
}

struct Ctx {
    float *x12, *qkv, *clsb, *cls;
    __half *xln, *att, *ffh, *col;
    const __half *Wqkv, *Wo, *Wfc, *Wp;
    const float *bqkv, *bo, *ln1g, *ln1b, *ln2g, *ln2b, *bfc, *bp;
    int attn_smem;
};

static void run_block(const Ctx& c, float* x, int Bn, int layer, const float* bias)
{
    const int M = Bn * S_;
    ln_kernel<__half><<<M, 256>>>(x, D_, c.xln, D_,
                                  c.ln1g + layer * D_, c.ln1b + layer * D_, M);
    run_gemm(c.xln, c.Wqkv + (size_t)layer * QKV3 * D_, c.bqkv + layer * QKV3,
             nullptr, c.qkv, M, QKV3, D_, 0);
    attn_kernel<<<dim3(H_, Bn), 256, c.attn_smem>>>(c.qkv, bias, c.att);
    run_gemm(c.att, c.Wo + (size_t)layer * D_ * D_, c.bo + layer * D_,
             x, x, M, D_, D_, 0);
    ln_kernel<__half><<<M, 256>>>(x, D_, c.xln, D_,
                                  c.ln2g + layer * D_, c.ln2b + layer * D_, M);
    run_gemm(c.xln, c.Wfc + (size_t)layer * FF_ * D_, c.bfc + layer * FF_,
             nullptr, c.ffh, M, FF_, D_, 1 | 2);
    run_gemm(c.ffh, c.Wp + (size_t)layer * D_ * FF_, c.bp + layer * D_,
             x, x, M, D_, FF_, 0);
}

extern "C" void kernel_launch(void* const* d_in, const int* in_sizes, int n_in,
                              void* d_out, int out_size)
{
    const float* masked   = (const float*)d_in[0];
    const float* prompted = (const float*)d_in[1];
    const float* pred     = (const float*)d_in[2];
    const float* conv_w   = (const float*)d_in[3];
    const float* cls_emb  = (const float*)d_in[4];
    const float* pos_emb  = (const float*)d_in[5];
    const float* lnpre_g  = (const float*)d_in[6];
    const float* lnpre_b  = (const float*)d_in[7];

    const float* Wqkv_raw = (const float*)d_in[8];
    const float* bqkv     = (const float*)d_in[9];
    const float* Wo_raw   = (const float*)d_in[10];
    const float* bo       = (const float*)d_in[11];
    const float* ln1g     = (const float*)d_in[12];
    const float* ln1b     = (const float*)d_in[13];
    const float* ln2g     = (const float*)d_in[14];
    const float* ln2b     = (const float*)d_in[15];
    const float* Wfc_raw  = (const float*)d_in[16];
    const float* bfc      = (const float*)d_in[17];
    const float* Wp_raw   = (const float*)d_in[18];
    const float* bp       = (const float*)d_in[19];
    const float* lnpost_g = (const float*)d_in[20];
    const float* lnpost_b = (const float*)d_in[21];
    const float* proj     = (const float*)d_in[22];
    float* out = (float*)d_out;

    Ctx c;
    c.x12  = symaddr_t<float>(g_x12);
    c.xln  = symaddr_t<__half>(g_xln);
    c.qkv  = symaddr_t<float>(g_qkv);
    c.att  = symaddr_t<__half>(g_att);
    c.ffh  = symaddr_t<__half>(g_ffh);
    c.col  = symaddr_t<__half>(g_im2col);
    c.clsb = symaddr_t<float>(g_clsb);
    c.cls  = symaddr_t<float>(g_cls);

    __half* wqkv = symaddr_t<__half>(g_wqkv);
    __half* wo   = symaddr_t<__half>(g_wo);
    __half* wfc  = symaddr_t<__half>(g_wfc);
    __half* wp   = symaddr_t<__half>(g_wp);
    __half* wcv  = symaddr_t<__half>(g_wcv);

    // convert all GEMM B-operands to fp16
    run_cvt(Wqkv_raw, wqkv, (long)LAYERS_ * QKV3 * D_);
    run_cvt(Wo_raw,   wo,   (long)LAYERS_ * D_ * D_);
    run_cvt(Wfc_raw,  wfc,  (long)LAYERS_ * FF_ * D_);
    run_cvt(Wp_raw,   wp,   (long)LAYERS_ * D_ * FF_);
    run_cvt(conv_w,   wcv,  (long)D_ * D_);

    c.Wqkv = wqkv; c.bqkv = bqkv;
    c.Wo   = wo;   c.bo   = bo;
    c.ln1g = ln1g; c.ln1b = ln1b;
    c.ln2g = ln2g; c.ln2b = ln2b;
    c.Wfc  = wfc;  c.bfc  = bfc;
    c.Wp   = wp;   c.bp   = bp;

    c.attn_smem = (2 * S_ * KVS + 8 * 200) * (int)sizeof(float);
    cudaFuncSetAttribute(attn_kernel, cudaFuncAttributeMaxDynamicSharedMemorySize,
                         c.attn_smem);
    cudaFuncSetAttribute(gemm_h, cudaFuncAttributeMaxDynamicSharedMemorySize,
                         GEMM_SMEM);

    // ---- patch embed (im2col GEMM) ----
    {
        const int total = B2 * L_ * D_;
        im2col_kernel<<<(total + 255) / 256, 256>>>(masked, prompted, c.col);
        run_gemm(c.col, wcv, nullptr, nullptr, c.att, B2 * L_, D_, D_, 1);
        const int tot2 = B2 * S_ * D_;
        embed_kernel<<<(tot2 + 255) / 256, 256>>>(c.att, cls_emb, pos_emb, c.x12);
        ln_kernel<float><<<B2 * S_, 256>>>(c.x12, D_, c.x12, D_,
                                           lnpre_g, lnpre_b, B2 * S_);
    }

    clsbias_kernel<<<(NB * L_ + 255) / 256, 256>>>(pred, c.clsb);

    for (int i = 0; i < 10; i++)
        run_block(c, c.x12, B2, i, nullptr);

    float* x  = c.x12;
    float* x2 = c.x12 + (size_t)NB * S_ * D_;
    const int layers2[2] = {10, 11};
    for (int t = 0; t < 2; t++) {
        int i = layers2[t];
        const int tot = NB * S_ * D_;
        mask_combine_kernel<<<(tot + 255) / 256, 256>>>(x, x2, pred);
        run_block(c, x, NB, i, nullptr);
        run_block(c, x2, NB, i, c.clsb);
    }

    ln_kernel<float><<<NB, 256>>>(x, (long)S_ * D_, c.cls, D_,
                                  lnpost_g, lnpost_b, NB);
    proj_out_kernel<<<dim3((OUT_ + 255) / 256, NB), 256>>>(c.cls, proj, out);

    (void)in_sizes; (void)n_in; (void)out_size;
}

// round 9
// speedup vs baseline: 6.7760x; 1.8956x over previous
#include <cuda_runtime.h>
#include <cuda_fp16.h>
#include <math.h>
#include <stdint.h>

// ---------------- Problem constants ----------------
#define D_    768
#define H_    12
#define HD_   64
#define S_    197
#define L_    196
#define NB    16          // batch per image set
#define B2    32          // both image sets
#define FF_   3072
#define OUT_  512
#define QKV3  2304
#define IMG_  224
#define GRID_ 14
#define PCH_  16
#define LAYERS_ 12

// ---------------- Scratch (device globals; no allocation allowed) ----------------
__device__ float  g_x12[B2 * S_ * D_];      // residual stream (fp32)
__device__ __half g_xln[B2 * S_ * D_];      // LN output (fp16)
__device__ __half g_qkv[B2 * S_ * QKV3];    // qkv (fp16, feeds TC attention)
__device__ __half g_att[B2 * S_ * D_];      // attention out / conv_out temp (fp16)
__device__ __half g_ffh[B2 * S_ * FF_];     // MLP hidden (fp16)
__device__ __half g_im2col[B2 * L_ * D_];   // patch im2col (fp16)
__device__ float  g_clsb[NB * L_];          // cls-row attention bias
__device__ float  g_cls[NB * D_];           // ln_post output (fp32)

// fp16 weight copies (B operands, [N,K] row-major)
__device__ __half g_wqkv[LAYERS_ * QKV3 * D_];
__device__ __half g_wo  [LAYERS_ * D_ * D_];
__device__ __half g_wfc [LAYERS_ * FF_ * D_];
__device__ __half g_wp  [LAYERS_ * D_ * FF_];
__device__ __half g_wcv [D_ * D_];

// ---- weight fp32 -> fp16 conversion (once per launch) ----
__global__ void cvt_half_kernel(const float4* __restrict__ in,
                                uint2* __restrict__ out, int n4)
{
    for (int i = blockIdx.x * 256 + threadIdx.x; i < n4; i += gridDim.x * 256) {
        float4 v = in[i];
        __half2 h0 = __floats2half2_rn(v.x, v.y);
        __half2 h1 = __floats2half2_rn(v.z, v.w);
        uint2 o;
        o.x = *(uint32_t*)&h0;
        o.y = *(uint32_t*)&h1;
        out[i] = o;
    }
}

// ---------------- shared MMA / LDSM macros ----------------
#define LDSM4(r0, r1, r2, r3, addr)                                    \
    asm volatile("ldmatrix.sync.aligned.m8n8.x4.shared.b16 "           \
                 "{%0,%1,%2,%3}, [%4];"                                \
                 : "=r"(r0), "=r"(r1), "=r"(r2), "=r"(r3) : "r"(addr))

#define LDSM4T(r0, r1, r2, r3, addr)                                   \
    asm volatile("ldmatrix.sync.aligned.m8n8.x4.trans.shared.b16 "     \
                 "{%0,%1,%2,%3}, [%4];"                                \
                 : "=r"(r0), "=r"(r1), "=r"(r2), "=r"(r3) : "r"(addr))

#define MMA_F16(d, a, b)                                               \
    asm volatile(                                                      \
        "mma.sync.aligned.m16n8k16.row.col.f32.f16.f16.f32 "           \
        "{%0,%1,%2,%3}, {%4,%5,%6,%7}, {%8,%9}, {%0,%1,%2,%3};"        \
        : "+f"((d)[0]), "+f"((d)[1]), "+f"((d)[2]), "+f"((d)[3])       \
        : "r"((a)[0]), "r"((a)[1]), "r"((a)[2]), "r"((a)[3]),          \
          "r"((b)[0]), "r"((b)[1]))

__device__ __forceinline__ uint32_t packh2(float lo, float hi) {
    __half2 h = __floats2half2_rn(lo, hi);
    return *(uint32_t*)&h;
}

// ======================================================================
// FP16 tensor-core GEMM:
//   C[M,N] = act( A[M,K]h @ B[N,K]h^T + bias[N] ) (+ resid[M,N])
// 128x128x64 block tile, 256 threads (8 warps 4x2), warp tile 32x64.
// flags: bit0 = half output, bit1 = GELU.
// ======================================================================
#define HBK   64                 // K per tile (halfs)
#define HST   16384              // bytes per stage per operand (128*128)

__global__ __launch_bounds__(256, 2) void gemm_h(
    const __half* __restrict__ A, const __half* __restrict__ B,
    const float* __restrict__ bias, const float* __restrict__ resid,
    void* __restrict__ Cv, int M, int N, int K, int flags)
{
    extern __shared__ char smb[];

    const int tid  = threadIdx.x;
    const int lane = tid & 31, wid = tid >> 5;
    const int wm = wid & 3, wn = wid >> 2;
    const int grp = lane >> 2, qid = lane & 3;
    const int bm = blockIdx.y * 128, bn = blockIdx.x * 128;

    const uint32_t smemBase = (uint32_t)__cvta_generic_to_shared(smb);

    const int lr0 = tid >> 3;
    const int lc  = tid & 7;

    float acc[2][8][4];
    #pragma unroll
    for (int mf = 0; mf < 2; mf++)
        #pragma unroll
        for (int nf = 0; nf < 8; nf++)
            #pragma unroll
            for (int r = 0; r < 4; r++) acc[mf][nf][r] = 0.f;

    const int niter = K / HBK;

    auto issue = [&](int it, int st) {
        const int k0 = it * HBK;
        #pragma unroll
        for (int i = 0; i < 4; i++) {
            const int row = lr0 + i * 32;
            const uint32_t xoff = (uint32_t)(row * 128 + ((lc ^ (row & 7)) * 16));
            {
                int gr = bm + row;
                int ok = (gr < M);
                const __half* src = A + (size_t)(ok ? gr : (M - 1)) * K + k0 + lc * 8;
                uint32_t dst = smemBase + st * HST + xoff;
                int sz = ok ? 16 : 0;
                asm volatile("cp.async.cg.shared.global [%0], [%1], 16, %2;"
                             :: "r"(dst), "l"(src), "r"(sz));
            }
            {
                const __half* src = B + (size_t)(bn + row) * K + k0 + lc * 8;
                uint32_t dst = smemBase + 2 * HST + st * HST + xoff;
                asm volatile("cp.async.cg.shared.global [%0], [%1], 16;"
                             :: "r"(dst), "l"(src));
            }
        }
        asm volatile("cp.async.commit_group;");
    };

    issue(0, 0);
    int stage = 0;

    const int aRowIn = lane & 15;
    const int aKHalf = lane >> 4;
    const int bMat   = lane >> 3;
    const int bRowIn = (lane & 7) + ((bMat >> 1) << 3);
    const int bKHalf = bMat & 1;

    for (int it = 0; it < niter; it++) {
        if (it + 1 < niter) {
            issue(it + 1, stage ^ 1);
            asm volatile("cp.async.wait_group 1;");
        } else {
            asm volatile("cp.async.wait_group 0;");
        }
        __syncthreads();

        const uint32_t aStage = smemBase + stage * HST;
        const uint32_t bStage = smemBase + 2 * HST + stage * HST;

        #pragma unroll
        for (int ks = 0; ks < HBK; ks += 16) {
            const int kc = ks >> 3;
            uint32_t a[2][4], b[16];
            #pragma unroll
            for (int mf = 0; mf < 2; mf++) {
                const int row = wm * 32 + mf * 16 + aRowIn;
                const int ch  = (kc + aKHalf) ^ (row & 7);
                LDSM4(a[mf][0], a[mf][1], a[mf][2], a[mf][3],
                      aStage + (uint32_t)(row * 128 + ch * 16));
            }
            #pragma unroll
            for (int np = 0; np < 4; np++) {
                const int row = wn * 64 + np * 16 + bRowIn;
                const int ch  = (kc + bKHalf) ^ (row & 7);
                LDSM4(b[np * 4 + 0], b[np * 4 + 1], b[np * 4 + 2], b[np * 4 + 3],
                      bStage + (uint32_t)(row * 128 + ch * 16));
            }
            #pragma unroll
            for (int mf = 0; mf < 2; mf++)
                #pragma unroll
                for (int np = 0; np < 4; np++) {
                    MMA_F16(acc[mf][np * 2 + 0], a[mf], &b[np * 4 + 0]);
                    MMA_F16(acc[mf][np * 2 + 1], a[mf], &b[np * 4 + 2]);
                }
        }
        __syncthreads();
        stage ^= 1;
    }

    const int halfOut = flags & 1;
    const int act     = flags & 2;
    float* Cf = (float*)Cv;
    __half* Ch = (__half*)Cv;

    #pragma unroll
    for (int mf = 0; mf < 2; mf++) {
        #pragma unroll
        for (int hh = 0; hh < 2; hh++) {
            const int gm = bm + wm * 32 + mf * 16 + grp + hh * 8;
            if (gm >= M) continue;
            #pragma unroll
            for (int nf = 0; nf < 8; nf++) {
                const int gn = bn + wn * 64 + nf * 8 + 2 * qid;
                float v0 = acc[mf][nf][hh * 2 + 0];
                float v1 = acc[mf][nf][hh * 2 + 1];
                if (bias) { v0 += bias[gn]; v1 += bias[gn + 1]; }
                if (act) {
                    v0 = v0 / (1.f + expf(-1.702f * v0));
                    v1 = v1 / (1.f + expf(-1.702f * v1));
                }
                if (resid) {
                    const float* rp = resid + (size_t)gm * N + gn;
                    v0 += rp[0]; v1 += rp[1];
                }
                if (halfOut) {
                    __half2 h = __floats2half2_rn(v0, v1);
                    *(__half2*)(Ch + (size_t)gm * N + gn) = h;
                } else {
                    float2 o; o.x = v0; o.y = v1;
                    *(float2*)(Cf + (size_t)gm * N + gn) = o;
                }
            }
        }
    }
}

// ======================================================================
// Tensor-core attention. One block per (head=bx, batch=by), 8 warps.
// Q/K/V fp16 in smem (224 rows padded, 128B rows, xor swizzle).
// Per warp: chunks of 16 queries; QK^T mma -> fp32 scores in regs ->
// softmax (quad shuffles) -> P repacked to A-frags -> PV mma with
// ldmatrix.trans on V. Output /= rowsum at the end.
// ======================================================================
#define SATT   224                         // padded seq (14 * 16)
#define ATT_MAT 28672                      // bytes per matrix (224 * 128)
#define ATT_SMEM (3 * ATT_MAT)             // 86,016 B

__global__ __launch_bounds__(256) void attn_tc(
    const __half* __restrict__ qkv, const float* __restrict__ clsbias,
    __half* __restrict__ out)
{
    extern __shared__ char smb[];
    const int h = blockIdx.x, b = blockIdx.y;
    const int tid = threadIdx.x;
    const int lane = tid & 31, wid = tid >> 5;
    const uint32_t base = (uint32_t)__cvta_generic_to_shared(smb);

    // ---- load Q,K,V into swizzled smem (Q scaled by 1/8, exact) ----
    for (int i = tid; i < S_ * 24; i += 256) {
        int s = i / 24, rem = i % 24;
        int m3 = rem >> 3, c = rem & 7;
        const uint4 v = *(const uint4*)(qkv + ((size_t)(b * S_ + s)) * QKV3
                                        + m3 * D_ + h * HD_ + c * 8);
        uint4 w = v;
        if (m3 == 0) {
            const __half2 sc = __floats2half2_rn(0.125f, 0.125f);
            __half2* hp = (__half2*)&w;
            hp[0] = __hmul2(hp[0], sc); hp[1] = __hmul2(hp[1], sc);
            hp[2] = __hmul2(hp[2], sc); hp[3] = __hmul2(hp[3], sc);
        }
        *(uint4*)(smb + m3 * ATT_MAT + s * 128 + ((c ^ (s & 7)) * 16)) = w;
    }
    // zero-pad rows 197..223
    for (int i = tid; i < (SATT - S_) * 24; i += 256) {
        int r = S_ + i / 24, rem = i % 24;
        int m3 = rem >> 3, c = rem & 7;
        *(uint4*)(smb + m3 * ATT_MAT + r * 128 + ((c ^ (r & 7)) * 16)) =
            make_uint4(0, 0, 0, 0);
    }
    __syncthreads();

    const int grp = lane >> 2, qid = lane & 3;
    const int aRow = lane & 15, aK = lane >> 4;                 // QK A (Q)
    const int bRow = (lane & 7) + ((lane >> 4) << 3);           // QK B (K)
    const int bK   = (lane >> 3) & 1;
    const int vRow = (lane & 7) + (((lane >> 3) & 1) << 3);     // PV B (V, trans)
    const int vC   = lane >> 4;

    const bool hasBias = (clsbias != nullptr);

    for (int chunk = wid; chunk < 13; chunk += 8) {
        const int mbase = chunk * 16;

        // ---- QK^T: scores [16 x 224] ----
        float sc[28][4];
        #pragma unroll
        for (int j = 0; j < 28; j++)
            #pragma unroll
            for (int e = 0; e < 4; e++) sc[j][e] = 0.f;

        #pragma unroll
        for (int t = 0; t < 4; t++) {
            uint32_t a[4];
            const int ar = mbase + aRow;
            LDSM4(a[0], a[1], a[2], a[3],
                  base + (uint32_t)(ar * 128 + (((2 * t + aK) ^ (ar & 7)) * 16)));
            #pragma unroll
            for (int np = 0; np < 14; np++) {
                uint32_t bb[4];
                const int br = np * 16 + bRow;
                LDSM4(bb[0], bb[1], bb[2], bb[3],
                      base + (uint32_t)(ATT_MAT + br * 128
                                        + (((2 * t + bK) ^ (br & 7)) * 16)));
                MMA_F16(sc[np * 2 + 0], a, &bb[0]);
                MMA_F16(sc[np * 2 + 1], a, &bb[2]);
            }
        }

        // ---- softmax over k (cols) in registers ----
        const bool dobias = hasBias && (mbase == 0) && (grp == 0);
        float m0 = -1e30f, m1 = -1e30f;
        #pragma unroll
        for (int j = 0; j < 28; j++) {
            const int col = j * 8 + 2 * qid;
            if (dobias) {
                if (col >= 1 && col < S_)     sc[j][0] += clsbias[b * L_ + col - 1];
                if (col + 1 < S_)             sc[j][1] += clsbias[b * L_ + col];
            }
            if (col >= S_)     { sc[j][0] = -1e30f; sc[j][2] = -1e30f; }
            if (col + 1 >= S_) { sc[j][1] = -1e30f; sc[j][3] = -1e30f; }
            m0 = fmaxf(m0, fmaxf(sc[j][0], sc[j][1]));
            m1 = fmaxf(m1, fmaxf(sc[j][2], sc[j][3]));
        }
        m0 = fmaxf(m0, __shfl_xor_sync(0xffffffffu, m0, 1));
        m0 = fmaxf(m0, __shfl_xor_sync(0xffffffffu, m0, 2));
        m1 = fmaxf(m1, __shfl_xor_sync(0xffffffffu, m1, 1));
        m1 = fmaxf(m1, __shfl_xor_sync(0xffffffffu, m1, 2));

        float s0 = 0.f, s1 = 0.f;
        #pragma unroll
        for (int j = 0; j < 28; j++) {
            sc[j][0] = __expf(sc[j][0] - m0);
            sc[j][1] = __expf(sc[j][1] - m0);
            sc[j][2] = __expf(sc[j][2] - m1);
            sc[j][3] = __expf(sc[j][3] - m1);
            s0 += sc[j][0] + sc[j][1];
            s1 += sc[j][2] + sc[j][3];
        }
        s0 += __shfl_xor_sync(0xffffffffu, s0, 1);
        s0 += __shfl_xor_sync(0xffffffffu, s0, 2);
        s1 += __shfl_xor_sync(0xffffffffu, s1, 1);
        s1 += __shfl_xor_sync(0xffffffffu, s1, 2);

        // ---- PV: out [16 x 64] = P [16 x 224] @ V [224 x 64] ----
        float ov[8][4];
        #pragma unroll
        for (int j = 0; j < 8; j++)
            #pragma unroll
            for (int e = 0; e < 4; e++) ov[j][e] = 0.f;

        #pragma unroll
        for (int t = 0; t < 14; t++) {
            uint32_t a[4];
            a[0] = packh2(sc[2 * t][0],     sc[2 * t][1]);
            a[1] = packh2(sc[2 * t][2],     sc[2 * t][3]);
            a[2] = packh2(sc[2 * t + 1][0], sc[2 * t + 1][1]);
            a[3] = packh2(sc[2 * t + 1][2], sc[2 * t + 1][3]);
            const int vr = t * 16 + vRow;
            #pragma unroll
            for (int np = 0; np < 4; np++) {
                uint32_t vv[4];
                const int vc = 2 * np + vC;
                LDSM4T(vv[0], vv[1], vv[2], vv[3],
                       base + (uint32_t)(2 * ATT_MAT + vr * 128
                                         + ((vc ^ (vr & 7)) * 16)));
                MMA_F16(ov[np * 2 + 0], a, &vv[0]);
                MMA_F16(ov[np * 2 + 1], a, &vv[2]);
            }
        }

        // ---- normalize + store ----
        const float inv0 = 1.f / s0, inv1 = 1.f / s1;
        const int q0 = mbase + grp, q1 = q0 + 8;
        #pragma unroll
        for (int j = 0; j < 8; j++) {
            const int col = h * HD_ + j * 8 + 2 * qid;
            if (q0 < S_) {
                __half2 o = __floats2half2_rn(ov[j][0] * inv0, ov[j][1] * inv0);
                *(__half2*)(out + (size_t)(b * S_ + q0) * D_ + col) = o;
            }
            if (q1 < S_) {
                __half2 o = __floats2half2_rn(ov[j][2] * inv1, ov[j][3] * inv1);
                *(__half2*)(out + (size_t)(b * S_ + q1) * D_ + col) = o;
            }
        }
    }
}

// ======================================================================
// LayerNorm: one block (256 thr) per row of 768. Output type templated.
// ======================================================================
template <typename TO>
__global__ __launch_bounds__(256) void ln_kernel(
    const float* __restrict__ x, long in_stride,
    TO* __restrict__ y, long out_stride,
    const float* __restrict__ g, const float* __restrict__ b, int rows)
{
    int r = blockIdx.x;
    if (r >= rows) return;
    const float* xr = x + (size_t)r * in_stride;
    TO* yr = y + (size_t)r * out_stride;
    int t = threadIdx.x;

    float v0 = xr[t], v1 = xr[t + 256], v2 = xr[t + 512];

    __shared__ float red[8];
    __shared__ float bc;

    float s = v0 + v1 + v2;
    #pragma unroll
    for (int o = 16; o > 0; o >>= 1) s += __shfl_xor_sync(0xffffffffu, s, o);
    if ((t & 31) == 0) red[t >> 5] = s;
    __syncthreads();
    if (t == 0) { float tot = 0.f; for (int i = 0; i < 8; i++) tot += red[i]; bc = tot; }
    __syncthreads();
    float mu = bc * (1.f / 768.f);

    float d0 = v0 - mu, d1 = v1 - mu, d2 = v2 - mu;
    float ss = d0 * d0 + d1 * d1 + d2 * d2;
    #pragma unroll
    for (int o = 16; o > 0; o >>= 1) ss += __shfl_xor_sync(0xffffffffu, ss, o);
    __syncthreads();
    if ((t & 31) == 0) red[t >> 5] = ss;
    __syncthreads();
    if (t == 0) { float tot = 0.f; for (int i = 0; i < 8; i++) tot += red[i]; bc = tot; }
    __syncthreads();
    float rs = rsqrtf(bc * (1.f / 768.f) + 1e-5f);

    yr[t]       = (TO)(d0 * rs * g[t]       + b[t]);
    yr[t + 256] = (TO)(d1 * rs * g[t + 256] + b[t + 256]);
    yr[t + 512] = (TO)(d2 * rs * g[t + 512] + b[t + 512]);
}

// ======================================================================
// Patch embed helpers
// ======================================================================
__global__ void im2col_kernel(const float* __restrict__ masked,
                              const float* __restrict__ prompted,
                              __half* __restrict__ col)
{
    int idx = blockIdx.x * 256 + threadIdx.x;
    const int total = B2 * L_ * D_;
    if (idx >= total) return;
    int k = idx % D_;
    int m = idx / D_;
    int b = m / L_, l = m % L_;
    int gy = l / GRID_, gx = l % GRID_;
    int c = k >> 8, rem = k & 255;
    int py = rem >> 4, px = rem & 15;
    const float* src = (b < NB) ? (masked + (size_t)b * 3 * IMG_ * IMG_)
                                : (prompted + (size_t)(b - NB) * 3 * IMG_ * IMG_);
    col[idx] = __float2half_rn(
        src[((size_t)c * IMG_ + gy * PCH_ + py) * IMG_ + gx * PCH_ + px]);
}

__global__ void embed_kernel(const __half* __restrict__ conv_out,
                             const float* __restrict__ cls_emb,
                             const float* __restrict__ pos,
                             float* __restrict__ x)
{
    int idx = blockIdx.x * 256 + threadIdx.x;
    const int total = B2 * S_ * D_;
    if (idx >= total) return;
    int d = idx % D_;
    int bs = idx / D_;
    int s = bs % S_, b = bs / S_;
    float v = (s == 0) ? cls_emb[d]
                       : __half2float(conv_out[((size_t)b * L_ + (s - 1)) * D_ + d]);
    x[idx] = v + pos[s * D_ + d];
}

__global__ void clsbias_kernel(const float* __restrict__ pm, float* __restrict__ cb)
{
    int i = blockIdx.x * 256 + threadIdx.x;
    if (i < NB * L_) cb[i] = (pm[i] != 0.f) ? 0.f : -1e30f;
}

__global__ void mask_combine_kernel(float* __restrict__ x, const float* __restrict__ x2,
                                    const float* __restrict__ pm)
{
    int idx = blockIdx.x * 256 + threadIdx.x;
    const int total = NB * S_ * D_;
    if (idx >= total) return;
    int bs = idx / D_;
    int s = bs % S_;
    int b = bs / S_;
    float mf = (s == 0) ? 1.f : pm[b * L_ + (s - 1)];
    x[idx] = 2.f * x2[idx] * mf + x[idx];
}

__global__ void proj_out_kernel(const float* __restrict__ cls,
                                const float* __restrict__ proj,
                                float* __restrict__ out)
{
    int n = blockIdx.x * 256 + threadIdx.x;
    int m = blockIdx.y;
    if (n >= OUT_) return;
    float s = 0.f;
    #pragma unroll 4
    for (int k = 0; k < D_; k++) s += cls[m * D_ + k] * proj[(size_t)k * OUT_ + n];
    out[m * OUT_ + n] = s;
}

// ======================================================================
// Host orchestration
// ======================================================================
template <typename T>
static T* symaddr_t(const void* s) {
    void* p = nullptr;
    cudaGetSymbolAddress(&p, s);
    return (T*)p;
}

#define GEMM_SMEM (4 * HST)   // 65,536 B

static void run_gemm(const __half* A, const __half* B, const float* bias,
                     const float* resid, void* C, int M, int N, int K, int flags)
{
    dim3 grid(N / 128, (M + 127) / 128);
    gemm_h<<<grid, 256, GEMM_SMEM>>>(A, B, bias, resid, C, M, N, K, flags);
}

static void run_cvt(const float* in, __half* out, long n)
{
    int n4 = (int)(n / 4);
    int blocks = (n4 + 255) / 256;
    if (blocks > 16384) blocks = 16384;
    cvt_half_kernel<<<blocks, 256>>>((const float4*)in, (uint2*)out, n4);
}

struct Ctx {
    float *x12, *clsb, *cls;
    __half *xln, *qkv, *att, *ffh, *col;
    const __half *Wqkv, *Wo, *Wfc, *Wp;
    const float *bqkv, *bo, *ln1g, *ln1b, *ln2g, *ln2b, *bfc, *bp;
};

static void run_block(const Ctx& c, float* x, int Bn, int layer, const float* bias)
{
    const int M = Bn * S_;
    ln_kernel<__half><<<M, 256>>>(x, D_, c.xln, D_,
                                  c.ln1g + layer * D_, c.ln1b + layer * D_, M);
    run_gemm(c.xln, c.Wqkv + (size_t)layer * QKV3 * D_, c.bqkv + layer * QKV3,
             nullptr, c.qkv, M, QKV3, D_, 1);
    attn_tc<<<dim3(H_, Bn), 256, ATT_SMEM>>>(c.qkv, bias, c.att);
    run_gemm(c.att, c.Wo + (size_t)layer * D_ * D_, c.bo + layer * D_,
             x, x, M, D_, D_, 0);
    ln_kernel<__half><<<M, 256>>>(x, D_, c.xln, D_,
                                  c.ln2g + layer * D_, c.ln2b + layer * D_, M);
    run_gemm(c.xln, c.Wfc + (size_t)layer * FF_ * D_, c.bfc + layer * FF_,
             nullptr, c.ffh, M, FF_, D_, 1 | 2);
    run_gemm(c.ffh, c.Wp + (size_t)layer * D_ * FF_, c.bp + layer * D_,
             x, x, M, D_, FF_, 0);
}

extern "C" void kernel_launch(void* const* d_in, const int* in_sizes, int n_in,
                              void* d_out, int out_size)
{
    const float* masked   = (const float*)d_in[0];
    const float* prompted = (const float*)d_in[1];
    const float* pred     = (const float*)d_in[2];
    const float* conv_w   = (const float*)d_in[3];
    const float* cls_emb  = (const float*)d_in[4];
    const float* pos_emb  = (const float*)d_in[5];
    const float* lnpre_g  = (const float*)d_in[6];
    const float* lnpre_b  = (const float*)d_in[7];

    const float* Wqkv_raw = (const float*)d_in[8];
    const float* bqkv     = (const float*)d_in[9];
    const float* Wo_raw   = (const float*)d_in[10];
    const float* bo       = (const float*)d_in[11];
    const float* ln1g     = (const float*)d_in[12];
    const float* ln1b     = (const float*)d_in[13];
    const float* ln2g     = (const float*)d_in[14];
    const float* ln2b     = (const float*)d_in[15];
    const float* Wfc_raw  = (const float*)d_in[16];
    const float* bfc      = (const float*)d_in[17];
    const float* Wp_raw   = (const float*)d_in[18];
    const float* bp       = (const float*)d_in[19];
    const float* lnpost_g = (const float*)d_in[20];
    const float* lnpost_b = (const float*)d_in[21];
    const float* proj     = (const float*)d_in[22];
    float* out = (float*)d_out;

    Ctx c;
    c.x12  = symaddr_t<float>(g_x12);
    c.xln  = symaddr_t<__half>(g_xln);
    c.qkv  = symaddr_t<__half>(g_qkv);
    c.att  = symaddr_t<__half>(g_att);
    c.ffh  = symaddr_t<__half>(g_ffh);
    c.col  = symaddr_t<__half>(g_im2col);
    c.clsb = symaddr_t<float>(g_clsb);
    c.cls  = symaddr_t<float>(g_cls);

    __half* wqkv = symaddr_t<__half>(g_wqkv);
    __half* wo   = symaddr_t<__half>(g_wo);
    __half* wfc  = symaddr_t<__half>(g_wfc);
    __half* wp   = symaddr_t<__half>(g_wp);
    __half* wcv  = symaddr_t<__half>(g_wcv);

    run_cvt(Wqkv_raw, wqkv, (long)LAYERS_ * QKV3 * D_);
    run_cvt(Wo_raw,   wo,   (long)LAYERS_ * D_ * D_);
    run_cvt(Wfc_raw,  wfc,  (long)LAYERS_ * FF_ * D_);
    run_cvt(Wp_raw,   wp,   (long)LAYERS_ * D_ * FF_);
    run_cvt(conv_w,   wcv,  (long)D_ * D_);

    c.Wqkv = wqkv; c.bqkv = bqkv;
    c.Wo   = wo;   c.bo   = bo;
    c.ln1g = ln1g; c.ln1b = ln1b;
    c.ln2g = ln2g; c.ln2b = ln2b;
    c.Wfc  = wfc;  c.bfc  = bfc;
    c.Wp   = wp;   c.bp   = bp;

    cudaFuncSetAttribute(attn_tc, cudaFuncAttributeMaxDynamicSharedMemorySize,
                         ATT_SMEM);
    cudaFuncSetAttribute(gemm_h, cudaFuncAttributeMaxDynamicSharedMemorySize,
                         GEMM_SMEM);

    // ---- patch embed (im2col GEMM) ----
    {
        const int total = B2 * L_ * D_;
        im2col_kernel<<<(total + 255) / 256, 256>>>(masked, prompted, c.col);
        run_gemm(c.col, wcv, nullptr, nullptr, c.att, B2 * L_, D_, D_, 1);
        const int tot2 = B2 * S_ * D_;
        embed_kernel<<<(tot2 + 255) / 256, 256>>>(c.att, cls_emb, pos_emb, c.x12);
        ln_kernel<float><<<B2 * S_, 256>>>(c.x12, D_, c.x12, D_,
                                           lnpre_g, lnpre_b, B2 * S_);
    }

    clsbias_kernel<<<(NB * L_ + 255) / 256, 256>>>(pred, c.clsb);

    for (int i = 0; i < 10; i++)
        run_block(c, c.x12, B2, i, nullptr);

    float* x  = c.x12;
    float* x2 = c.x12 + (size_t)NB * S_ * D_;
    const int layers2[2] = {10, 11};
    for (int t = 0; t < 2; t++) {
        int i = layers2[t];
        const int tot = NB * S_ * D_;
        mask_combine_kernel<<<(tot + 255) / 256, 256>>>(x, x2, pred);
        run_block(c, x, NB, i, nullptr);
        run_block(c, x2, NB, i, c.clsb);
    }

    ln_kernel<float><<<NB, 256>>>(x, (long)S_ * D_, c.cls, D_,
                                  lnpost_g, lnpost_b, NB);
    proj_out_kernel<<<dim3((OUT_ + 255) / 256, NB), 256>>>(c.cls, proj, out);

    (void)in_sizes; (void)n_in; (void)out_size;
}

// round 11
// speedup vs baseline: 6.9311x; 1.0229x over previous
#include <cuda_runtime.h>
#include <cuda_fp16.h>
#include <math.h>
#include <stdint.h>

// ---------------- Problem constants ----------------
#define D_    768
#define H_    12
#define HD_   64
#define S_    197
#define L_    196
#define NB    16          // batch per image set
#define B2    32          // both image sets
#define FF_   3072
#define OUT_  512
#define QKV3  2304
#define IMG_  224
#define GRID_ 14
#define PCH_  16
#define LAYERS_ 12

// ---------------- Scratch (device globals; no allocation allowed) ----------------
__device__ float  g_x12[B2 * S_ * D_];      // residual stream (fp32)
__device__ __half g_xln[B2 * S_ * D_];      // LN output (fp16)
__device__ __half g_qkv[B2 * S_ * QKV3];    // qkv (fp16, feeds TC attention)
__device__ __half g_att[B2 * S_ * D_];      // attention out / conv_out temp (fp16)
__device__ __half g_ffh[B2 * S_ * FF_];     // MLP hidden (fp16)
__device__ __half g_im2col[B2 * L_ * D_];   // patch im2col (fp16)
__device__ float  g_clsb[NB * L_];          // cls-row attention bias
__device__ float  g_cls[NB * D_];           // ln_post output (fp32)

// fp16 weight copies (B operands, [N,K] row-major)
__device__ __half g_wqkv[LAYERS_ * QKV3 * D_];
__device__ __half g_wo  [LAYERS_ * D_ * D_];
__device__ __half g_wfc [LAYERS_ * FF_ * D_];
__device__ __half g_wp  [LAYERS_ * D_ * FF_];
__device__ __half g_wcv [D_ * D_];

// ---- weight fp32 -> fp16 conversion (once per launch) ----
__global__ void cvt_half_kernel(const float4* __restrict__ in,
                                uint2* __restrict__ out, int n4)
{
    for (int i = blockIdx.x * 256 + threadIdx.x; i < n4; i += gridDim.x * 256) {
        float4 v = in[i];
        __half2 h0 = __floats2half2_rn(v.x, v.y);
        __half2 h1 = __floats2half2_rn(v.z, v.w);
        uint2 o;
        o.x = *(uint32_t*)&h0;
        o.y = *(uint32_t*)&h1;
        out[i] = o;
    }
}

// ---------------- MMA / LDSM macros ----------------
#define LDSM4(r0, r1, r2, r3, addr)                                    \
    asm volatile("ldmatrix.sync.aligned.m8n8.x4.shared.b16 "           \
                 "{%0,%1,%2,%3}, [%4];"                                \
                 : "=r"(r0), "=r"(r1), "=r"(r2), "=r"(r3) : "r"(addr))

#define LDSM4T(r0, r1, r2, r3, addr)                                   \
    asm volatile("ldmatrix.sync.aligned.m8n8.x4.trans.shared.b16 "     \
                 "{%0,%1,%2,%3}, [%4];"                                \
                 : "=r"(r0), "=r"(r1), "=r"(r2), "=r"(r3) : "r"(addr))

#define MMA_F16(d, a, b)                                               \
    asm volatile(                                                      \
        "mma.sync.aligned.m16n8k16.row.col.f32.f16.f16.f32 "           \
        "{%0,%1,%2,%3}, {%4,%5,%6,%7}, {%8,%9}, {%0,%1,%2,%3};"        \
        : "+f"((d)[0]), "+f"((d)[1]), "+f"((d)[2]), "+f"((d)[3])       \
        : "r"((a)[0]), "r"((a)[1]), "r"((a)[2]), "r"((a)[3]),          \
          "r"((b)[0]), "r"((b)[1]))

__device__ __forceinline__ uint32_t packh2(float lo, float hi) {
    __half2 h = __floats2half2_rn(lo, hi);
    return *(uint32_t*)&h;
}

// ======================================================================
// FP16 tensor-core GEMM (mma.sync):
//   C[M,N] = act( A[M,K]h @ B[N,K]h^T + bias[N] ) (+ resid[M,N])
// 128x128x64 block tile, 256 threads (8 warps 4x2), warp tile 32x64.
// flags: bit0 = half output, bit1 = GELU.
// ======================================================================
#define HBK   64
#define HST   16384

__global__ __launch_bounds__(256, 2) void gemm_h(
    const __half* __restrict__ A, const __half* __restrict__ B,
    const float* __restrict__ bias, const float* __restrict__ resid,
    void* __restrict__ Cv, int M, int N, int K, int flags)
{
    extern __shared__ char smb[];

    const int tid  = threadIdx.x;
    const int lane = tid & 31, wid = tid >> 5;
    const int wm = wid & 3, wn = wid >> 2;
    const int grp = lane >> 2, qid = lane & 3;
    const int bm = blockIdx.y * 128, bn = blockIdx.x * 128;

    const uint32_t smemBase = (uint32_t)__cvta_generic_to_shared(smb);

    const int lr0 = tid >> 3;
    const int lc  = tid & 7;

    float acc[2][8][4];
    #pragma unroll
    for (int mf = 0; mf < 2; mf++)
        #pragma unroll
        for (int nf = 0; nf < 8; nf++)
            #pragma unroll
            for (int r = 0; r < 4; r++) acc[mf][nf][r] = 0.f;

    const int niter = K / HBK;

    auto issue = [&](int it, int st) {
        const int k0 = it * HBK;
        #pragma unroll
        for (int i = 0; i < 4; i++) {
            const int row = lr0 + i * 32;
            const uint32_t xoff = (uint32_t)(row * 128 + ((lc ^ (row & 7)) * 16));
            {
                int gr = bm + row;
                int ok = (gr < M);
                const __half* src = A + (size_t)(ok ? gr : (M - 1)) * K + k0 + lc * 8;
                uint32_t dst = smemBase + st * HST + xoff;
                int sz = ok ? 16 : 0;
                asm volatile("cp.async.cg.shared.global [%0], [%1], 16, %2;"
                             :: "r"(dst), "l"(src), "r"(sz));
            }
            {
                const __half* src = B + (size_t)(bn + row) * K + k0 + lc * 8;
                uint32_t dst = smemBase + 2 * HST + st * HST + xoff;
                asm volatile("cp.async.cg.shared.global [%0], [%1], 16;"
                             :: "r"(dst), "l"(src));
            }
        }
        asm volatile("cp.async.commit_group;");
    };

    issue(0, 0);
    int stage = 0;

    const int aRowIn = lane & 15;
    const int aKHalf = lane >> 4;
    const int bMat   = lane >> 3;
    const int bRowIn = (lane & 7) + ((bMat >> 1) << 3);
    const int bKHalf = bMat & 1;

    for (int it = 0; it < niter; it++) {
        if (it + 1 < niter) {
            issue(it + 1, stage ^ 1);
            asm volatile("cp.async.wait_group 1;");
        } else {
            asm volatile("cp.async.wait_group 0;");
        }
        __syncthreads();

        const uint32_t aStage = smemBase + stage * HST;
        const uint32_t bStage = smemBase + 2 * HST + stage * HST;

        #pragma unroll
        for (int ks = 0; ks < HBK; ks += 16) {
            const int kc = ks >> 3;
            uint32_t a[2][4], b[16];
            #pragma unroll
            for (int mf = 0; mf < 2; mf++) {
                const int row = wm * 32 + mf * 16 + aRowIn;
                const int ch  = (kc + aKHalf) ^ (row & 7);
                LDSM4(a[mf][0], a[mf][1], a[mf][2], a[mf][3],
                      aStage + (uint32_t)(row * 128 + ch * 16));
            }
            #pragma unroll
            for (int np = 0; np < 4; np++) {
                const int row = wn * 64 + np * 16 + bRowIn;
                const int ch  = (kc + bKHalf) ^ (row & 7);
                LDSM4(b[np * 4 + 0], b[np * 4 + 1], b[np * 4 + 2], b[np * 4 + 3],
                      bStage + (uint32_t)(row * 128 + ch * 16));
            }
            #pragma unroll
            for (int mf = 0; mf < 2; mf++)
                #pragma unroll
                for (int np = 0; np < 4; np++) {
                    MMA_F16(acc[mf][np * 2 + 0], a[mf], &b[np * 4 + 0]);
                    MMA_F16(acc[mf][np * 2 + 1], a[mf], &b[np * 4 + 2]);
                }
        }
        __syncthreads();
        stage ^= 1;
    }

    const int halfOut = flags & 1;
    const int act     = flags & 2;
    float* Cf = (float*)Cv;
    __half* Ch = (__half*)Cv;

    #pragma unroll
    for (int mf = 0; mf < 2; mf++) {
        #pragma unroll
        for (int hh = 0; hh < 2; hh++) {
            const int gm = bm + wm * 32 + mf * 16 + grp + hh * 8;
            if (gm >= M) continue;
            #pragma unroll
            for (int nf = 0; nf < 8; nf++) {
                const int gn = bn + wn * 64 + nf * 8 + 2 * qid;
                float v0 = acc[mf][nf][hh * 2 + 0];
                float v1 = acc[mf][nf][hh * 2 + 1];
                if (bias) { v0 += bias[gn]; v1 += bias[gn + 1]; }
                if (act) {
                    v0 = v0 / (1.f + expf(-1.702f * v0));
                    v1 = v1 / (1.f + expf(-1.702f * v1));
                }
                if (resid) {
                    const float* rp = resid + (size_t)gm * N + gn;
                    v0 += rp[0]; v1 += rp[1];
                }
                if (halfOut) {
                    __half2 h = __floats2half2_rn(v0, v1);
                    *(__half2*)(Ch + (size_t)gm * N + gn) = h;
                } else {
                    float2 o; o.x = v0; o.y = v1;
                    *(float2*)(Cf + (size_t)gm * N + gn) = o;
                }
            }
        }
    }
}

// ======================================================================
// Tensor-core attention (mma.sync). One block per (head, batch), 8 warps.
// ======================================================================
#define SATT   224
#define ATT_MAT 28672
#define ATT_SMEM (3 * ATT_MAT)

__global__ __launch_bounds__(256) void attn_tc(
    const __half* __restrict__ qkv, const float* __restrict__ clsbias,
    __half* __restrict__ out)
{
    extern __shared__ char smb[];
    const int h = blockIdx.x, b = blockIdx.y;
    const int tid = threadIdx.x;
    const int lane = tid & 31, wid = tid >> 5;
    const uint32_t base = (uint32_t)__cvta_generic_to_shared(smb);

    for (int i = tid; i < S_ * 24; i += 256) {
        int s = i / 24, rem = i % 24;
        int m3 = rem >> 3, c = rem & 7;
        const uint4 v = *(const uint4*)(qkv + ((size_t)(b * S_ + s)) * QKV3
                                        + m3 * D_ + h * HD_ + c * 8);
        uint4 w = v;
        if (m3 == 0) {
            const __half2 sc = __floats2half2_rn(0.125f, 0.125f);
            __half2* hp = (__half2*)&w;
            hp[0] = __hmul2(hp[0], sc); hp[1] = __hmul2(hp[1], sc);
            hp[2] = __hmul2(hp[2], sc); hp[3] = __hmul2(hp[3], sc);
        }
        *(uint4*)(smb + m3 * ATT_MAT + s * 128 + ((c ^ (s & 7)) * 16)) = w;
    }
    for (int i = tid; i < (SATT - S_) * 24; i += 256) {
        int r = S_ + i / 24, rem = i % 24;
        int m3 = rem >> 3, c = rem & 7;
        *(uint4*)(smb + m3 * ATT_MAT + r * 128 + ((c ^ (r & 7)) * 16)) =
            make_uint4(0, 0, 0, 0);
    }
    __syncthreads();

    const int grp = lane >> 2, qid = lane & 3;
    const int aRow = lane & 15, aK = lane >> 4;
    const int bRow = (lane & 7) + ((lane >> 4) << 3);
    const int bK   = (lane >> 3) & 1;
    const int vRow = (lane & 7) + (((lane >> 3) & 1) << 3);
    const int vC   = lane >> 4;

    const bool hasBias = (clsbias != nullptr);

    for (int chunk = wid; chunk < 13; chunk += 8) {
        const int mbase = chunk * 16;

        float sc[28][4];
        #pragma unroll
        for (int j = 0; j < 28; j++)
            #pragma unroll
            for (int e = 0; e < 4; e++) sc[j][e] = 0.f;

        #pragma unroll
        for (int t = 0; t < 4; t++) {
            uint32_t a[4];
            const int ar = mbase + aRow;
            LDSM4(a[0], a[1], a[2], a[3],
                  base + (uint32_t)(ar * 128 + (((2 * t + aK) ^ (ar & 7)) * 16)));
            #pragma unroll
            for (int np = 0; np < 14; np++) {
                uint32_t bb[4];
                const int br = np * 16 + bRow;
                LDSM4(bb[0], bb[1], bb[2], bb[3],
                      base + (uint32_t)(ATT_MAT + br * 128
                                        + (((2 * t + bK) ^ (br & 7)) * 16)));
                MMA_F16(sc[np * 2 + 0], a, &bb[0]);
                MMA_F16(sc[np * 2 + 1], a, &bb[2]);
            }
        }

        const bool dobias = hasBias && (mbase == 0) && (grp == 0);
        float m0 = -1e30f, m1 = -1e30f;
        #pragma unroll
        for (int j = 0; j < 28; j++) {
            const int col = j * 8 + 2 * qid;
            if (dobias) {
                if (col >= 1 && col < S_)     sc[j][0] += clsbias[b * L_ + col - 1];
                if (col + 1 < S_)             sc[j][1] += clsbias[b * L_ + col];
            }
            if (col >= S_)     { sc[j][0] = -1e30f; sc[j][2] = -1e30f; }
            if (col + 1 >= S_) { sc[j][1] = -1e30f; sc[j][3] = -1e30f; }
            m0 = fmaxf(m0, fmaxf(sc[j][0], sc[j][1]));
            m1 = fmaxf(m1, fmaxf(sc[j][2], sc[j][3]));
        }
        m0 = fmaxf(m0, __shfl_xor_sync(0xffffffffu, m0, 1));
        m0 = fmaxf(m0, __shfl_xor_sync(0xffffffffu, m0, 2));
        m1 = fmaxf(m1, __shfl_xor_sync(0xffffffffu, m1, 1));
        m1 = fmaxf(m1, __shfl_xor_sync(0xffffffffu, m1, 2));

        float s0 = 0.f, s1 = 0.f;
        #pragma unroll
        for (int j = 0; j < 28; j++) {
            sc[j][0] = __expf(sc[j][0] - m0);
            sc[j][1] = __expf(sc[j][1] - m0);
            sc[j][2] = __expf(sc[j][2] - m1);
            sc[j][3] = __expf(sc[j][3] - m1);
            s0 += sc[j][0] + sc[j][1];
            s1 += sc[j][2] + sc[j][3];
        }
        s0 += __shfl_xor_sync(0xffffffffu, s0, 1);
        s0 += __shfl_xor_sync(0xffffffffu, s0, 2);
        s1 += __shfl_xor_sync(0xffffffffu, s1, 1);
        s1 += __shfl_xor_sync(0xffffffffu, s1, 2);

        float ov[8][4];
        #pragma unroll
        for (int j = 0; j < 8; j++)
            #pragma unroll
            for (int e = 0; e < 4; e++) ov[j][e] = 0.f;

        #pragma unroll
        for (int t = 0; t < 14; t++) {
            uint32_t a[4];
            a[0] = packh2(sc[2 * t][0],     sc[2 * t][1]);
            a[1] = packh2(sc[2 * t][2],     sc[2 * t][3]);
            a[2] = packh2(sc[2 * t + 1][0], sc[2 * t + 1][1]);
            a[3] = packh2(sc[2 * t + 1][2], sc[2 * t + 1][3]);
            const int vr = t * 16 + vRow;
            #pragma unroll
            for (int np = 0; np < 4; np++) {
                uint32_t vv[4];
                const int vc = 2 * np + vC;
                LDSM4T(vv[0], vv[1], vv[2], vv[3],
                       base + (uint32_t)(2 * ATT_MAT + vr * 128
                                         + ((vc ^ (vr & 7)) * 16)));
                MMA_F16(ov[np * 2 + 0], a, &vv[0]);
                MMA_F16(ov[np * 2 + 1], a, &vv[2]);
            }
        }

        const float inv0 = 1.f / s0, inv1 = 1.f / s1;
        const int q0 = mbase + grp, q1 = q0 + 8;
        #pragma unroll
        for (int j = 0; j < 8; j++) {
            const int col = h * HD_ + j * 8 + 2 * qid;
            if (q0 < S_) {
                __half2 o = __floats2half2_rn(ov[j][0] * inv0, ov[j][1] * inv0);
                *(__half2*)(out + (size_t)(b * S_ + q0) * D_ + col) = o;
            }
            if (q1 < S_) {
                __half2 o = __floats2half2_rn(ov[j][2] * inv1, ov[j][3] * inv1);
                *(__half2*)(out + (size_t)(b * S_ + q1) * D_ + col) = o;
            }
        }
    }
}

// ======================================================================
// LayerNorm: one block (256 thr) per row of 768.
// ======================================================================
template <typename TO>
__global__ __launch_bounds__(256) void ln_kernel(
    const float* __restrict__ x, long in_stride,
    TO* __restrict__ y, long out_stride,
    const float* __restrict__ g, const float* __restrict__ b, int rows)
{
    int r = blockIdx.x;
    if (r >= rows) return;
    const float* xr = x + (size_t)r * in_stride;
    TO* yr = y + (size_t)r * out_stride;
    int t = threadIdx.x;

    float v0 = xr[t], v1 = xr[t + 256], v2 = xr[t + 512];

    __shared__ float red[8];
    __shared__ float bc;

    float s = v0 + v1 + v2;
    #pragma unroll
    for (int o = 16; o > 0; o >>= 1) s += __shfl_xor_sync(0xffffffffu, s, o);
    if ((t & 31) == 0) red[t >> 5] = s;
    __syncthreads();
    if (t == 0) { float tot = 0.f; for (int i = 0; i < 8; i++) tot += red[i]; bc = tot; }
    __syncthreads();
    float mu = bc * (1.f / 768.f);

    float d0 = v0 - mu, d1 = v1 - mu, d2 = v2 - mu;
    float ss = d0 * d0 + d1 * d1 + d2 * d2;
    #pragma unroll
    for (int o = 16; o > 0; o >>= 1) ss += __shfl_xor_sync(0xffffffffu, ss, o);
    __syncthreads();
    if ((t & 31) == 0) red[t >> 5] = ss;
    __syncthreads();
    if (t == 0) { float tot = 0.f; for (int i = 0; i < 8; i++) tot += red[i]; bc = tot; }
    __syncthreads();
    float rs = rsqrtf(bc * (1.f / 768.f) + 1e-5f);

    yr[t]       = (TO)(d0 * rs * g[t]       + b[t]);
    yr[t + 256] = (TO)(d1 * rs * g[t + 256] + b[t + 256]);
    yr[t + 512] = (TO)(d2 * rs * g[t + 512] + b[t + 512]);
}

// ======================================================================
// Patch embed helpers
// ======================================================================
__global__ void im2col_kernel(const float* __restrict__ masked,
                              const float* __restrict__ prompted,
                              __half* __restrict__ col)
{
    int idx = blockIdx.x * 256 + threadIdx.x;
    const int total = B2 * L_ * D_;
    if (idx >= total) return;
    int k = idx % D_;
    int m = idx / D_;
    int b = m / L_, l = m % L_;
    int gy = l / GRID_, gx = l % GRID_;
    int c = k >> 8, rem = k & 255;
    int py = rem >> 4, px = rem & 15;
    const float* src = (b < NB) ? (masked + (size_t)b * 3 * IMG_ * IMG_)
                                : (prompted + (size_t)(b - NB) * 3 * IMG_ * IMG_);
    col[idx] = __float2half_rn(
        src[((size_t)c * IMG_ + gy * PCH_ + py) * IMG_ + gx * PCH_ + px]);
}

__global__ void embed_kernel(const __half* __restrict__ conv_out,
                             const float* __restrict__ cls_emb,
                             const float* __restrict__ pos,
                             float* __restrict__ x)
{
    int idx = blockIdx.x * 256 + threadIdx.x;
    const int total = B2 * S_ * D_;
    if (idx >= total) return;
    int d = idx % D_;
    int bs = idx / D_;
    int s = bs % S_, b = bs / S_;
    float v = (s == 0) ? cls_emb[d]
                       : __half2float(conv_out[((size_t)b * L_ + (s - 1)) * D_ + d]);
    x[idx] = v + pos[s * D_ + d];
}

__global__ void clsbias_kernel(const float* __restrict__ pm, float* __restrict__ cb)
{
    int i = blockIdx.x * 256 + threadIdx.x;
    if (i < NB * L_) cb[i] = (pm[i] != 0.f) ? 0.f : -1e30f;
}

__global__ void mask_combine_kernel(float* __restrict__ x, const float* __restrict__ x2,
                                    const float* __restrict__ pm)
{
    int idx = blockIdx.x * 256 + threadIdx.x;
    const int total = NB * S_ * D_;
    if (idx >= total) return;
    int bs = idx / D_;
    int s = bs % S_;
    int b = bs / S_;
    float mf = (s == 0) ? 1.f : pm[b * L_ + (s - 1)];
    x[idx] = 2.f * x2[idx] * mf + x[idx];
}

__global__ void proj_out_kernel(const float* __restrict__ cls,
                                const float* __restrict__ proj,
                                float* __restrict__ out)
{
    int n = blockIdx.x * 256 + threadIdx.x;
    int m = blockIdx.y;
    if (n >= OUT_) return;
    float s = 0.f;
    #pragma unroll 4
    for (int k = 0; k < D_; k++) s += cls[m * D_ + k] * proj[(size_t)k * OUT_ + n];
    out[m * OUT_ + n] = s;
}

// ======================================================================
// Host orchestration (two streams inside graph capture)
// ======================================================================
template <typename T>
static T* symaddr_t(const void* s) {
    void* p = nullptr;
    cudaGetSymbolAddress(&p, s);
    return (T*)p;
}

#define GEMM_SMEM (4 * HST)   // 65,536 B

static void run_gemm(const __half* A, const __half* B, const float* bias,
                     const float* resid, void* C, int M, int N, int K, int flags,
                     cudaStream_t st)
{
    dim3 grid(N / 128, (M + 127) / 128);
    gemm_h<<<grid, 256, GEMM_SMEM, st>>>(A, B, bias, resid, C, M, N, K, flags);
}

static void run_cvt(const float* in, __half* out, long n, cudaStream_t st)
{
    int n4 = (int)(n / 4);
    int blocks = (n4 + 255) / 256;
    if (blocks > 16384) blocks = 16384;
    cvt_half_kernel<<<blocks, 256, 0, st>>>((const float4*)in, (uint2*)out, n4);
}

struct Ctx {
    float *x12, *clsb, *cls;
    __half *xln, *qkv, *att, *ffh, *col;
    const __half *Wqkv, *Wo, *Wfc, *Wp;
    const float *bqkv, *bo, *ln1g, *ln1b, *ln2g, *ln2b, *bfc, *bp;
};

// half = 0 -> first half of scratch, 1 -> second half (for concurrent blocks)
static void run_block(const Ctx& c, float* x, int Bn, int layer, const float* bias,
                      cudaStream_t st, int half)
{
    const int M = Bn * S_;
    __half* xln = c.xln + (size_t)half * NB * S_ * D_;
    __half* qkv = c.qkv + (size_t)half * NB * S_ * QKV3;
    __half* att = c.att + (size_t)half * NB * S_ * D_;
    __half* ffh = c.ffh + (size_t)half * NB * S_ * FF_;

    ln_kernel<__half><<<M, 256, 0, st>>>(x, D_, xln, D_,
                                  c.ln1g + layer * D_, c.ln1b + layer * D_, M);
    run_gemm(xln, c.Wqkv + (size_t)layer * QKV3 * D_, c.bqkv + layer * QKV3,
             nullptr, qkv, M, QKV3, D_, 1, st);
    attn_tc<<<dim3(H_, Bn), 256, ATT_SMEM, st>>>(qkv, bias, att);
    run_gemm(att, c.Wo + (size_t)layer * D_ * D_, c.bo + layer * D_,
             x, x, M, D_, D_, 0, st);
    ln_kernel<__half><<<M, 256, 0, st>>>(x, D_, xln, D_,
                                  c.ln2g + layer * D_, c.ln2b + layer * D_, M);
    run_gemm(xln, c.Wfc + (size_t)layer * FF_ * D_, c.bfc + layer * FF_,
             nullptr, ffh, M, FF_, D_, 1 | 2, st);
    run_gemm(ffh, c.Wp + (size_t)layer * D_ * FF_, c.bp + layer * D_,
             x, x, M, D_, FF_, 0, st);
}

extern "C" void kernel_launch(void* const* d_in, const int* in_sizes, int n_in,
                              void* d_out, int out_size)
{
    const float* masked   = (const float*)d_in[0];
    const float* prompted = (const float*)d_in[1];
    const float* pred     = (const float*)d_in[2];
    const float* conv_w   = (const float*)d_in[3];
    const float* cls_emb  = (const float*)d_in[4];
    const float* pos_emb  = (const float*)d_in[5];
    const float* lnpre_g  = (const float*)d_in[6];
    const float* lnpre_b  = (const float*)d_in[7];

    const float* Wqkv_raw = (const float*)d_in[8];
    const float* bqkv     = (const float*)d_in[9];
    const float* Wo_raw   = (const float*)d_in[10];
    const float* bo       = (const float*)d_in[11];
    const float* ln1g     = (const float*)d_in[12];
    const float* ln1b     = (const float*)d_in[13];
    const float* ln2g     = (const float*)d_in[14];
    const float* ln2b     = (const float*)d_in[15];
    const float* Wfc_raw  = (const float*)d_in[16];
    const float* bfc      = (const float*)d_in[17];
    const float* Wp_raw   = (const float*)d_in[18];
    const float* bp       = (const float*)d_in[19];
    const float* lnpost_g = (const float*)d_in[20];
    const float* lnpost_b = (const float*)d_in[21];
    const float* proj     = (const float*)d_in[22];
    float* out = (float*)d_out;

    // one-time stream/event creation (host resources only; no device memory)
    static cudaStream_t s2 = nullptr;
    static cudaEvent_t ev[8];
    if (!s2) {
        cudaStreamCreateWithFlags(&s2, cudaStreamNonBlocking);
        for (int i = 0; i < 8; i++)
            cudaEventCreateWithFlags(&ev[i], cudaEventDisableTiming);
    }
    cudaStream_t s0 = 0;   // capture (default) stream

    Ctx c;
    c.x12  = symaddr_t<float>(g_x12);
    c.xln  = symaddr_t<__half>(g_xln);
    c.qkv  = symaddr_t<__half>(g_qkv);
    c.att  = symaddr_t<__half>(g_att);
    c.ffh  = symaddr_t<__half>(g_ffh);
    c.col  = symaddr_t<__half>(g_im2col);
    c.clsb = symaddr_t<float>(g_clsb);
    c.cls  = symaddr_t<float>(g_cls);

    __half* wqkv = symaddr_t<__half>(g_wqkv);
    __half* wo   = symaddr_t<__half>(g_wo);
    __half* wfc  = symaddr_t<__half>(g_wfc);
    __half* wp   = symaddr_t<__half>(g_wp);
    __half* wcv  = symaddr_t<__half>(g_wcv);

    c.Wqkv = wqkv; c.bqkv = bqkv;
    c.Wo   = wo;   c.bo   = bo;
    c.ln1g = ln1g; c.ln1b = ln1b;
    c.ln2g = ln2g; c.ln2b = ln2b;
    c.Wfc  = wfc;  c.bfc  = bfc;
    c.Wp   = wp;   c.bp   = bp;

    cudaFuncSetAttribute(attn_tc, cudaFuncAttributeMaxDynamicSharedMemorySize,
                         ATT_SMEM);
    cudaFuncSetAttribute(gemm_h, cudaFuncAttributeMaxDynamicSharedMemorySize,
                         GEMM_SMEM);

    // ---- fork: weight conversion on s2, im2col on s0 ----
    cudaEventRecord(ev[0], s0);
    cudaStreamWaitEvent(s2, ev[0], 0);

    run_cvt(conv_w, wcv, (long)D_ * D_, s2);
    cudaEventRecord(ev[1], s2);                  // conv weights ready
    run_cvt(Wqkv_raw, wqkv, (long)LAYERS_ * QKV3 * D_, s2);
    run_cvt(Wo_raw,   wo,   (long)LAYERS_ * D_ * D_, s2);
    run_cvt(Wfc_raw,  wfc,  (long)LAYERS_ * FF_ * D_, s2);
    run_cvt(Wp_raw,   wp,   (long)LAYERS_ * D_ * FF_, s2);
    cudaEventRecord(ev[2], s2);                  // all weights ready

    {
        const int total = B2 * L_ * D_;
        im2col_kernel<<<(total + 255) / 256, 256, 0, s0>>>(masked, prompted, c.col);
        clsbias_kernel<<<(NB * L_ + 255) / 256, 256, 0, s0>>>(pred, c.clsb);
        cudaStreamWaitEvent(s0, ev[1], 0);       // need wcv
        run_gemm(c.col, wcv, nullptr, nullptr, c.att, B2 * L_, D_, D_, 1, s0);
        const int tot2 = B2 * S_ * D_;
        embed_kernel<<<(tot2 + 255) / 256, 256, 0, s0>>>(c.att, cls_emb, pos_emb, c.x12);
        ln_kernel<float><<<B2 * S_, 256, 0, s0>>>(c.x12, D_, c.x12, D_,
                                                  lnpre_g, lnpre_b, B2 * S_);
    }
    cudaStreamWaitEvent(s0, ev[2], 0);           // need all weights before layer 0

    for (int i = 0; i < 10; i++)
        run_block(c, c.x12, B2, i, nullptr, s0, 0);

    // ---- masking phase: overlap x-path (s0) and x2-path (s2) ----
    float* x  = c.x12;
    float* x2 = c.x12 + (size_t)NB * S_ * D_;
    const int layers2[2] = {10, 11};
    for (int t = 0; t < 2; t++) {
        int i = layers2[t];
        const int tot = NB * S_ * D_;
        mask_combine_kernel<<<(tot + 255) / 256, 256, 0, s0>>>(x, x2, pred);
        cudaEventRecord(ev[3 + 2 * t], s0);
        cudaStreamWaitEvent(s2, ev[3 + 2 * t], 0);
        run_block(c, x,  NB, i, nullptr, s0, 0);
        run_block(c, x2, NB, i, c.clsb,  s2, 1);
        cudaEventRecord(ev[4 + 2 * t], s2);
        cudaStreamWaitEvent(s0, ev[4 + 2 * t], 0);
    }

    ln_kernel<float><<<NB, 256, 0, s0>>>(x, (long)S_ * D_, c.cls, D_,
                                         lnpost_g, lnpost_b, NB);
    proj_out_kernel<<<dim3((OUT_ + 255) / 256, NB), 256, 0, s0>>>(c.cls, proj, out);

    (void)in_sizes; (void)n_in; (void)out_size;
}

// round 12
// speedup vs baseline: 6.9892x; 1.0084x over previous
#include <cuda_runtime.h>
#include <cuda_fp16.h>
#include <math.h>
#include <stdint.h>

// ---------------- Problem constants ----------------
#define D_    768
#define H_    12
#define HD_   64
#define S_    197
#define L_    196
#define NB    16          // batch per image set
#define B2    32          // both image sets
#define FF_   3072
#define OUT_  512
#define QKV3  2304
#define IMG_  224
#define GRID_ 14
#define PCH_  16
#define LAYERS_ 12

// ---------------- Scratch (device globals; no allocation allowed) ----------------
__device__ float  g_x12[B2 * S_ * D_];      // residual stream (fp32)
__device__ __half g_xln[B2 * S_ * D_];      // LN output (fp16)
__device__ __half g_qkv[B2 * S_ * QKV3];    // qkv (fp16, feeds TC attention)
__device__ __half g_att[B2 * S_ * D_];      // attention out / conv_out temp (fp16)
__device__ __half g_ffh[B2 * S_ * FF_];     // MLP hidden (fp16)
__device__ __half g_im2col[B2 * L_ * D_];   // patch im2col (fp16)
__device__ float  g_clsb[NB * L_];          // cls-row attention bias
__device__ float  g_cls[NB * D_];           // ln_post output (fp32)

// fp16 weight copies (B operands, [N,K] row-major)
__device__ __half g_wqkv[LAYERS_ * QKV3 * D_];
__device__ __half g_wo  [LAYERS_ * D_ * D_];
__device__ __half g_wfc [LAYERS_ * FF_ * D_];
__device__ __half g_wp  [LAYERS_ * D_ * FF_];
__device__ __half g_wcv [D_ * D_];

// ---- weight fp32 -> fp16 conversion (once per launch) ----
__global__ void cvt_half_kernel(const float4* __restrict__ in,
                                uint2* __restrict__ out, int n4)
{
    for (int i = blockIdx.x * 256 + threadIdx.x; i < n4; i += gridDim.x * 256) {
        float4 v = in[i];
        __half2 h0 = __floats2half2_rn(v.x, v.y);
        __half2 h1 = __floats2half2_rn(v.z, v.w);
        uint2 o;
        o.x = *(uint32_t*)&h0;
        o.y = *(uint32_t*)&h1;
        out[i] = o;
    }
}

// ---------------- MMA / LDSM macros ----------------
#define LDSM4(r0, r1, r2, r3, addr)                                    \
    asm volatile("ldmatrix.sync.aligned.m8n8.x4.shared.b16 "           \
                 "{%0,%1,%2,%3}, [%4];"                                \
                 : "=r"(r0), "=r"(r1), "=r"(r2), "=r"(r3) : "r"(addr))

#define LDSM4T(r0, r1, r2, r3, addr)                                   \
    asm volatile("ldmatrix.sync.aligned.m8n8.x4.trans.shared.b16 "     \
                 "{%0,%1,%2,%3}, [%4];"                                \
                 : "=r"(r0), "=r"(r1), "=r"(r2), "=r"(r3) : "r"(addr))

#define MMA_F16(d, a, b)                                               \
    asm volatile(                                                      \
        "mma.sync.aligned.m16n8k16.row.col.f32.f16.f16.f32 "           \
        "{%0,%1,%2,%3}, {%4,%5,%6,%7}, {%8,%9}, {%0,%1,%2,%3};"        \
        : "+f"((d)[0]), "+f"((d)[1]), "+f"((d)[2]), "+f"((d)[3])       \
        : "r"((a)[0]), "r"((a)[1]), "r"((a)[2]), "r"((a)[3]),          \
          "r"((b)[0]), "r"((b)[1]))

__device__ __forceinline__ uint32_t packh2(float lo, float hi) {
    __half2 h = __floats2half2_rn(lo, hi);
    return *(uint32_t*)&h;
}

// ======================================================================
// FP16 tensor-core GEMM (mma.sync):
//   C[M,N] = act( A[M,K]h @ B[N,K]h^T + bias[N] ) (+ resid[M,N])
// 128x128x64 block tile, 256 threads (8 warps 4x2), warp tile 32x64.
// flags: bit0 = half output, bit1 = GELU.
// ======================================================================
#define HBK   64
#define HST   16384

__global__ __launch_bounds__(256, 2) void gemm_h(
    const __half* __restrict__ A, const __half* __restrict__ B,
    const float* __restrict__ bias, const float* __restrict__ resid,
    void* __restrict__ Cv, int M, int N, int K, int flags)
{
    extern __shared__ char smb[];

    const int tid  = threadIdx.x;
    const int lane = tid & 31, wid = tid >> 5;
    const int wm = wid & 3, wn = wid >> 2;
    const int grp = lane >> 2, qid = lane & 3;
    const int bm = blockIdx.y * 128, bn = blockIdx.x * 128;

    const uint32_t smemBase = (uint32_t)__cvta_generic_to_shared(smb);

    const int lr0 = tid >> 3;
    const int lc  = tid & 7;

    float acc[2][8][4];
    #pragma unroll
    for (int mf = 0; mf < 2; mf++)
        #pragma unroll
        for (int nf = 0; nf < 8; nf++)
            #pragma unroll
            for (int r = 0; r < 4; r++) acc[mf][nf][r] = 0.f;

    const int niter = K / HBK;

    auto issue = [&](int it, int st) {
        const int k0 = it * HBK;
        #pragma unroll
        for (int i = 0; i < 4; i++) {
            const int row = lr0 + i * 32;
            const uint32_t xoff = (uint32_t)(row * 128 + ((lc ^ (row & 7)) * 16));
            {
                int gr = bm + row;
                int ok = (gr < M);
                const __half* src = A + (size_t)(ok ? gr : (M - 1)) * K + k0 + lc * 8;
                uint32_t dst = smemBase + st * HST + xoff;
                int sz = ok ? 16 : 0;
                asm volatile("cp.async.cg.shared.global [%0], [%1], 16, %2;"
                             :: "r"(dst), "l"(src), "r"(sz));
            }
            {
                const __half* src = B + (size_t)(bn + row) * K + k0 + lc * 8;
                uint32_t dst = smemBase + 2 * HST + st * HST + xoff;
                asm volatile("cp.async.cg.shared.global [%0], [%1], 16;"
                             :: "r"(dst), "l"(src));
            }
        }
        asm volatile("cp.async.commit_group;");
    };

    issue(0, 0);
    int stage = 0;

    const int aRowIn = lane & 15;
    const int aKHalf = lane >> 4;
    const int bMat   = lane >> 3;
    const int bRowIn = (lane & 7) + ((bMat >> 1) << 3);
    const int bKHalf = bMat & 1;

    for (int it = 0; it < niter; it++) {
        if (it + 1 < niter) {
            issue(it + 1, stage ^ 1);
            asm volatile("cp.async.wait_group 1;");
        } else {
            asm volatile("cp.async.wait_group 0;");
        }
        __syncthreads();

        const uint32_t aStage = smemBase + stage * HST;
        const uint32_t bStage = smemBase + 2 * HST + stage * HST;

        #pragma unroll
        for (int ks = 0; ks < HBK; ks += 16) {
            const int kc = ks >> 3;
            uint32_t a[2][4], b[16];
            #pragma unroll
            for (int mf = 0; mf < 2; mf++) {
                const int row = wm * 32 + mf * 16 + aRowIn;
                const int ch  = (kc + aKHalf) ^ (row & 7);
                LDSM4(a[mf][0], a[mf][1], a[mf][2], a[mf][3],
                      aStage + (uint32_t)(row * 128 + ch * 16));
            }
            #pragma unroll
            for (int np = 0; np < 4; np++) {
                const int row = wn * 64 + np * 16 + bRowIn;
                const int ch  = (kc + bKHalf) ^ (row & 7);
                LDSM4(b[np * 4 + 0], b[np * 4 + 1], b[np * 4 + 2], b[np * 4 + 3],
                      bStage + (uint32_t)(row * 128 + ch * 16));
            }
            #pragma unroll
            for (int mf = 0; mf < 2; mf++)
                #pragma unroll
                for (int np = 0; np < 4; np++) {
                    MMA_F16(acc[mf][np * 2 + 0], a[mf], &b[np * 4 + 0]);
                    MMA_F16(acc[mf][np * 2 + 1], a[mf], &b[np * 4 + 2]);
                }
        }
        __syncthreads();
        stage ^= 1;
    }

    const int halfOut = flags & 1;
    const int act     = flags & 2;
    float* Cf = (float*)Cv;
    __half* Ch = (__half*)Cv;

    #pragma unroll
    for (int mf = 0; mf < 2; mf++) {
        #pragma unroll
        for (int hh = 0; hh < 2; hh++) {
            const int gm = bm + wm * 32 + mf * 16 + grp + hh * 8;
            if (gm >= M) continue;
            #pragma unroll
            for (int nf = 0; nf < 8; nf++) {
                const int gn = bn + wn * 64 + nf * 8 + 2 * qid;
                float v0 = acc[mf][nf][hh * 2 + 0];
                float v1 = acc[mf][nf][hh * 2 + 1];
                if (bias) { v0 += bias[gn]; v1 += bias[gn + 1]; }
                if (act) {
                    v0 = v0 / (1.f + expf(-1.702f * v0));
                    v1 = v1 / (1.f + expf(-1.702f * v1));
                }
                if (resid) {
                    const float* rp = resid + (size_t)gm * N + gn;
                    v0 += rp[0]; v1 += rp[1];
                }
                if (halfOut) {
                    __half2 h = __floats2half2_rn(v0, v1);
                    *(__half2*)(Ch + (size_t)gm * N + gn) = h;
                } else {
                    float2 o; o.x = v0; o.y = v1;
                    *(float2*)(Cf + (size_t)gm * N + gn) = o;
                }
            }
        }
    }
}

// ======================================================================
// Tensor-core attention (mma.sync). One block per (head, batch), 8 warps.
// cls bias applies only to batches b >= bias_base (row b - bias_base).
// ======================================================================
#define SATT   224
#define ATT_MAT 28672
#define ATT_SMEM (3 * ATT_MAT)

__global__ __launch_bounds__(256) void attn_tc(
    const __half* __restrict__ qkv, const float* __restrict__ clsbias,
    int bias_base, __half* __restrict__ out)
{
    extern __shared__ char smb[];
    const int h = blockIdx.x, b = blockIdx.y;
    const int tid = threadIdx.x;
    const int lane = tid & 31, wid = tid >> 5;
    const uint32_t base = (uint32_t)__cvta_generic_to_shared(smb);

    for (int i = tid; i < S_ * 24; i += 256) {
        int s = i / 24, rem = i % 24;
        int m3 = rem >> 3, c = rem & 7;
        const uint4 v = *(const uint4*)(qkv + ((size_t)(b * S_ + s)) * QKV3
                                        + m3 * D_ + h * HD_ + c * 8);
        uint4 w = v;
        if (m3 == 0) {
            const __half2 sc = __floats2half2_rn(0.125f, 0.125f);
            __half2* hp = (__half2*)&w;
            hp[0] = __hmul2(hp[0], sc); hp[1] = __hmul2(hp[1], sc);
            hp[2] = __hmul2(hp[2], sc); hp[3] = __hmul2(hp[3], sc);
        }
        *(uint4*)(smb + m3 * ATT_MAT + s * 128 + ((c ^ (s & 7)) * 16)) = w;
    }
    for (int i = tid; i < (SATT - S_) * 24; i += 256) {
        int r = S_ + i / 24, rem = i % 24;
        int m3 = rem >> 3, c = rem & 7;
        *(uint4*)(smb + m3 * ATT_MAT + r * 128 + ((c ^ (r & 7)) * 16)) =
            make_uint4(0, 0, 0, 0);
    }
    __syncthreads();

    const int grp = lane >> 2, qid = lane & 3;
    const int aRow = lane & 15, aK = lane >> 4;
    const int bRow = (lane & 7) + ((lane >> 4) << 3);
    const int bK   = (lane >> 3) & 1;
    const int vRow = (lane & 7) + (((lane >> 3) & 1) << 3);
    const int vC   = lane >> 4;

    const bool hasBias = (clsbias != nullptr) && (b >= bias_base);
    const float* biasRow = hasBias ? (clsbias + (size_t)(b - bias_base) * L_)
                                   : nullptr;

    for (int chunk = wid; chunk < 13; chunk += 8) {
        const int mbase = chunk * 16;

        float sc[28][4];
        #pragma unroll
        for (int j = 0; j < 28; j++)
            #pragma unroll
            for (int e = 0; e < 4; e++) sc[j][e] = 0.f;

        #pragma unroll
        for (int t = 0; t < 4; t++) {
            uint32_t a[4];
            const int ar = mbase + aRow;
            LDSM4(a[0], a[1], a[2], a[3],
                  base + (uint32_t)(ar * 128 + (((2 * t + aK) ^ (ar & 7)) * 16)));
            #pragma unroll
            for (int np = 0; np < 14; np++) {
                uint32_t bb[4];
                const int br = np * 16 + bRow;
                LDSM4(bb[0], bb[1], bb[2], bb[3],
                      base + (uint32_t)(ATT_MAT + br * 128
                                        + (((2 * t + bK) ^ (br & 7)) * 16)));
                MMA_F16(sc[np * 2 + 0], a, &bb[0]);
                MMA_F16(sc[np * 2 + 1], a, &bb[2]);
            }
        }

        const bool dobias = hasBias && (mbase == 0) && (grp == 0);
        float m0 = -1e30f, m1 = -1e30f;
        #pragma unroll
        for (int j = 0; j < 28; j++) {
            const int col = j * 8 + 2 * qid;
            if (dobias) {
                if (col >= 1 && col < S_)     sc[j][0] += biasRow[col - 1];
                if (col + 1 < S_)             sc[j][1] += biasRow[col];
            }
            if (col >= S_)     { sc[j][0] = -1e30f; sc[j][2] = -1e30f; }
            if (col + 1 >= S_) { sc[j][1] = -1e30f; sc[j][3] = -1e30f; }
            m0 = fmaxf(m0, fmaxf(sc[j][0], sc[j][1]));
            m1 = fmaxf(m1, fmaxf(sc[j][2], sc[j][3]));
        }
        m0 = fmaxf(m0, __shfl_xor_sync(0xffffffffu, m0, 1));
        m0 = fmaxf(m0, __shfl_xor_sync(0xffffffffu, m0, 2));
        m1 = fmaxf(m1, __shfl_xor_sync(0xffffffffu, m1, 1));
        m1 = fmaxf(m1, __shfl_xor_sync(0xffffffffu, m1, 2));

        float s0 = 0.f, s1 = 0.f;
        #pragma unroll
        for (int j = 0; j < 28; j++) {
            sc[j][0] = __expf(sc[j][0] - m0);
            sc[j][1] = __expf(sc[j][1] - m0);
            sc[j][2] = __expf(sc[j][2] - m1);
            sc[j][3] = __expf(sc[j][3] - m1);
            s0 += sc[j][0] + sc[j][1];
            s1 += sc[j][2] + sc[j][3];
        }
        s0 += __shfl_xor_sync(0xffffffffu, s0, 1);
        s0 += __shfl_xor_sync(0xffffffffu, s0, 2);
        s1 += __shfl_xor_sync(0xffffffffu, s1, 1);
        s1 += __shfl_xor_sync(0xffffffffu, s1, 2);

        float ov[8][4];
        #pragma unroll
        for (int j = 0; j < 8; j++)
            #pragma unroll
            for (int e = 0; e < 4; e++) ov[j][e] = 0.f;

        #pragma unroll
        for (int t = 0; t < 14; t++) {
            uint32_t a[4];
            a[0] = packh2(sc[2 * t][0],     sc[2 * t][1]);
            a[1] = packh2(sc[2 * t][2],     sc[2 * t][3]);
            a[2] = packh2(sc[2 * t + 1][0], sc[2 * t + 1][1]);
            a[3] = packh2(sc[2 * t + 1][2], sc[2 * t + 1][3]);
            const int vr = t * 16 + vRow;
            #pragma unroll
            for (int np = 0; np < 4; np++) {
                uint32_t vv[4];
                const int vc = 2 * np + vC;
                LDSM4T(vv[0], vv[1], vv[2], vv[3],
                       base + (uint32_t)(2 * ATT_MAT + vr * 128
                                         + ((vc ^ (vr & 7)) * 16)));
                MMA_F16(ov[np * 2 + 0], a, &vv[0]);
                MMA_F16(ov[np * 2 + 1], a, &vv[2]);
            }
        }

        const float inv0 = 1.f / s0, inv1 = 1.f / s1;
        const int q0 = mbase + grp, q1 = q0 + 8;
        #pragma unroll
        for (int j = 0; j < 8; j++) {
            const int col = h * HD_ + j * 8 + 2 * qid;
            if (q0 < S_) {
                __half2 o = __floats2half2_rn(ov[j][0] * inv0, ov[j][1] * inv0);
                *(__half2*)(out + (size_t)(b * S_ + q0) * D_ + col) = o;
            }
            if (q1 < S_) {
                __half2 o = __floats2half2_rn(ov[j][2] * inv1, ov[j][3] * inv1);
                *(__half2*)(out + (size_t)(b * S_ + q1) * D_ + col) = o;
            }
        }
    }
}

// ======================================================================
// LayerNorm: warp-per-row (8 rows / 256-thr block), float4 IO, pure
// shuffle reductions — no smem, no __syncthreads.
// ======================================================================
__device__ __forceinline__ void ln_store(float* yr, int idx, float4 o) {
    ((float4*)yr)[idx] = o;
}
__device__ __forceinline__ void ln_store(__half* yr, int idx, float4 o) {
    __half2 h0 = __floats2half2_rn(o.x, o.y);
    __half2 h1 = __floats2half2_rn(o.z, o.w);
    uint2 u; u.x = *(uint32_t*)&h0; u.y = *(uint32_t*)&h1;
    ((uint2*)yr)[idx] = u;
}

template <typename TO>
__global__ __launch_bounds__(256) void ln_kernel(
    const float* __restrict__ x, long in_stride,
    TO* __restrict__ y, long out_stride,
    const float* __restrict__ g, const float* __restrict__ b, int rows)
{
    const int wid = threadIdx.x >> 5, lane = threadIdx.x & 31;
    const int r = blockIdx.x * 8 + wid;
    if (r >= rows) return;

    const float4* xr = (const float4*)(x + (size_t)r * in_stride);
    TO* yr = y + (size_t)r * out_stride;

    float4 v[6];
    float s = 0.f;
    #pragma unroll
    for (int i = 0; i < 6; i++) {
        v[i] = xr[lane + 32 * i];
        s += (v[i].x + v[i].y) + (v[i].z + v[i].w);
    }
    #pragma unroll
    for (int o = 16; o > 0; o >>= 1) s += __shfl_xor_sync(0xffffffffu, s, o);
    const float mu = s * (1.f / 768.f);

    float ss = 0.f;
    #pragma unroll
    for (int i = 0; i < 6; i++) {
        v[i].x -= mu; v[i].y -= mu; v[i].z -= mu; v[i].w -= mu;
        ss += v[i].x * v[i].x + v[i].y * v[i].y
            + v[i].z * v[i].z + v[i].w * v[i].w;
    }
    #pragma unroll
    for (int o = 16; o > 0; o >>= 1) ss += __shfl_xor_sync(0xffffffffu, ss, o);
    const float rs = rsqrtf(ss * (1.f / 768.f) + 1e-5f);

    const float4* g4 = (const float4*)g;
    const float4* b4 = (const float4*)b;
    #pragma unroll
    for (int i = 0; i < 6; i++) {
        const float4 gg = g4[lane + 32 * i];
        const float4 bb = b4[lane + 32 * i];
        float4 o;
        o.x = v[i].x * rs * gg.x + bb.x;
        o.y = v[i].y * rs * gg.y + bb.y;
        o.z = v[i].z * rs * gg.z + bb.z;
        o.w = v[i].w * rs * gg.w + bb.w;
        ln_store(yr, lane + 32 * i, o);
    }
}

// ======================================================================
// Patch embed helpers
// ======================================================================
__global__ void im2col_kernel(const float* __restrict__ masked,
                              const float* __restrict__ prompted,
                              __half* __restrict__ col)
{
    int idx = blockIdx.x * 256 + threadIdx.x;
    const int total = B2 * L_ * D_;
    if (idx >= total) return;
    int k = idx % D_;
    int m = idx / D_;
    int b = m / L_, l = m % L_;
    int gy = l / GRID_, gx = l % GRID_;
    int c = k >> 8, rem = k & 255;
    int py = rem >> 4, px = rem & 15;
    const float* src = (b < NB) ? (masked + (size_t)b * 3 * IMG_ * IMG_)
                                : (prompted + (size_t)(b - NB) * 3 * IMG_ * IMG_);
    col[idx] = __float2half_rn(
        src[((size_t)c * IMG_ + gy * PCH_ + py) * IMG_ + gx * PCH_ + px]);
}

__global__ void embed_kernel(const __half* __restrict__ conv_out,
                             const float* __restrict__ cls_emb,
                             const float* __restrict__ pos,
                             float* __restrict__ x)
{
    int idx = blockIdx.x * 256 + threadIdx.x;
    const int total = B2 * S_ * D_;
    if (idx >= total) return;
    int d = idx % D_;
    int bs = idx / D_;
    int s = bs % S_, b = bs / S_;
    float v = (s == 0) ? cls_emb[d]
                       : __half2float(conv_out[((size_t)b * L_ + (s - 1)) * D_ + d]);
    x[idx] = v + pos[s * D_ + d];
}

__global__ void clsbias_kernel(const float* __restrict__ pm, float* __restrict__ cb)
{
    int i = blockIdx.x * 256 + threadIdx.x;
    if (i < NB * L_) cb[i] = (pm[i] != 0.f) ? 0.f : -1e30f;
}

__global__ void mask_combine_kernel(float* __restrict__ x, const float* __restrict__ x2,
                                    const float* __restrict__ pm)
{
    int idx = blockIdx.x * 256 + threadIdx.x;
    const int total = NB * S_ * D_;
    if (idx >= total) return;
    int bs = idx / D_;
    int s = bs % S_;
    int b = bs / S_;
    float mf = (s == 0) ? 1.f : pm[b * L_ + (s - 1)];
    x[idx] = 2.f * x2[idx] * mf + x[idx];
}

__global__ void proj_out_kernel(const float* __restrict__ cls,
                                const float* __restrict__ proj,
                                float* __restrict__ out)
{
    int n = blockIdx.x * 256 + threadIdx.x;
    int m = blockIdx.y;
    if (n >= OUT_) return;
    float s = 0.f;
    #pragma unroll 4
    for (int k = 0; k < D_; k++) s += cls[m * D_ + k] * proj[(size_t)k * OUT_ + n];
    out[m * OUT_ + n] = s;
}

// ======================================================================
// Host orchestration
// ======================================================================
template <typename T>
static T* symaddr_t(const void* s) {
    void* p = nullptr;
    cudaGetSymbolAddress(&p, s);
    return (T*)p;
}

#define GEMM_SMEM (4 * HST)   // 65,536 B

static void run_gemm(const __half* A, const __half* B, const float* bias,
                     const float* resid, void* C, int M, int N, int K, int flags,
                     cudaStream_t st)
{
    dim3 grid(N / 128, (M + 127) / 128);
    gemm_h<<<grid, 256, GEMM_SMEM, st>>>(A, B, bias, resid, C, M, N, K, flags);
}

static void run_cvt(const float* in, __half* out, long n, cudaStream_t st)
{
    int n4 = (int)(n / 4);
    int blocks = (n4 + 255) / 256;
    if (blocks > 16384) blocks = 16384;
    cvt_half_kernel<<<blocks, 256, 0, st>>>((const float4*)in, (uint2*)out, n4);
}

struct Ctx {
    float *x12, *clsb, *cls;
    __half *xln, *qkv, *att, *ffh, *col;
    const __half *Wqkv, *Wo, *Wfc, *Wp;
    const float *bqkv, *bo, *ln1g, *ln1b, *ln2g, *ln2b, *bfc, *bp;
};

static void run_block(const Ctx& c, float* x, int Bn, int layer,
                      const float* bias, int bias_base, cudaStream_t st)
{
    const int M = Bn * S_;
    const int lgrid = (M + 7) / 8;
    ln_kernel<__half><<<lgrid, 256, 0, st>>>(x, D_, c.xln, D_,
                                  c.ln1g + layer * D_, c.ln1b + layer * D_, M);
    run_gemm(c.xln, c.Wqkv + (size_t)layer * QKV3 * D_, c.bqkv + layer * QKV3,
             nullptr, c.qkv, M, QKV3, D_, 1, st);
    attn_tc<<<dim3(H_, Bn), 256, ATT_SMEM, st>>>(c.qkv, bias, bias_base, c.att);
    run_gemm(c.att, c.Wo + (size_t)layer * D_ * D_, c.bo + layer * D_,
             x, x, M, D_, D_, 0, st);
    ln_kernel<__half><<<lgrid, 256, 0, st>>>(x, D_, c.xln, D_,
                                  c.ln2g + layer * D_, c.ln2b + layer * D_, M);
    run_gemm(c.xln, c.Wfc + (size_t)layer * FF_ * D_, c.bfc + layer * FF_,
             nullptr, c.ffh, M, FF_, D_, 1 | 2, st);
    run_gemm(c.ffh, c.Wp + (size_t)layer * D_ * FF_, c.bp + layer * D_,
             x, x, M, D_, FF_, 0, st);
}

extern "C" void kernel_launch(void* const* d_in, const int* in_sizes, int n_in,
                              void* d_out, int out_size)
{
    const float* masked   = (const float*)d_in[0];
    const float* prompted = (const float*)d_in[1];
    const float* pred     = (const float*)d_in[2];
    const float* conv_w   = (const float*)d_in[3];
    const float* cls_emb  = (const float*)d_in[4];
    const float* pos_emb  = (const float*)d_in[5];
    const float* lnpre_g  = (const float*)d_in[6];
    const float* lnpre_b  = (const float*)d_in[7];

    const float* Wqkv_raw = (const float*)d_in[8];
    const float* bqkv     = (const float*)d_in[9];
    const float* Wo_raw   = (const float*)d_in[10];
    const float* bo       = (const float*)d_in[11];
    const float* ln1g     = (const float*)d_in[12];
    const float* ln1b     = (const float*)d_in[13];
    const float* ln2g     = (const float*)d_in[14];
    const float* ln2b     = (const float*)d_in[15];
    const float* Wfc_raw  = (const float*)d_in[16];
    const float* bfc      = (const float*)d_in[17];
    const float* Wp_raw   = (const float*)d_in[18];
    const float* bp       = (const float*)d_in[19];
    const float* lnpost_g = (const float*)d_in[20];
    const float* lnpost_b = (const float*)d_in[21];
    const float* proj     = (const float*)d_in[22];
    float* out = (float*)d_out;

    // one-time stream/event creation (host resources only; no device memory)
    static cudaStream_t s2 = nullptr;
    static cudaEvent_t ev[3];
    if (!s2) {
        cudaStreamCreateWithFlags(&s2, cudaStreamNonBlocking);
        for (int i = 0; i < 3; i++)
            cudaEventCreateWithFlags(&ev[i], cudaEventDisableTiming);
    }
    cudaStream_t s0 = 0;   // capture (default) stream

    Ctx c;
    c.x12  = symaddr_t<float>(g_x12);
    c.xln  = symaddr_t<__half>(g_xln);
    c.qkv  = symaddr_t<__half>(g_qkv);
    c.att  = symaddr_t<__half>(g_att);
    c.ffh  = symaddr_t<__half>(g_ffh);
    c.col  = symaddr_t<__half>(g_im2col);
    c.clsb = symaddr_t<float>(g_clsb);
    c.cls  = symaddr_t<float>(g_cls);

    __half* wqkv = symaddr_t<__half>(g_wqkv);
    __half* wo   = symaddr_t<__half>(g_wo);
    __half* wfc  = symaddr_t<__half>(g_wfc);
    __half* wp   = symaddr_t<__half>(g_wp);
    __half* wcv  = symaddr_t<__half>(g_wcv);

    c.Wqkv = wqkv; c.bqkv = bqkv;
    c.Wo   = wo;   c.bo   = bo;
    c.ln1g = ln1g; c.ln1b = ln1b;
    c.ln2g = ln2g; c.ln2b = ln2b;
    c.Wfc  = wfc;  c.bfc  = bfc;
    c.Wp   = wp;   c.bp   = bp;

    cudaFuncSetAttribute(attn_tc, cudaFuncAttributeMaxDynamicSharedMemorySize,
                         ATT_SMEM);
    cudaFuncSetAttribute(gemm_h, cudaFuncAttributeMaxDynamicSharedMemorySize,
                         GEMM_SMEM);

    // ---- fork: weight conversion on s2, im2col/embed on s0 ----
    cudaEventRecord(ev[0], s0);
    cudaStreamWaitEvent(s2, ev[0], 0);

    run_cvt(conv_w, wcv, (long)D_ * D_, s2);
    cudaEventRecord(ev[1], s2);                  // conv weights ready
    run_cvt(Wqkv_raw, wqkv, (long)LAYERS_ * QKV3 * D_, s2);
    run_cvt(Wo_raw,   wo,   (long)LAYERS_ * D_ * D_, s2);
    run_cvt(Wfc_raw,  wfc,  (long)LAYERS_ * FF_ * D_, s2);
    run_cvt(Wp_raw,   wp,   (long)LAYERS_ * D_ * FF_, s2);
    cudaEventRecord(ev[2], s2);                  // all weights ready

    {
        const int total = B2 * L_ * D_;
        im2col_kernel<<<(total + 255) / 256, 256, 0, s0>>>(masked, prompted, c.col);
        clsbias_kernel<<<(NB * L_ + 255) / 256, 256, 0, s0>>>(pred, c.clsb);
        cudaStreamWaitEvent(s0, ev[1], 0);       // need wcv
        run_gemm(c.col, wcv, nullptr, nullptr, c.att, B2 * L_, D_, D_, 1, s0);
        const int tot2 = B2 * S_ * D_;
        embed_kernel<<<(tot2 + 255) / 256, 256, 0, s0>>>(c.att, cls_emb, pos_emb, c.x12);
        ln_kernel<float><<<(B2 * S_ + 7) / 8, 256, 0, s0>>>(
            c.x12, D_, c.x12, D_, lnpre_g, lnpre_b, B2 * S_);
    }
    cudaStreamWaitEvent(s0, ev[2], 0);           // need all weights before layer 0

    for (int i = 0; i < 10; i++)
        run_block(c, c.x12, B2, i, nullptr, 0, s0);

    // ---- masking phase: single merged block per layer over [x | x2] ----
    // x-path (batches 0..15): mask_combine then standard block, no bias.
    // x2-path (batches 16..31): standard block with cls bias (row b-16).
    float* x  = c.x12;
    float* x2 = c.x12 + (size_t)NB * S_ * D_;
    const int layers2[2] = {10, 11};
    for (int t = 0; t < 2; t++) {
        int i = layers2[t];
        const int tot = NB * S_ * D_;
        mask_combine_kernel<<<(tot + 255) / 256, 256, 0, s0>>>(x, x2, pred);
        run_block(c, c.x12, B2, i, c.clsb, NB, s0);
    }

    ln_kernel<float><<<(NB + 7) / 8, 256, 0, s0>>>(x, (long)S_ * D_, c.cls, D_,
                                                   lnpost_g, lnpost_b, NB);
    proj_out_kernel<<<dim3((OUT_ + 255) / 256, NB), 256, 0, s0>>>(c.cls, proj, out);

    (void)in_sizes; (void)n_in; (void)out_size;
}

// round 13
// speedup vs baseline: 7.1538x; 1.0235x over previous
#include <cuda_runtime.h>
#include <cuda_fp16.h>
#include <math.h>
#include <stdint.h>

// ---------------- Problem constants ----------------
#define D_    768
#define H_    12
#define HD_   64
#define S_    197
#define L_    196
#define NB    16          // batch per image set
#define B2    32          // both image sets
#define FF_   3072
#define OUT_  512
#define QKV3  2304
#define IMG_  224
#define GRID_ 14
#define PCH_  16
#define LAYERS_ 12

// ---------------- Scratch (device globals; no allocation allowed) ----------------
__device__ float  g_x12[B2 * S_ * D_];      // residual stream (fp32)
__device__ __half g_xln[B2 * S_ * D_];      // LN output (fp16)
__device__ __half g_qkv[B2 * S_ * QKV3];    // qkv (fp16, feeds TC attention)
__device__ __half g_att[B2 * S_ * D_];      // attention out / conv_out temp (fp16)
__device__ __half g_ffh[B2 * S_ * FF_];     // MLP hidden (fp16)
__device__ __half g_im2col[B2 * L_ * D_];   // patch im2col (fp16)
__device__ float  g_cls[NB * D_];           // ln_post output (fp32)

// fp16 weight copies (B operands, [N,K] row-major)
__device__ __half g_wqkv[LAYERS_ * QKV3 * D_];
__device__ __half g_wo  [LAYERS_ * D_ * D_];
__device__ __half g_wfc [LAYERS_ * FF_ * D_];
__device__ __half g_wp  [LAYERS_ * D_ * FF_];
__device__ __half g_wcv [D_ * D_];

// ---- weight fp32 -> fp16 conversion (once per launch) ----
__global__ void cvt_half_kernel(const float4* __restrict__ in,
                                uint2* __restrict__ out, int n4)
{
    for (int i = blockIdx.x * 256 + threadIdx.x; i < n4; i += gridDim.x * 256) {
        float4 v = in[i];
        __half2 h0 = __floats2half2_rn(v.x, v.y);
        __half2 h1 = __floats2half2_rn(v.z, v.w);
        uint2 o;
        o.x = *(uint32_t*)&h0;
        o.y = *(uint32_t*)&h1;
        out[i] = o;
    }
}

// ---------------- MMA / LDSM macros ----------------
#define LDSM4(r0, r1, r2, r3, addr)                                    \
    asm volatile("ldmatrix.sync.aligned.m8n8.x4.shared.b16 "           \
                 "{%0,%1,%2,%3}, [%4];"                                \
                 : "=r"(r0), "=r"(r1), "=r"(r2), "=r"(r3) : "r"(addr))

#define LDSM4T(r0, r1, r2, r3, addr)                                   \
    asm volatile("ldmatrix.sync.aligned.m8n8.x4.trans.shared.b16 "     \
                 "{%0,%1,%2,%3}, [%4];"                                \
                 : "=r"(r0), "=r"(r1), "=r"(r2), "=r"(r3) : "r"(addr))

#define MMA_F16(d, a, b)                                               \
    asm volatile(                                                      \
        "mma.sync.aligned.m16n8k16.row.col.f32.f16.f16.f32 "           \
        "{%0,%1,%2,%3}, {%4,%5,%6,%7}, {%8,%9}, {%0,%1,%2,%3};"        \
        : "+f"((d)[0]), "+f"((d)[1]), "+f"((d)[2]), "+f"((d)[3])       \
        : "r"((a)[0]), "r"((a)[1]), "r"((a)[2]), "r"((a)[3]),          \
          "r"((b)[0]), "r"((b)[1]))

__device__ __forceinline__ uint32_t packh2(float lo, float hi) {
    __half2 h = __floats2half2_rn(lo, hi);
    return *(uint32_t*)&h;
}

// ======================================================================
// FP16 tensor-core GEMM (mma.sync):
//   C[M,N] = act( A[M,K]h @ B[N,K]h^T + bias[N] ) (+ resid[M,N])
// 128x128x64 block tile, 256 threads (8 warps 4x2), warp tile 32x64.
// flags: bit0 = half output, bit1 = GELU.
// ======================================================================
#define HBK   64
#define HST   16384

__global__ __launch_bounds__(256, 2) void gemm_h(
    const __half* __restrict__ A, const __half* __restrict__ B,
    const float* __restrict__ bias, const float* __restrict__ resid,
    void* __restrict__ Cv, int M, int N, int K, int flags)
{
    extern __shared__ char smb[];

    const int tid  = threadIdx.x;
    const int lane = tid & 31, wid = tid >> 5;
    const int wm = wid & 3, wn = wid >> 2;
    const int grp = lane >> 2, qid = lane & 3;
    const int bm = blockIdx.y * 128, bn = blockIdx.x * 128;

    const uint32_t smemBase = (uint32_t)__cvta_generic_to_shared(smb);

    const int lr0 = tid >> 3;
    const int lc  = tid & 7;

    float acc[2][8][4];
    #pragma unroll
    for (int mf = 0; mf < 2; mf++)
        #pragma unroll
        for (int nf = 0; nf < 8; nf++)
            #pragma unroll
            for (int r = 0; r < 4; r++) acc[mf][nf][r] = 0.f;

    const int niter = K / HBK;

    auto issue = [&](int it, int st) {
        const int k0 = it * HBK;
        #pragma unroll
        for (int i = 0; i < 4; i++) {
            const int row = lr0 + i * 32;
            const uint32_t xoff = (uint32_t)(row * 128 + ((lc ^ (row & 7)) * 16));
            {
                int gr = bm + row;
                int ok = (gr < M);
                const __half* src = A + (size_t)(ok ? gr : (M - 1)) * K + k0 + lc * 8;
                uint32_t dst = smemBase + st * HST + xoff;
                int sz = ok ? 16 : 0;
                asm volatile("cp.async.cg.shared.global [%0], [%1], 16, %2;"
                             :: "r"(dst), "l"(src), "r"(sz));
            }
            {
                const __half* src = B + (size_t)(bn + row) * K + k0 + lc * 8;
                uint32_t dst = smemBase + 2 * HST + st * HST + xoff;
                asm volatile("cp.async.cg.shared.global [%0], [%1], 16;"
                             :: "r"(dst), "l"(src));
            }
        }
        asm volatile("cp.async.commit_group;");
    };

    issue(0, 0);
    int stage = 0;

    const int aRowIn = lane & 15;
    const int aKHalf = lane >> 4;
    const int bMat   = lane >> 3;
    const int bRowIn = (lane & 7) + ((bMat >> 1) << 3);
    const int bKHalf = bMat & 1;

    for (int it = 0; it < niter; it++) {
        if (it + 1 < niter) {
            issue(it + 1, stage ^ 1);
            asm volatile("cp.async.wait_group 1;");
        } else {
            asm volatile("cp.async.wait_group 0;");
        }
        __syncthreads();

        const uint32_t aStage = smemBase + stage * HST;
        const uint32_t bStage = smemBase + 2 * HST + stage * HST;

        #pragma unroll
        for (int ks = 0; ks < HBK; ks += 16) {
            const int kc = ks >> 3;
            uint32_t a[2][4], b[16];
            #pragma unroll
            for (int mf = 0; mf < 2; mf++) {
                const int row = wm * 32 + mf * 16 + aRowIn;
                const int ch  = (kc + aKHalf) ^ (row & 7);
                LDSM4(a[mf][0], a[mf][1], a[mf][2], a[mf][3],
                      aStage + (uint32_t)(row * 128 + ch * 16));
            }
            #pragma unroll
            for (int np = 0; np < 4; np++) {
                const int row = wn * 64 + np * 16 + bRowIn;
                const int ch  = (kc + bKHalf) ^ (row & 7);
                LDSM4(b[np * 4 + 0], b[np * 4 + 1], b[np * 4 + 2], b[np * 4 + 3],
                      bStage + (uint32_t)(row * 128 + ch * 16));
            }
            #pragma unroll
            for (int mf = 0; mf < 2; mf++)
                #pragma unroll
                for (int np = 0; np < 4; np++) {
                    MMA_F16(acc[mf][np * 2 + 0], a[mf], &b[np * 4 + 0]);
                    MMA_F16(acc[mf][np * 2 + 1], a[mf], &b[np * 4 + 2]);
                }
        }
        __syncthreads();
        stage ^= 1;
    }

    const int halfOut = flags & 1;
    const int act     = flags & 2;
    float* Cf = (float*)Cv;
    __half* Ch = (__half*)Cv;

    #pragma unroll
    for (int mf = 0; mf < 2; mf++) {
        #pragma unroll
        for (int hh = 0; hh < 2; hh++) {
            const int gm = bm + wm * 32 + mf * 16 + grp + hh * 8;
            if (gm >= M) continue;
            #pragma unroll
            for (int nf = 0; nf < 8; nf++) {
                const int gn = bn + wn * 64 + nf * 8 + 2 * qid;
                float v0 = acc[mf][nf][hh * 2 + 0];
                float v1 = acc[mf][nf][hh * 2 + 1];
                if (bias) { v0 += bias[gn]; v1 += bias[gn + 1]; }
                if (act) {
                    v0 = v0 / (1.f + __expf(-1.702f * v0));
                    v1 = v1 / (1.f + __expf(-1.702f * v1));
                }
                if (resid) {
                    const float* rp = resid + (size_t)gm * N + gn;
                    v0 += rp[0]; v1 += rp[1];
                }
                if (halfOut) {
                    __half2 h = __floats2half2_rn(v0, v1);
                    *(__half2*)(Ch + (size_t)gm * N + gn) = h;
                } else {
                    float2 o; o.x = v0; o.y = v1;
                    *(float2*)(Cf + (size_t)gm * N + gn) = o;
                }
            }
        }
    }
}

// ======================================================================
// Tensor-core attention (mma.sync). One block per (head, batch), 8 warps.
// For batches b >= bias_base, cls-row bias is derived from pred:
//   bias[k] = (pred[(b-bias_base)*L + k-1] != 0) ? 0 : -1e30, k in [1,196].
// ======================================================================
#define SATT   224
#define ATT_MAT 28672
#define ATT_SMEM (3 * ATT_MAT)

__global__ __launch_bounds__(256) void attn_tc(
    const __half* __restrict__ qkv, const float* __restrict__ pred,
    int bias_base, __half* __restrict__ out)
{
    extern __shared__ char smb[];
    const int h = blockIdx.x, b = blockIdx.y;
    const int tid = threadIdx.x;
    const int lane = tid & 31, wid = tid >> 5;
    const uint32_t base = (uint32_t)__cvta_generic_to_shared(smb);

    for (int i = tid; i < S_ * 24; i += 256) {
        int s = i / 24, rem = i % 24;
        int m3 = rem >> 3, c = rem & 7;
        const uint4 v = *(const uint4*)(qkv + ((size_t)(b * S_ + s)) * QKV3
                                        + m3 * D_ + h * HD_ + c * 8);
        uint4 w = v;
        if (m3 == 0) {
            const __half2 sc = __floats2half2_rn(0.125f, 0.125f);
            __half2* hp = (__half2*)&w;
            hp[0] = __hmul2(hp[0], sc); hp[1] = __hmul2(hp[1], sc);
            hp[2] = __hmul2(hp[2], sc); hp[3] = __hmul2(hp[3], sc);
        }
        *(uint4*)(smb + m3 * ATT_MAT + s * 128 + ((c ^ (s & 7)) * 16)) = w;
    }
    for (int i = tid; i < (SATT - S_) * 24; i += 256) {
        int r = S_ + i / 24, rem = i % 24;
        int m3 = rem >> 3, c = rem & 7;
        *(uint4*)(smb + m3 * ATT_MAT + r * 128 + ((c ^ (r & 7)) * 16)) =
            make_uint4(0, 0, 0, 0);
    }
    __syncthreads();

    const int grp = lane >> 2, qid = lane & 3;
    const int aRow = lane & 15, aK = lane >> 4;
    const int bRow = (lane & 7) + ((lane >> 4) << 3);
    const int bK   = (lane >> 3) & 1;
    const int vRow = (lane & 7) + (((lane >> 3) & 1) << 3);
    const int vC   = lane >> 4;

    const bool hasBias = (pred != nullptr) && (b >= bias_base);
    const float* predRow = hasBias ? (pred + (size_t)(b - bias_base) * L_)
                                   : nullptr;

    for (int chunk = wid; chunk < 13; chunk += 8) {
        const int mbase = chunk * 16;

        float sc[28][4];
        #pragma unroll
        for (int j = 0; j < 28; j++)
            #pragma unroll
            for (int e = 0; e < 4; e++) sc[j][e] = 0.f;

        #pragma unroll
        for (int t = 0; t < 4; t++) {
            uint32_t a[4];
            const int ar = mbase + aRow;
            LDSM4(a[0], a[1], a[2], a[3],
                  base + (uint32_t)(ar * 128 + (((2 * t + aK) ^ (ar & 7)) * 16)));
            #pragma unroll
            for (int np = 0; np < 14; np++) {
                uint32_t bb[4];
                const int br = np * 16 + bRow;
                LDSM4(bb[0], bb[1], bb[2], bb[3],
                      base + (uint32_t)(ATT_MAT + br * 128
                                        + (((2 * t + bK) ^ (br & 7)) * 16)));
                MMA_F16(sc[np * 2 + 0], a, &bb[0]);
                MMA_F16(sc[np * 2 + 1], a, &bb[2]);
            }
        }

        const bool dobias = hasBias && (mbase == 0) && (grp == 0);
        float m0 = -1e30f, m1 = -1e30f;
        #pragma unroll
        for (int j = 0; j < 28; j++) {
            const int col = j * 8 + 2 * qid;
            if (dobias) {
                if (col >= 1 && col < S_)
                    sc[j][0] += (predRow[col - 1] != 0.f) ? 0.f : -1e30f;
                if (col + 1 < S_)
                    sc[j][1] += (predRow[col] != 0.f) ? 0.f : -1e30f;
            }
            if (col >= S_)     { sc[j][0] = -1e30f; sc[j][2] = -1e30f; }
            if (col + 1 >= S_) { sc[j][1] = -1e30f; sc[j][3] = -1e30f; }
            m0 = fmaxf(m0, fmaxf(sc[j][0], sc[j][1]));
            m1 = fmaxf(m1, fmaxf(sc[j][2], sc[j][3]));
        }
        m0 = fmaxf(m0, __shfl_xor_sync(0xffffffffu, m0, 1));
        m0 = fmaxf(m0, __shfl_xor_sync(0xffffffffu, m0, 2));
        m1 = fmaxf(m1, __shfl_xor_sync(0xffffffffu, m1, 1));
        m1 = fmaxf(m1, __shfl_xor_sync(0xffffffffu, m1, 2));

        float s0 = 0.f, s1 = 0.f;
        #pragma unroll
        for (int j = 0; j < 28; j++) {
            sc[j][0] = __expf(sc[j][0] - m0);
            sc[j][1] = __expf(sc[j][1] - m0);
            sc[j][2] = __expf(sc[j][2] - m1);
            sc[j][3] = __expf(sc[j][3] - m1);
            s0 += sc[j][0] + sc[j][1];
            s1 += sc[j][2] + sc[j][3];
        }
        s0 += __shfl_xor_sync(0xffffffffu, s0, 1);
        s0 += __shfl_xor_sync(0xffffffffu, s0, 2);
        s1 += __shfl_xor_sync(0xffffffffu, s1, 1);
        s1 += __shfl_xor_sync(0xffffffffu, s1, 2);

        float ov[8][4];
        #pragma unroll
        for (int j = 0; j < 8; j++)
            #pragma unroll
            for (int e = 0; e < 4; e++) ov[j][e] = 0.f;

        #pragma unroll
        for (int t = 0; t < 14; t++) {
            uint32_t a[4];
            a[0] = packh2(sc[2 * t][0],     sc[2 * t][1]);
            a[1] = packh2(sc[2 * t][2],     sc[2 * t][3]);
            a[2] = packh2(sc[2 * t + 1][0], sc[2 * t + 1][1]);
            a[3] = packh2(sc[2 * t + 1][2], sc[2 * t + 1][3]);
            const int vr = t * 16 + vRow;
            #pragma unroll
            for (int np = 0; np < 4; np++) {
                uint32_t vv[4];
                const int vc = 2 * np + vC;
                LDSM4T(vv[0], vv[1], vv[2], vv[3],
                       base + (uint32_t)(2 * ATT_MAT + vr * 128
                                         + ((vc ^ (vr & 7)) * 16)));
                MMA_F16(ov[np * 2 + 0], a, &vv[0]);
                MMA_F16(ov[np * 2 + 1], a, &vv[2]);
            }
        }

        const float inv0 = 1.f / s0, inv1 = 1.f / s1;
        const int q0 = mbase + grp, q1 = q0 + 8;
        #pragma unroll
        for (int j = 0; j < 8; j++) {
            const int col = h * HD_ + j * 8 + 2 * qid;
            if (q0 < S_) {
                __half2 o = __floats2half2_rn(ov[j][0] * inv0, ov[j][1] * inv0);
                *(__half2*)(out + (size_t)(b * S_ + q0) * D_ + col) = o;
            }
            if (q1 < S_) {
                __half2 o = __floats2half2_rn(ov[j][2] * inv1, ov[j][3] * inv1);
                *(__half2*)(out + (size_t)(b * S_ + q1) * D_ + col) = o;
            }
        }
    }
}

// ======================================================================
// LayerNorm: warp-per-row (8 rows / 256-thr block), float4 IO, pure
// shuffle reductions — no smem, no __syncthreads.
// ======================================================================
__device__ __forceinline__ void ln_store(float* yr, int idx, float4 o) {
    ((float4*)yr)[idx] = o;
}
__device__ __forceinline__ void ln_store(__half* yr, int idx, float4 o) {
    __half2 h0 = __floats2half2_rn(o.x, o.y);
    __half2 h1 = __floats2half2_rn(o.z, o.w);
    uint2 u; u.x = *(uint32_t*)&h0; u.y = *(uint32_t*)&h1;
    ((uint2*)yr)[idx] = u;
}

template <typename TO>
__global__ __launch_bounds__(256) void ln_kernel(
    const float* __restrict__ x, long in_stride,
    TO* __restrict__ y, long out_stride,
    const float* __restrict__ g, const float* __restrict__ b, int rows)
{
    const int wid = threadIdx.x >> 5, lane = threadIdx.x & 31;
    const int r = blockIdx.x * 8 + wid;
    if (r >= rows) return;

    const float4* xr = (const float4*)(x + (size_t)r * in_stride);
    TO* yr = y + (size_t)r * out_stride;

    float4 v[6];
    float s = 0.f;
    #pragma unroll
    for (int i = 0; i < 6; i++) {
        v[i] = xr[lane + 32 * i];
        s += (v[i].x + v[i].y) + (v[i].z + v[i].w);
    }
    #pragma unroll
    for (int o = 16; o > 0; o >>= 1) s += __shfl_xor_sync(0xffffffffu, s, o);
    const float mu = s * (1.f / 768.f);

    float ss = 0.f;
    #pragma unroll
    for (int i = 0; i < 6; i++) {
        v[i].x -= mu; v[i].y -= mu; v[i].z -= mu; v[i].w -= mu;
        ss += v[i].x * v[i].x + v[i].y * v[i].y
            + v[i].z * v[i].z + v[i].w * v[i].w;
    }
    #pragma unroll
    for (int o = 16; o > 0; o >>= 1) ss += __shfl_xor_sync(0xffffffffu, ss, o);
    const float rs = rsqrtf(ss * (1.f / 768.f) + 1e-5f);

    const float4* g4 = (const float4*)g;
    const float4* b4 = (const float4*)b;
    #pragma unroll
    for (int i = 0; i < 6; i++) {
        const float4 gg = g4[lane + 32 * i];
        const float4 bb = b4[lane + 32 * i];
        float4 o;
        o.x = v[i].x * rs * gg.x + bb.x;
        o.y = v[i].y * rs * gg.y + bb.y;
        o.z = v[i].z * rs * gg.z + bb.z;
        o.w = v[i].w * rs * gg.w + bb.w;
        ln_store(yr, lane + 32 * i, o);
    }
}

// ======================================================================
// Fused mask_combine + LayerNorm for the masking layers.
// Rows 0..NB*S-1 (x half): v = 2*x2*mf + x  -> write v back to x, LN(v)->y.
// Rows NB*S..2*NB*S-1 (x2 half): plain LN.
// ======================================================================
__global__ __launch_bounds__(256) void ln_mask_kernel(
    float* __restrict__ x, const float* __restrict__ pred,
    __half* __restrict__ y,
    const float* __restrict__ g, const float* __restrict__ b)
{
    const int wid = threadIdx.x >> 5, lane = threadIdx.x & 31;
    const int r = blockIdx.x * 8 + wid;
    if (r >= B2 * S_) return;

    float4* xr = (float4*)(x + (size_t)r * D_);
    __half* yr = y + (size_t)r * D_;

    const bool comb = (r < NB * S_);
    float4 v[6];

    if (comb) {
        const int bidx = r / S_, s_ = r % S_;
        const float mf = (s_ == 0) ? 1.f : pred[bidx * L_ + (s_ - 1)];
        const float4* x2r = (const float4*)(x + ((size_t)NB * S_ + r) * D_);
        #pragma unroll
        for (int i = 0; i < 6; i++) {
            float4 a = xr[lane + 32 * i];
            float4 c = x2r[lane + 32 * i];
            v[i].x = 2.f * c.x * mf + a.x;
            v[i].y = 2.f * c.y * mf + a.y;
            v[i].z = 2.f * c.z * mf + a.z;
            v[i].w = 2.f * c.w * mf + a.w;
            xr[lane + 32 * i] = v[i];
        }
    } else {
        #pragma unroll
        for (int i = 0; i < 6; i++) v[i] = xr[lane + 32 * i];
    }

    float s = 0.f;
    #pragma unroll
    for (int i = 0; i < 6; i++)
        s += (v[i].x + v[i].y) + (v[i].z + v[i].w);
    #pragma unroll
    for (int o = 16; o > 0; o >>= 1) s += __shfl_xor_sync(0xffffffffu, s, o);
    const float mu = s * (1.f / 768.f);

    float ss = 0.f;
    #pragma unroll
    for (int i = 0; i < 6; i++) {
        v[i].x -= mu; v[i].y -= mu; v[i].z -= mu; v[i].w -= mu;
        ss += v[i].x * v[i].x + v[i].y * v[i].y
            + v[i].z * v[i].z + v[i].w * v[i].w;
    }
    #pragma unroll
    for (int o = 16; o > 0; o >>= 1) ss += __shfl_xor_sync(0xffffffffu, ss, o);
    const float rs = rsqrtf(ss * (1.f / 768.f) + 1e-5f);

    const float4* g4 = (const float4*)g;
    const float4* b4 = (const float4*)b;
    #pragma unroll
    for (int i = 0; i < 6; i++) {
        const float4 gg = g4[lane + 32 * i];
        const float4 bb = b4[lane + 32 * i];
        float4 o;
        o.x = v[i].x * rs * gg.x + bb.x;
        o.y = v[i].y * rs * gg.y + bb.y;
        o.z = v[i].z * rs * gg.z + bb.z;
        o.w = v[i].w * rs * gg.w + bb.w;
        ln_store(yr, lane + 32 * i, o);
    }
}

// ======================================================================
// Patch embed helpers
// ======================================================================
__global__ void im2col_kernel(const float* __restrict__ masked,
                              const float* __restrict__ prompted,
                              __half* __restrict__ col)
{
    int idx = blockIdx.x * 256 + threadIdx.x;
    const int total = B2 * L_ * D_;
    if (idx >= total) return;
    int k = idx % D_;
    int m = idx / D_;
    int b = m / L_, l = m % L_;
    int gy = l / GRID_, gx = l % GRID_;
    int c = k >> 8, rem = k & 255;
    int py = rem >> 4, px = rem & 15;
    const float* src = (b < NB) ? (masked + (size_t)b * 3 * IMG_ * IMG_)
                                : (prompted + (size_t)(b - NB) * 3 * IMG_ * IMG_);
    col[idx] = __float2half_rn(
        src[((size_t)c * IMG_ + gy * PCH_ + py) * IMG_ + gx * PCH_ + px]);
}

__global__ void embed_kernel(const __half* __restrict__ conv_out,
                             const float* __restrict__ cls_emb,
                             const float* __restrict__ pos,
                             float* __restrict__ x)
{
    int idx = blockIdx.x * 256 + threadIdx.x;
    const int total = B2 * S_ * D_;
    if (idx >= total) return;
    int d = idx % D_;
    int bs = idx / D_;
    int s = bs % S_, b = bs / S_;
    float v = (s == 0) ? cls_emb[d]
                       : __half2float(conv_out[((size_t)b * L_ + (s - 1)) * D_ + d]);
    x[idx] = v + pos[s * D_ + d];
}

__global__ void proj_out_kernel(const float* __restrict__ cls,
                                const float* __restrict__ proj,
                                float* __restrict__ out)
{
    int n = blockIdx.x * 256 + threadIdx.x;
    int m = blockIdx.y;
    if (n >= OUT_) return;
    float s = 0.f;
    #pragma unroll 4
    for (int k = 0; k < D_; k++) s += cls[m * D_ + k] * proj[(size_t)k * OUT_ + n];
    out[m * OUT_ + n] = s;
}

// ======================================================================
// Host orchestration
// ======================================================================
template <typename T>
static T* symaddr_t(const void* s) {
    void* p = nullptr;
    cudaGetSymbolAddress(&p, s);
    return (T*)p;
}

#define GEMM_SMEM (4 * HST)   // 65,536 B

static void run_gemm(const __half* A, const __half* B, const float* bias,
                     const float* resid, void* C, int M, int N, int K, int flags,
                     cudaStream_t st)
{
    dim3 grid(N / 128, (M + 127) / 128);
    gemm_h<<<grid, 256, GEMM_SMEM, st>>>(A, B, bias, resid, C, M, N, K, flags);
}

static void run_cvt(const float* in, __half* out, long n, cudaStream_t st)
{
    int n4 = (int)(n / 4);
    int blocks = (n4 + 255) / 256;
    if (blocks > 16384) blocks = 16384;
    cvt_half_kernel<<<blocks, 256, 0, st>>>((const float4*)in, (uint2*)out, n4);
}

struct Ctx {
    float *x12, *cls;
    __half *xln, *qkv, *att, *ffh, *col;
    const __half *Wqkv, *Wo, *Wfc, *Wp;
    const float *bqkv, *bo, *ln1g, *ln1b, *ln2g, *ln2b, *bfc, *bp;
    const float *pred;
};

// maskfuse: if nonzero, layer's LN1 is the fused mask_combine+LN over B2
static void run_block(const Ctx& c, float* x, int Bn, int layer,
                      const float* bias_pred, int bias_base, int maskfuse,
                      cudaStream_t st)
{
    const int M = Bn * S_;
    const int lgrid = (M + 7) / 8;
    if (maskfuse) {
        ln_mask_kernel<<<lgrid, 256, 0, st>>>(x, c.pred, c.xln,
                                              c.ln1g + layer * D_,
                                              c.ln1b + layer * D_);
    } else {
        ln_kernel<__half><<<lgrid, 256, 0, st>>>(x, D_, c.xln, D_,
                                      c.ln1g + layer * D_, c.ln1b + layer * D_, M);
    }
    run_gemm(c.xln, c.Wqkv + (size_t)layer * QKV3 * D_, c.bqkv + layer * QKV3,
             nullptr, c.qkv, M, QKV3, D_, 1, st);
    attn_tc<<<dim3(H_, Bn), 256, ATT_SMEM, st>>>(c.qkv, bias_pred, bias_base, c.att);
    run_gemm(c.att, c.Wo + (size_t)layer * D_ * D_, c.bo + layer * D_,
             x, x, M, D_, D_, 0, st);
    ln_kernel<__half><<<lgrid, 256, 0, st>>>(x, D_, c.xln, D_,
                                  c.ln2g + layer * D_, c.ln2b + layer * D_, M);
    run_gemm(c.xln, c.Wfc + (size_t)layer * FF_ * D_, c.bfc + layer * FF_,
             nullptr, c.ffh, M, FF_, D_, 1 | 2, st);
    run_gemm(c.ffh, c.Wp + (size_t)layer * D_ * FF_, c.bp + layer * D_,
             x, x, M, D_, FF_, 0, st);
}

extern "C" void kernel_launch(void* const* d_in, const int* in_sizes, int n_in,
                              void* d_out, int out_size)
{
    const float* masked   = (const float*)d_in[0];
    const float* prompted = (const float*)d_in[1];
    const float* pred     = (const float*)d_in[2];
    const float* conv_w   = (const float*)d_in[3];
    const float* cls_emb  = (const float*)d_in[4];
    const float* pos_emb  = (const float*)d_in[5];
    const float* lnpre_g  = (const float*)d_in[6];
    const float* lnpre_b  = (const float*)d_in[7];

    const float* Wqkv_raw = (const float*)d_in[8];
    const float* bqkv     = (const float*)d_in[9];
    const float* Wo_raw   = (const float*)d_in[10];
    const float* bo       = (const float*)d_in[11];
    const float* ln1g     = (const float*)d_in[12];
    const float* ln1b     = (const float*)d_in[13];
    const float* ln2g     = (const float*)d_in[14];
    const float* ln2b     = (const float*)d_in[15];
    const float* Wfc_raw  = (const float*)d_in[16];
    const float* bfc      = (const float*)d_in[17];
    const float* Wp_raw   = (const float*)d_in[18];
    const float* bp       = (const float*)d_in[19];
    const float* lnpost_g = (const float*)d_in[20];
    const float* lnpost_b = (const float*)d_in[21];
    const float* proj     = (const float*)d_in[22];
    float* out = (float*)d_out;

    // one-time stream/event creation (host resources only; no device memory)
    static cudaStream_t s2 = nullptr;
    static cudaEvent_t ev[4];
    if (!s2) {
        cudaStreamCreateWithFlags(&s2, cudaStreamNonBlocking);
        for (int i = 0; i < 4; i++)
            cudaEventCreateWithFlags(&ev[i], cudaEventDisableTiming);
    }
    cudaStream_t s0 = 0;   // capture (default) stream

    Ctx c;
    c.x12  = symaddr_t<float>(g_x12);
    c.xln  = symaddr_t<__half>(g_xln);
    c.qkv  = symaddr_t<__half>(g_qkv);
    c.att  = symaddr_t<__half>(g_att);
    c.ffh  = symaddr_t<__half>(g_ffh);
    c.col  = symaddr_t<__half>(g_im2col);
    c.cls  = symaddr_t<float>(g_cls);
    c.pred = pred;

    __half* wqkv = symaddr_t<__half>(g_wqkv);
    __half* wo   = symaddr_t<__half>(g_wo);
    __half* wfc  = symaddr_t<__half>(g_wfc);
    __half* wp   = symaddr_t<__half>(g_wp);
    __half* wcv  = symaddr_t<__half>(g_wcv);

    c.Wqkv = wqkv; c.bqkv = bqkv;
    c.Wo   = wo;   c.bo   = bo;
    c.ln1g = ln1g; c.ln1b = ln1b;
    c.ln2g = ln2g; c.ln2b = ln2b;
    c.Wfc  = wfc;  c.bfc  = bfc;
    c.Wp   = wp;   c.bp   = bp;

    cudaFuncSetAttribute(attn_tc, cudaFuncAttributeMaxDynamicSharedMemorySize,
                         ATT_SMEM);
    cudaFuncSetAttribute(gemm_h, cudaFuncAttributeMaxDynamicSharedMemorySize,
                         GEMM_SMEM);

    // ---- fork: weight conversion on s2 (layer 0 first), embed path on s0 ----
    cudaEventRecord(ev[0], s0);
    cudaStreamWaitEvent(s2, ev[0], 0);

    run_cvt(conv_w, wcv, (long)D_ * D_, s2);
    cudaEventRecord(ev[1], s2);                  // conv weights ready
    // layer-0 weight slices first
    run_cvt(Wqkv_raw, wqkv, (long)QKV3 * D_, s2);
    run_cvt(Wo_raw,   wo,   (long)D_ * D_, s2);
    run_cvt(Wfc_raw,  wfc,  (long)FF_ * D_, s2);
    run_cvt(Wp_raw,   wp,   (long)D_ * FF_, s2);
    cudaEventRecord(ev[3], s2);                  // layer-0 weights ready
    // remaining layers 1..11
    run_cvt(Wqkv_raw + (long)QKV3 * D_, wqkv + (long)QKV3 * D_,
            (long)(LAYERS_ - 1) * QKV3 * D_, s2);
    run_cvt(Wo_raw + (long)D_ * D_, wo + (long)D_ * D_,
            (long)(LAYERS_ - 1) * D_ * D_, s2);
    run_cvt(Wfc_raw + (long)FF_ * D_, wfc + (long)FF_ * D_,
            (long)(LAYERS_ - 1) * FF_ * D_, s2);
    run_cvt(Wp_raw + (long)D_ * FF_, wp + (long)D_ * FF_,
            (long)(LAYERS_ - 1) * D_ * FF_, s2);
    cudaEventRecord(ev[2], s2);                  // all weights ready

    {
        const int total = B2 * L_ * D_;
        im2col_kernel<<<(total + 255) / 256, 256, 0, s0>>>(masked, prompted, c.col);
        cudaStreamWaitEvent(s0, ev[1], 0);       // need wcv
        run_gemm(c.col, wcv, nullptr, nullptr, c.att, B2 * L_, D_, D_, 1, s0);
        const int tot2 = B2 * S_ * D_;
        embed_kernel<<<(tot2 + 255) / 256, 256, 0, s0>>>(c.att, cls_emb, pos_emb, c.x12);
        ln_kernel<float><<<(B2 * S_ + 7) / 8, 256, 0, s0>>>(
            c.x12, D_, c.x12, D_, lnpre_g, lnpre_b, B2 * S_);
    }

    cudaStreamWaitEvent(s0, ev[3], 0);           // layer-0 weights
    run_block(c, c.x12, B2, 0, nullptr, 0, 0, s0);
    cudaStreamWaitEvent(s0, ev[2], 0);           // all weights
    for (int i = 1; i < 10; i++)
        run_block(c, c.x12, B2, i, nullptr, 0, 0, s0);

    // ---- masking phase: merged block per layer; fused combine+LN1 ----
    float* x = c.x12;
    const int layers2[2] = {10, 11};
    for (int t = 0; t < 2; t++)
        run_block(c, c.x12, B2, layers2[t], pred, NB, 1, s0);

    ln_kernel<float><<<(NB + 7) / 8, 256, 0, s0>>>(x, (long)S_ * D_, c.cls, D_,
                                                   lnpost_g, lnpost_b, NB);
    proj_out_kernel<<<dim3((OUT_ + 255) / 256, NB), 256, 0, s0>>>(c.cls, proj, out);

    (void)in_sizes; (void)n_in; (void)out_size;
}